// round 2
// baseline (speedup 1.0000x reference)
#include <cuda_runtime.h>
#include <cuda_bf16.h>
#include <math.h>

// Problem constants
#define B_  4
#define S_  2048
#define E_  768
#define H_  12
#define D_  64
#define N_ROWS (B_ * S_)          // 8192
#define QKV_COLS (3 * E_)         // 2304

// Scratch (device globals; allocation inside kernel_launch is forbidden)
__device__ float g_Q[(size_t)B_ * H_ * S_ * D_];
__device__ float g_K[(size_t)B_ * H_ * S_ * D_];
__device__ float g_V[(size_t)B_ * H_ * S_ * D_];
__device__ float g_attn[(size_t)N_ROWS * E_];

// ---------------------------------------------------------------------------
// Kernel 1: fused QKV projection.
// C[r][j] = sum_e x[r][e] * W_sel[h][e][d] + bias_sel[h][d]
// where j in [0,2304): sel = j/768, h = (j%768)/64, d = j%64.
// BN=64 aligned to head boundaries -> each block serves exactly one (sel, h).
// Tiles: BM=64, BN=64, BK=16; 256 threads; 4x4 micro-tile per thread.
// ---------------------------------------------------------------------------
__global__ __launch_bounds__(256)
void qkv_gemm_kernel(const float* __restrict__ x,
                     const float* __restrict__ Wq, const float* __restrict__ bq,
                     const float* __restrict__ Wk, const float* __restrict__ bk,
                     const float* __restrict__ Wv, const float* __restrict__ bv)
{
    __shared__ __align__(16) float As[16][64];   // As[k][m]
    __shared__ __align__(16) float Bs[16][64];   // Bs[k][n]

    const int tid = threadIdx.x;
    const int ty = tid >> 4;          // 0..15
    const int tx = tid & 15;          // 0..15
    const int m0 = blockIdx.y * 64;
    const int j0 = blockIdx.x * 64;

    const int sel = j0 / E_;
    const int h = (j0 % E_) / D_;

    const float* W   = (sel == 0) ? Wq : (sel == 1) ? Wk : Wv;
    const float* bia = (sel == 0) ? bq : (sel == 1) ? bk : bv;
    float* out       = (sel == 0) ? g_Q : (sel == 1) ? g_K : g_V;
    const float* Wh = W + (size_t)h * E_ * D_;   // [E_][64]

    // load mapping
    const int arow = tid >> 2;            // 0..63 (m within tile)
    const int acol = (tid & 3) * 4;       // 0,4,8,12 (k within tile)
    const int brow = tid >> 4;            // 0..15 (k within tile)
    const int bcol = (tid & 15) * 4;      // 0..60 (n within tile)

    float acc[4][4] = {};

    for (int k0 = 0; k0 < E_; k0 += 16) {
        float4 av = *(const float4*)(x + (size_t)(m0 + arow) * E_ + k0 + acol);
        As[acol + 0][arow] = av.x;
        As[acol + 1][arow] = av.y;
        As[acol + 2][arow] = av.z;
        As[acol + 3][arow] = av.w;
        float4 wv = *(const float4*)(Wh + (size_t)(k0 + brow) * D_ + bcol);
        *(float4*)&Bs[brow][bcol] = wv;
        __syncthreads();

#pragma unroll
        for (int kk = 0; kk < 16; kk++) {
            float4 a = *(const float4*)&As[kk][ty * 4];
            float4 b = *(const float4*)&Bs[kk][tx * 4];
            float ar[4] = {a.x, a.y, a.z, a.w};
            float br[4] = {b.x, b.y, b.z, b.w};
#pragma unroll
            for (int i = 0; i < 4; i++)
#pragma unroll
                for (int j = 0; j < 4; j++)
                    acc[i][j] = fmaf(ar[i], br[j], acc[i][j]);
        }
        __syncthreads();
    }

    // epilogue: bias + write to [B][H][S][D]
    const int d0 = tx * 4;
    float4 bb = *(const float4*)(bia + h * D_ + d0);
#pragma unroll
    for (int i = 0; i < 4; i++) {
        const int r = m0 + ty * 4 + i;
        const int b_ = r / S_;
        const int s = r % S_;
        float4 v;
        v.x = acc[i][0] + bb.x;
        v.y = acc[i][1] + bb.y;
        v.z = acc[i][2] + bb.z;
        v.w = acc[i][3] + bb.w;
        *(float4*)(out + ((((size_t)b_ * H_ + h) * S_) + s) * D_ + d0) = v;
    }
}

// ---------------------------------------------------------------------------
// Kernel 2: flash attention (fp32, online softmax).
// Grid: (S/64, H, B). Block: 256 threads = 16x16, each owns 4q x 4{k,d}.
// Shared: Qs/Ks/Vs/Ss as [64][65] padded, plus m/l/c rows + key mask tile.
// Output written to g_attn in [B, S, H*D] layout for the final GEMM.
// ---------------------------------------------------------------------------
#define FA_SMEM_BYTES ((4 * 64 * 65 + 3 * 64) * 4 + 64 * 4)

__global__ __launch_bounds__(256)
void flash_attn_kernel(const int* __restrict__ mask)
{
    extern __shared__ float sm[];
    float* Qs  = sm;                 // [64][65]
    float* Ks  = Qs + 64 * 65;
    float* Vs  = Ks + 64 * 65;
    float* Ss  = Vs + 64 * 65;
    float* m_sh = Ss + 64 * 65;      // [64]
    float* l_sh = m_sh + 64;
    float* c_sh = l_sh + 64;
    int*   msk  = (int*)(c_sh + 64); // [64]

    const int tid = threadIdx.x;
    const int ty = tid >> 4;         // 0..15
    const int tx = tid & 15;         // 0..15
    const int q0 = blockIdx.x * 64;
    const int h = blockIdx.y;
    const int b = blockIdx.z;

    const size_t base = (((size_t)b * H_ + h) * S_) * D_;
    const float* Qg = g_Q + base;
    const float* Kg = g_K + base;
    const float* Vg = g_V + base;

    const int lr = tid >> 2;         // 0..63
    const int lc = (tid & 3) * 16;   // 0,16,32,48

    // Load Q tile once
#pragma unroll
    for (int j = 0; j < 16; j += 4) {
        float4 v = *(const float4*)(Qg + (size_t)(q0 + lr) * D_ + lc + j);
        Qs[lr * 65 + lc + j + 0] = v.x;
        Qs[lr * 65 + lc + j + 1] = v.y;
        Qs[lr * 65 + lc + j + 2] = v.z;
        Qs[lr * 65 + lc + j + 3] = v.w;
    }
    if (tid < 64) { m_sh[tid] = -INFINITY; l_sh[tid] = 0.f; }

    float acc[4][4] = {};
    __syncthreads();

    for (int k0 = 0; k0 < S_; k0 += 64) {
        // Load K, V tiles + mask slice
#pragma unroll
        for (int j = 0; j < 16; j += 4) {
            float4 kv = *(const float4*)(Kg + (size_t)(k0 + lr) * D_ + lc + j);
            Ks[lr * 65 + lc + j + 0] = kv.x;
            Ks[lr * 65 + lc + j + 1] = kv.y;
            Ks[lr * 65 + lc + j + 2] = kv.z;
            Ks[lr * 65 + lc + j + 3] = kv.w;
            float4 vv = *(const float4*)(Vg + (size_t)(k0 + lr) * D_ + lc + j);
            Vs[lr * 65 + lc + j + 0] = vv.x;
            Vs[lr * 65 + lc + j + 1] = vv.y;
            Vs[lr * 65 + lc + j + 2] = vv.z;
            Vs[lr * 65 + lc + j + 3] = vv.w;
        }
        if (tid < 64) msk[tid] = mask[(size_t)b * S_ + k0 + tid];
        __syncthreads();

        // Scores: 4q x 4k per thread, dot over d=64
        float sc[4][4] = {};
#pragma unroll
        for (int d = 0; d < 64; d++) {
            float a0 = Qs[(ty * 4 + 0) * 65 + d];
            float a1 = Qs[(ty * 4 + 1) * 65 + d];
            float a2 = Qs[(ty * 4 + 2) * 65 + d];
            float a3 = Qs[(ty * 4 + 3) * 65 + d];
            float b0 = Ks[(tx * 4 + 0) * 65 + d];
            float b1 = Ks[(tx * 4 + 1) * 65 + d];
            float b2 = Ks[(tx * 4 + 2) * 65 + d];
            float b3 = Ks[(tx * 4 + 3) * 65 + d];
            sc[0][0] = fmaf(a0, b0, sc[0][0]); sc[0][1] = fmaf(a0, b1, sc[0][1]);
            sc[0][2] = fmaf(a0, b2, sc[0][2]); sc[0][3] = fmaf(a0, b3, sc[0][3]);
            sc[1][0] = fmaf(a1, b0, sc[1][0]); sc[1][1] = fmaf(a1, b1, sc[1][1]);
            sc[1][2] = fmaf(a1, b2, sc[1][2]); sc[1][3] = fmaf(a1, b3, sc[1][3]);
            sc[2][0] = fmaf(a2, b0, sc[2][0]); sc[2][1] = fmaf(a2, b1, sc[2][1]);
            sc[2][2] = fmaf(a2, b2, sc[2][2]); sc[2][3] = fmaf(a2, b3, sc[2][3]);
            sc[3][0] = fmaf(a3, b0, sc[3][0]); sc[3][1] = fmaf(a3, b1, sc[3][1]);
            sc[3][2] = fmaf(a3, b2, sc[3][2]); sc[3][3] = fmaf(a3, b3, sc[3][3]);
        }
        // scale, mask, stash into Ss
#pragma unroll
        for (int i = 0; i < 4; i++)
#pragma unroll
            for (int j = 0; j < 4; j++) {
                const int kk = tx * 4 + j;
                float v = sc[i][j] * 0.125f;          // 1/sqrt(64)
                if (msk[kk] == 0) v = -1000000000.0f;
                Ss[(ty * 4 + i) * 65 + kk] = v;
            }
        __syncthreads();

        // Online softmax row update: 4 threads per row
        {
            const int r = tid >> 2;
            const int seg = (tid & 3) * 16;
            float tm = -INFINITY;
#pragma unroll
            for (int c = 0; c < 16; c++)
                tm = fmaxf(tm, Ss[r * 65 + seg + c]);
            tm = fmaxf(tm, __shfl_xor_sync(0xffffffffu, tm, 1));
            tm = fmaxf(tm, __shfl_xor_sync(0xffffffffu, tm, 2));
            const float mold = m_sh[r];
            const float mnew = fmaxf(mold, tm);
            float ts = 0.f;
#pragma unroll
            for (int c = 0; c < 16; c++) {
                float p = __expf(Ss[r * 65 + seg + c] - mnew);
                Ss[r * 65 + seg + c] = p;
                ts += p;
            }
            ts += __shfl_xor_sync(0xffffffffu, ts, 1);
            ts += __shfl_xor_sync(0xffffffffu, ts, 2);
            if ((tid & 3) == 0) {
                const float cf = __expf(mold - mnew);
                c_sh[r] = cf;
                l_sh[r] = l_sh[r] * cf + ts;
                m_sh[r] = mnew;
            }
        }
        __syncthreads();

        // acc = acc * c + P @ V
        float cf0 = c_sh[ty * 4 + 0];
        float cf1 = c_sh[ty * 4 + 1];
        float cf2 = c_sh[ty * 4 + 2];
        float cf3 = c_sh[ty * 4 + 3];
#pragma unroll
        for (int j = 0; j < 4; j++) {
            acc[0][j] *= cf0; acc[1][j] *= cf1;
            acc[2][j] *= cf2; acc[3][j] *= cf3;
        }
#pragma unroll
        for (int kk = 0; kk < 64; kk++) {
            float p0 = Ss[(ty * 4 + 0) * 65 + kk];
            float p1 = Ss[(ty * 4 + 1) * 65 + kk];
            float p2 = Ss[(ty * 4 + 2) * 65 + kk];
            float p3 = Ss[(ty * 4 + 3) * 65 + kk];
            float v0 = Vs[kk * 65 + tx * 4 + 0];
            float v1 = Vs[kk * 65 + tx * 4 + 1];
            float v2 = Vs[kk * 65 + tx * 4 + 2];
            float v3 = Vs[kk * 65 + tx * 4 + 3];
            acc[0][0] = fmaf(p0, v0, acc[0][0]); acc[0][1] = fmaf(p0, v1, acc[0][1]);
            acc[0][2] = fmaf(p0, v2, acc[0][2]); acc[0][3] = fmaf(p0, v3, acc[0][3]);
            acc[1][0] = fmaf(p1, v0, acc[1][0]); acc[1][1] = fmaf(p1, v1, acc[1][1]);
            acc[1][2] = fmaf(p1, v2, acc[1][2]); acc[1][3] = fmaf(p1, v3, acc[1][3]);
            acc[2][0] = fmaf(p2, v0, acc[2][0]); acc[2][1] = fmaf(p2, v1, acc[2][1]);
            acc[2][2] = fmaf(p2, v2, acc[2][2]); acc[2][3] = fmaf(p2, v3, acc[2][3]);
            acc[3][0] = fmaf(p3, v0, acc[3][0]); acc[3][1] = fmaf(p3, v1, acc[3][1]);
            acc[3][2] = fmaf(p3, v2, acc[3][2]); acc[3][3] = fmaf(p3, v3, acc[3][3]);
        }
        __syncthreads();
    }

    // Write: g_attn[b][q][h*64 + d] = acc / l
#pragma unroll
    for (int i = 0; i < 4; i++) {
        const float inv = 1.0f / l_sh[ty * 4 + i];
        const int q = q0 + ty * 4 + i;
        float4 v;
        v.x = acc[i][0] * inv;
        v.y = acc[i][1] * inv;
        v.z = acc[i][2] * inv;
        v.w = acc[i][3] * inv;
        *(float4*)(g_attn + ((size_t)b * S_ + q) * E_ + h * D_ + tx * 4) = v;
    }
}

// ---------------------------------------------------------------------------
// Kernel 3: output projection. C = g_attn(8192x768) @ Wo(768x768) + bo
// Same tiling as kernel 1.
// ---------------------------------------------------------------------------
__global__ __launch_bounds__(256)
void out_gemm_kernel(const float* __restrict__ Wo, const float* __restrict__ bo,
                     float* __restrict__ out)
{
    __shared__ __align__(16) float As[16][64];
    __shared__ __align__(16) float Bs[16][64];

    const int tid = threadIdx.x;
    const int ty = tid >> 4;
    const int tx = tid & 15;
    const int m0 = blockIdx.y * 64;
    const int n0 = blockIdx.x * 64;

    const int arow = tid >> 2;
    const int acol = (tid & 3) * 4;
    const int brow = tid >> 4;
    const int bcol = (tid & 15) * 4;

    float acc[4][4] = {};

    for (int k0 = 0; k0 < E_; k0 += 16) {
        float4 av = *(const float4*)(g_attn + (size_t)(m0 + arow) * E_ + k0 + acol);
        As[acol + 0][arow] = av.x;
        As[acol + 1][arow] = av.y;
        As[acol + 2][arow] = av.z;
        As[acol + 3][arow] = av.w;
        float4 wv = *(const float4*)(Wo + (size_t)(k0 + brow) * E_ + n0 + bcol);
        *(float4*)&Bs[brow][bcol] = wv;
        __syncthreads();

#pragma unroll
        for (int kk = 0; kk < 16; kk++) {
            float4 a = *(const float4*)&As[kk][ty * 4];
            float4 b = *(const float4*)&Bs[kk][tx * 4];
            float ar[4] = {a.x, a.y, a.z, a.w};
            float br[4] = {b.x, b.y, b.z, b.w};
#pragma unroll
            for (int i = 0; i < 4; i++)
#pragma unroll
                for (int j = 0; j < 4; j++)
                    acc[i][j] = fmaf(ar[i], br[j], acc[i][j]);
        }
        __syncthreads();
    }

    const int n = n0 + tx * 4;
    float4 bb = *(const float4*)(bo + n);
#pragma unroll
    for (int i = 0; i < 4; i++) {
        const int r = m0 + ty * 4 + i;
        float4 v;
        v.x = acc[i][0] + bb.x;
        v.y = acc[i][1] + bb.y;
        v.z = acc[i][2] + bb.z;
        v.w = acc[i][3] + bb.w;
        *(float4*)(out + (size_t)r * E_ + n) = v;
    }
}

// ---------------------------------------------------------------------------
// Launch
// ---------------------------------------------------------------------------
extern "C" void kernel_launch(void* const* d_in, const int* in_sizes, int n_in,
                              void* d_out, int out_size)
{
    const float* x    = (const float*)d_in[0];
    const int*   mask = (const int*)d_in[1];
    const float* Wq   = (const float*)d_in[2];
    const float* bq   = (const float*)d_in[3];
    const float* Wk   = (const float*)d_in[4];
    const float* bk   = (const float*)d_in[5];
    const float* Wv   = (const float*)d_in[6];
    const float* bv   = (const float*)d_in[7];
    const float* Wo   = (const float*)d_in[8];
    const float* bo   = (const float*)d_in[9];
    float* out = (float*)d_out;

    // Kernel 1: fused QKV projection
    {
        dim3 grid(QKV_COLS / 64, N_ROWS / 64);   // (36, 128)
        qkv_gemm_kernel<<<grid, 256>>>(x, Wq, bq, Wk, bk, Wv, bv);
    }
    // Kernel 2: flash attention
    {
        cudaFuncSetAttribute(flash_attn_kernel,
                             cudaFuncAttributeMaxDynamicSharedMemorySize,
                             FA_SMEM_BYTES);
        dim3 grid(S_ / 64, H_, B_);              // (32, 12, 4)
        flash_attn_kernel<<<grid, 256, FA_SMEM_BYTES>>>(mask);
    }
    // Kernel 3: output projection
    {
        dim3 grid(E_ / 64, N_ROWS / 64);         // (12, 128)
        out_gemm_kernel<<<grid, 256>>>(Wo, bo, out);
    }
}

// round 3
// speedup vs baseline: 1.2197x; 1.2197x over previous
#include <cuda_runtime.h>
#include <math.h>

#define B_  4
#define S_  2048
#define E_  768
#define H_  12
#define D_  64
#define NR  (B_ * S_)

// Scratch
__device__ float g_Q[(size_t)B_ * H_ * S_ * D_];
__device__ float g_K[(size_t)B_ * H_ * S_ * D_];
__device__ float g_V[(size_t)B_ * H_ * S_ * D_];
__device__ float g_attn[(size_t)NR * E_];

// ---------------------------------------------------------------------------
// Kernel 1: fused QKV projection. 128x128x16 tiles, 256 threads, 8x8 micro.
// Block covers 128 output cols = 2 heads of one of {Q,K,V}.
// ---------------------------------------------------------------------------
__global__ __launch_bounds__(256)
void qkv_gemm_kernel(const float* __restrict__ x,
                     const float* __restrict__ Wq, const float* __restrict__ bq,
                     const float* __restrict__ Wk, const float* __restrict__ bk,
                     const float* __restrict__ Wv, const float* __restrict__ bv)
{
    __shared__ __align__(16) float As[16][132];   // [k][m]
    __shared__ __align__(16) float Bs[16][132];   // [k][n]

    const int tid = threadIdx.x;
    const int ty = tid >> 4, tx = tid & 15;
    const int m0 = blockIdx.y * 128;
    const int j0 = blockIdx.x * 128;
    const int sel = j0 / E_;
    const int jrem = j0 % E_;

    const float* W   = (sel == 0) ? Wq : (sel == 1) ? Wk : Wv;
    const float* bia = (sel == 0) ? bq : (sel == 1) ? bk : bv;
    float* outp      = (sel == 0) ? g_Q : (sel == 1) ? g_K : g_V;

    // A load mapping: thread covers (m=tid>>2, k=(tid&3)*4) and m+64
    const int am = tid >> 2;
    const int ak = (tid & 3) * 4;
    // B load mapping: rows brow, brow+8; cols bcol..bcol+3
    const int brow = tid >> 5;
    const int bcol = (tid & 31) * 4;
    const int jb = jrem + bcol;
    const float* Wb = W + (size_t)(jb >> 6) * E_ * D_ + (jb & 63);

    const float* xa0 = x + (size_t)(m0 + am) * E_ + ak;
    const float* xa1 = x + (size_t)(m0 + 64 + am) * E_ + ak;

    float4 aP0 = *(const float4*)xa0;
    float4 aP1 = *(const float4*)xa1;
    float4 bP0 = *(const float4*)(Wb + (size_t)brow * D_);
    float4 bP1 = *(const float4*)(Wb + (size_t)(brow + 8) * D_);

    float acc[8][8] = {};

    for (int k0 = 0; k0 < E_; k0 += 16) {
        As[ak+0][am] = aP0.x; As[ak+1][am] = aP0.y;
        As[ak+2][am] = aP0.z; As[ak+3][am] = aP0.w;
        As[ak+0][64+am] = aP1.x; As[ak+1][64+am] = aP1.y;
        As[ak+2][64+am] = aP1.z; As[ak+3][64+am] = aP1.w;
        *(float4*)&Bs[brow][bcol]   = bP0;
        *(float4*)&Bs[brow+8][bcol] = bP1;
        __syncthreads();

        if (k0 + 16 < E_) {   // prefetch next tile into regs (overlaps compute)
            aP0 = *(const float4*)(xa0 + k0 + 16);
            aP1 = *(const float4*)(xa1 + k0 + 16);
            bP0 = *(const float4*)(Wb + (size_t)(k0 + 16 + brow) * D_);
            bP1 = *(const float4*)(Wb + (size_t)(k0 + 24 + brow) * D_);
        }

#pragma unroll
        for (int kk = 0; kk < 16; kk++) {
            float4 a0 = *(const float4*)&As[kk][ty*8];
            float4 a1 = *(const float4*)&As[kk][ty*8+4];
            float4 b0 = *(const float4*)&Bs[kk][tx*4];
            float4 b1 = *(const float4*)&Bs[kk][64+tx*4];
            float ar[8] = {a0.x,a0.y,a0.z,a0.w,a1.x,a1.y,a1.z,a1.w};
            float br[8] = {b0.x,b0.y,b0.z,b0.w,b1.x,b1.y,b1.z,b1.w};
#pragma unroll
            for (int i = 0; i < 8; i++)
#pragma unroll
                for (int j = 0; j < 8; j++)
                    acc[i][j] = fmaf(ar[i], br[j], acc[i][j]);
        }
        __syncthreads();
    }

    // Epilogue: bias + write [B][H][S][D]. Col groups: tx*4 and 64+tx*4.
    const int jt0 = jrem + tx*4;
    const int jt1 = jrem + 64 + tx*4;
    const int h0 = jt0 >> 6, d0 = jt0 & 63;
    const int h1 = jt1 >> 6, d1 = jt1 & 63;
    float4 bb0 = *(const float4*)(bia + h0*D_ + d0);
    float4 bb1 = *(const float4*)(bia + h1*D_ + d1);
#pragma unroll
    for (int i = 0; i < 8; i++) {
        const int r = m0 + ty*8 + i;
        const int bb = r >> 11;            // / S_
        const int s  = r & (S_ - 1);
        const size_t rb = ((size_t)bb * H_) * S_ * D_ + (size_t)s * D_;
        float4 v0 = make_float4(acc[i][0]+bb0.x, acc[i][1]+bb0.y,
                                acc[i][2]+bb0.z, acc[i][3]+bb0.w);
        float4 v1 = make_float4(acc[i][4]+bb1.x, acc[i][5]+bb1.y,
                                acc[i][6]+bb1.z, acc[i][7]+bb1.w);
        *(float4*)(outp + rb + (size_t)h0 * S_ * D_ + d0) = v0;
        *(float4*)(outp + rb + (size_t)h1 * S_ * D_ + d1) = v1;
    }
}

// ---------------------------------------------------------------------------
// Kernel 2: flash attention. Bq=128, Bk=128, 256 threads.
// Score: 8x8 per thread; PV: 8x4 per thread.
// Layouts: Qt[64][132] (transposed, vec loads), Ks[128][65] (scalar reads,
// 2-way max conflicts), Vs[128][68] (vec), Ss[128][132] (row-major P).
// ---------------------------------------------------------------------------
#define LDQ 132
#define LDK 65
#define LDV 68
#define LDSS 132
#define FA_SMEM ((64*LDQ + 128*LDK + 128*LDV + 128*LDSS + 3*128) * 4 + 128 * 4)

__global__ __launch_bounds__(256)
void flash_attn_kernel(const int* __restrict__ mask)
{
    extern __shared__ __align__(16) float sm[];
    float* Qt   = sm;                       // [64][LDQ]  (d, q)
    float* Ks   = Qt + 64*LDQ;              // [128][LDK] (k, d)
    float* Vs   = Ks + 128*LDK;             // [128][LDV] (k, d)
    float* Ss   = Vs + 128*LDV;             // [128][LDSS] (q, k)
    float* m_sh = Ss + 128*LDSS;
    float* l_sh = m_sh + 128;
    float* c_sh = l_sh + 128;
    int*   msk  = (int*)(c_sh + 128);

    const int tid = threadIdx.x;
    const int ty = tid >> 4, tx = tid & 15;
    const int q0 = blockIdx.x * 128;
    const int h = blockIdx.y, b = blockIdx.z;
    const size_t base = ((size_t)b * H_ + h) * S_ * D_;

    // Load Q tile, store transposed (one-time cost)
#pragma unroll
    for (int it = 0; it < 8; it++) {
        const int qr = it*16 + ty;
        float4 t = *(const float4*)(g_Q + base + (size_t)(q0+qr)*D_ + tx*4);
        Qt[(tx*4+0)*LDQ + qr] = t.x;
        Qt[(tx*4+1)*LDQ + qr] = t.y;
        Qt[(tx*4+2)*LDQ + qr] = t.z;
        Qt[(tx*4+3)*LDQ + qr] = t.w;
    }
    if (tid < 128) { m_sh[tid] = -INFINITY; l_sh[tid] = 0.f; }

    float acc[8][4] = {};
    __syncthreads();

    for (int k0 = 0; k0 < S_; k0 += 128) {
        // K (scalar store, row-major ld=65) and V (vec store)
#pragma unroll
        for (int it = 0; it < 8; it++) {
            const int kr = it*16 + ty;
            float4 t = *(const float4*)(g_K + base + (size_t)(k0+kr)*D_ + tx*4);
            Ks[kr*LDK + tx*4+0] = t.x;
            Ks[kr*LDK + tx*4+1] = t.y;
            Ks[kr*LDK + tx*4+2] = t.z;
            Ks[kr*LDK + tx*4+3] = t.w;
            float4 u = *(const float4*)(g_V + base + (size_t)(k0+kr)*D_ + tx*4);
            *(float4*)&Vs[kr*LDV + tx*4] = u;
        }
        if (tid < 128) msk[tid] = mask[(size_t)b * S_ + k0 + tid];
        __syncthreads();

        // Scores: 8 q-rows (ty*8..) x 8 k-cols ({tx*4, 64+tx*4})
        float sc[8][8];
#pragma unroll
        for (int i = 0; i < 8; i++)
#pragma unroll
            for (int j = 0; j < 8; j++) sc[i][j] = 0.f;

#pragma unroll 8
        for (int d = 0; d < 64; d++) {
            float4 a0 = *(const float4*)&Qt[d*LDQ + ty*8];
            float4 a1 = *(const float4*)&Qt[d*LDQ + ty*8 + 4];
            float ar[8] = {a0.x,a0.y,a0.z,a0.w,a1.x,a1.y,a1.z,a1.w};
            float br[8];
#pragma unroll
            for (int j = 0; j < 4; j++) br[j]   = Ks[(tx*4+j)*LDK + d];
#pragma unroll
            for (int j = 0; j < 4; j++) br[4+j] = Ks[(64+tx*4+j)*LDK + d];
#pragma unroll
            for (int i = 0; i < 8; i++)
#pragma unroll
                for (int j = 0; j < 8; j++)
                    sc[i][j] = fmaf(ar[i], br[j], sc[i][j]);
        }

        // scale + mask + store P-input to Ss (vectorized)
        int mk[8];
#pragma unroll
        for (int j = 0; j < 4; j++) { mk[j] = msk[tx*4+j]; mk[4+j] = msk[64+tx*4+j]; }
#pragma unroll
        for (int i = 0; i < 8; i++) {
            float v[8];
#pragma unroll
            for (int j = 0; j < 8; j++) {
                float s = sc[i][j] * 0.125f;
                v[j] = (mk[j] == 0) ? -1000000000.0f : s;
            }
            *(float4*)&Ss[(ty*8+i)*LDSS + tx*4]      = make_float4(v[0],v[1],v[2],v[3]);
            *(float4*)&Ss[(ty*8+i)*LDSS + 64 + tx*4] = make_float4(v[4],v[5],v[6],v[7]);
        }
        __syncthreads();

        // Online softmax: 2 threads per row, 64 cols each
        {
            const int r = tid >> 1;
            float* row = &Ss[r*LDSS + (tid & 1) * 64];
            float tm = -INFINITY;
#pragma unroll 16
            for (int c = 0; c < 64; c++) tm = fmaxf(tm, row[c]);
            tm = fmaxf(tm, __shfl_xor_sync(0xffffffffu, tm, 1));
            const float mold = m_sh[r];
            const float mnew = fmaxf(mold, tm);
            float ts = 0.f;
#pragma unroll 16
            for (int c = 0; c < 64; c++) {
                float p = __expf(row[c] - mnew);
                row[c] = p;
                ts += p;
            }
            ts += __shfl_xor_sync(0xffffffffu, ts, 1);
            if ((tid & 1) == 0) {
                const float cf = __expf(mold - mnew);
                c_sh[r] = cf;
                l_sh[r] = l_sh[r] * cf + ts;
                m_sh[r] = mnew;
            }
        }
        __syncthreads();

        // acc = acc * cf + P @ V   (8 rows x 4 d-cols per thread)
#pragma unroll
        for (int i = 0; i < 8; i++) {
            const float cf = c_sh[ty*8 + i];
            acc[i][0] *= cf; acc[i][1] *= cf; acc[i][2] *= cf; acc[i][3] *= cf;
        }
#pragma unroll 4
        for (int kk = 0; kk < 128; kk++) {
            float4 vv = *(const float4*)&Vs[kk*LDV + tx*4];
#pragma unroll
            for (int i = 0; i < 8; i++) {
                const float p = Ss[(ty*8+i)*LDSS + kk];   // broadcast
                acc[i][0] = fmaf(p, vv.x, acc[i][0]);
                acc[i][1] = fmaf(p, vv.y, acc[i][1]);
                acc[i][2] = fmaf(p, vv.z, acc[i][2]);
                acc[i][3] = fmaf(p, vv.w, acc[i][3]);
            }
        }
        __syncthreads();
    }

    // Final normalize + write to [B, S, H*D]
#pragma unroll
    for (int i = 0; i < 8; i++) {
        const int r = ty*8 + i;
        const float inv = 1.0f / l_sh[r];
        float4 o = make_float4(acc[i][0]*inv, acc[i][1]*inv,
                               acc[i][2]*inv, acc[i][3]*inv);
        *(float4*)(g_attn + ((size_t)b * S_ + q0 + r) * E_ + h*D_ + tx*4) = o;
    }
}

// ---------------------------------------------------------------------------
// Kernel 3: output projection. 128x128x16, same structure as kernel 1.
// ---------------------------------------------------------------------------
__global__ __launch_bounds__(256)
void out_gemm_kernel(const float* __restrict__ Wo, const float* __restrict__ bo,
                     float* __restrict__ out)
{
    __shared__ __align__(16) float As[16][132];
    __shared__ __align__(16) float Bs[16][132];

    const int tid = threadIdx.x;
    const int ty = tid >> 4, tx = tid & 15;
    const int m0 = blockIdx.y * 128;
    const int n0 = blockIdx.x * 128;

    const int am = tid >> 2;
    const int ak = (tid & 3) * 4;
    const int brow = tid >> 5;
    const int bcol = (tid & 31) * 4;

    const float* xa0 = g_attn + (size_t)(m0 + am) * E_ + ak;
    const float* xa1 = g_attn + (size_t)(m0 + 64 + am) * E_ + ak;
    const float* Wb  = Wo + n0 + bcol;

    float4 aP0 = *(const float4*)xa0;
    float4 aP1 = *(const float4*)xa1;
    float4 bP0 = *(const float4*)(Wb + (size_t)brow * E_);
    float4 bP1 = *(const float4*)(Wb + (size_t)(brow + 8) * E_);

    float acc[8][8] = {};

    for (int k0 = 0; k0 < E_; k0 += 16) {
        As[ak+0][am] = aP0.x; As[ak+1][am] = aP0.y;
        As[ak+2][am] = aP0.z; As[ak+3][am] = aP0.w;
        As[ak+0][64+am] = aP1.x; As[ak+1][64+am] = aP1.y;
        As[ak+2][64+am] = aP1.z; As[ak+3][64+am] = aP1.w;
        *(float4*)&Bs[brow][bcol]   = bP0;
        *(float4*)&Bs[brow+8][bcol] = bP1;
        __syncthreads();

        if (k0 + 16 < E_) {
            aP0 = *(const float4*)(xa0 + k0 + 16);
            aP1 = *(const float4*)(xa1 + k0 + 16);
            bP0 = *(const float4*)(Wb + (size_t)(k0 + 16 + brow) * E_);
            bP1 = *(const float4*)(Wb + (size_t)(k0 + 24 + brow) * E_);
        }

#pragma unroll
        for (int kk = 0; kk < 16; kk++) {
            float4 a0 = *(const float4*)&As[kk][ty*8];
            float4 a1 = *(const float4*)&As[kk][ty*8+4];
            float4 b0 = *(const float4*)&Bs[kk][tx*4];
            float4 b1 = *(const float4*)&Bs[kk][64+tx*4];
            float ar[8] = {a0.x,a0.y,a0.z,a0.w,a1.x,a1.y,a1.z,a1.w};
            float br[8] = {b0.x,b0.y,b0.z,b0.w,b1.x,b1.y,b1.z,b1.w};
#pragma unroll
            for (int i = 0; i < 8; i++)
#pragma unroll
                for (int j = 0; j < 8; j++)
                    acc[i][j] = fmaf(ar[i], br[j], acc[i][j]);
        }
        __syncthreads();
    }

    float4 bb0 = *(const float4*)(bo + n0 + tx*4);
    float4 bb1 = *(const float4*)(bo + n0 + 64 + tx*4);
#pragma unroll
    for (int i = 0; i < 8; i++) {
        const int r = m0 + ty*8 + i;
        float4 v0 = make_float4(acc[i][0]+bb0.x, acc[i][1]+bb0.y,
                                acc[i][2]+bb0.z, acc[i][3]+bb0.w);
        float4 v1 = make_float4(acc[i][4]+bb1.x, acc[i][5]+bb1.y,
                                acc[i][6]+bb1.z, acc[i][7]+bb1.w);
        *(float4*)(out + (size_t)r * E_ + n0 + tx*4)      = v0;
        *(float4*)(out + (size_t)r * E_ + n0 + 64 + tx*4) = v1;
    }
}

// ---------------------------------------------------------------------------
// Launch
// ---------------------------------------------------------------------------
extern "C" void kernel_launch(void* const* d_in, const int* in_sizes, int n_in,
                              void* d_out, int out_size)
{
    const float* x    = (const float*)d_in[0];
    const int*   mask = (const int*)d_in[1];
    const float* Wq   = (const float*)d_in[2];
    const float* bq   = (const float*)d_in[3];
    const float* Wk   = (const float*)d_in[4];
    const float* bk   = (const float*)d_in[5];
    const float* Wv   = (const float*)d_in[6];
    const float* bv   = (const float*)d_in[7];
    const float* Wo   = (const float*)d_in[8];
    const float* bo   = (const float*)d_in[9];
    float* out = (float*)d_out;

    {
        dim3 grid(18, 64);    // 2304/128, 8192/128
        qkv_gemm_kernel<<<grid, 256>>>(x, Wq, bq, Wk, bk, Wv, bv);
    }
    {
        static int smem_set = 0;
        cudaFuncSetAttribute(flash_attn_kernel,
                             cudaFuncAttributeMaxDynamicSharedMemorySize,
                             FA_SMEM);
        (void)smem_set;
        dim3 grid(S_ / 128, H_, B_);   // (16, 12, 4)
        flash_attn_kernel<<<grid, 256, FA_SMEM>>>(mask);
    }
    {
        dim3 grid(6, 64);     // 768/128, 8192/128
        out_gemm_kernel<<<grid, 256>>>(Wo, bo, out);
    }
}

// round 6
// speedup vs baseline: 1.4195x; 1.1639x over previous
#include <cuda_runtime.h>
#include <cuda_bf16.h>
#include <stdint.h>
#include <math.h>

#define B_  4
#define S_  2048
#define E_  768
#define H_  12
#define D_  64
#define NR  (B_ * S_)

// Scratch
__device__ float g_Q[(size_t)B_ * H_ * S_ * D_];
__device__ float g_K[(size_t)B_ * H_ * S_ * D_];
__device__ float g_V[(size_t)B_ * H_ * S_ * D_];
__device__ float g_attn[(size_t)NR * E_];

// ===========================================================================
// mma.sync helper: m16n8k16 bf16 -> fp32
// ===========================================================================
__device__ __forceinline__ void mma16816(float* d, const uint32_t* a, const uint32_t* b) {
    asm volatile(
        "mma.sync.aligned.m16n8k16.row.col.f32.bf16.bf16.f32 "
        "{%0,%1,%2,%3}, {%4,%5,%6,%7}, {%8,%9}, {%0,%1,%2,%3};"
        : "+f"(d[0]), "+f"(d[1]), "+f"(d[2]), "+f"(d[3])
        : "r"(a[0]), "r"(a[1]), "r"(a[2]), "r"(a[3]), "r"(b[0]), "r"(b[1]));
}

// ---------------------------------------------------------------------------
// Shared GEMM body: D[128 x 64] = A[128 x 768] @ B (B[n][k] via accessor),
// split-bf16 (hh + hl + lh), fp32 accumulate via HMMA.
// 256 threads = 8 warps (4m x 2n), warp tile 32x32, BK=32.
// Result: d[2][4][4] per thread (m16n8 fragment layout).
// ---------------------------------------------------------------------------
#define GPITCH 40   // halves per row (32 data + 8 pad)

__device__ __forceinline__ void gemm_hmma_body(
    const float* __restrict__ Arow, const float* __restrict__ Bsrc, int ldb,
    float d[2][4][4])
{
    __shared__ __align__(16) __nv_bfloat16 As_hi[128][GPITCH];
    __shared__ __align__(16) __nv_bfloat16 As_lo[128][GPITCH];
    __shared__ __align__(16) __nv_bfloat16 Bs_hi[64][GPITCH];
    __shared__ __align__(16) __nv_bfloat16 Bs_lo[64][GPITCH];

    const int tid = threadIdx.x;
    const int wid = tid >> 5, lane = tid & 31;
    const int wm = wid & 3;          // 0..3 : m tile (32 rows)
    const int wn = wid >> 2;         // 0..1 : n tile (32 cols)
    const int fr = lane >> 2;        // 0..7
    const int fc = (lane & 3) * 2;   // 0,2,4,6

    // loaders
    const int arow = tid >> 1;             // 0..127
    const int ac0 = (tid & 1) * 16;        // 0 / 16
    const int bn = tid & 63;               // 0..63
    const int bk0 = (tid >> 6) * 8;        // 0,8,16,24

#pragma unroll
    for (int mt = 0; mt < 2; mt++)
#pragma unroll
        for (int nt = 0; nt < 4; nt++)
#pragma unroll
            for (int e = 0; e < 4; e++) d[mt][nt][e] = 0.f;

    for (int kb = 0; kb < E_ / 32; kb++) {
        // ---- load A tile (128 x 32 fp32 -> hi/lo bf16) ----
        {
            const float* ap = Arow + (size_t)arow * E_ + kb * 32 + ac0;
#pragma unroll
            for (int i = 0; i < 4; i++) {
                float4 v = *(const float4*)(ap + i * 4);
                __nv_bfloat162 h01 = __floats2bfloat162_rn(v.x, v.y);
                __nv_bfloat162 h23 = __floats2bfloat162_rn(v.z, v.w);
                __nv_bfloat162 l01 = __floats2bfloat162_rn(
                    v.x - __bfloat162float(h01.x), v.y - __bfloat162float(h01.y));
                __nv_bfloat162 l23 = __floats2bfloat162_rn(
                    v.z - __bfloat162float(h23.x), v.w - __bfloat162float(h23.y));
                *(uint2*)&As_hi[arow][ac0 + i * 4] =
                    make_uint2(*(uint32_t*)&h01, *(uint32_t*)&h23);
                *(uint2*)&As_lo[arow][ac0 + i * 4] =
                    make_uint2(*(uint32_t*)&l01, *(uint32_t*)&l23);
            }
        }
        // ---- load B tile (64 n x 32 k) ----
        {
#pragma unroll
            for (int i = 0; i < 8; i++) {
                int k = bk0 + i;
                float v = Bsrc[(size_t)(kb * 32 + k) * ldb + bn];
                __nv_bfloat16 hb = __float2bfloat16_rn(v);
                __nv_bfloat16 lb = __float2bfloat16_rn(v - __bfloat162float(hb));
                Bs_hi[bn][k] = hb;
                Bs_lo[bn][k] = lb;
            }
        }
        __syncthreads();

#pragma unroll
        for (int ks = 0; ks < 2; ks++) {
            const int k = ks * 16;
            // A fragments (hi & lo) for 2 m-tiles
            uint32_t ah[2][4], al[2][4];
#pragma unroll
            for (int mt = 0; mt < 2; mt++) {
                const int rb = wm * 32 + mt * 16;
                ah[mt][0] = *(const uint32_t*)&As_hi[rb + fr    ][k + fc    ];
                ah[mt][1] = *(const uint32_t*)&As_hi[rb + fr + 8][k + fc    ];
                ah[mt][2] = *(const uint32_t*)&As_hi[rb + fr    ][k + fc + 8];
                ah[mt][3] = *(const uint32_t*)&As_hi[rb + fr + 8][k + fc + 8];
                al[mt][0] = *(const uint32_t*)&As_lo[rb + fr    ][k + fc    ];
                al[mt][1] = *(const uint32_t*)&As_lo[rb + fr + 8][k + fc    ];
                al[mt][2] = *(const uint32_t*)&As_lo[rb + fr    ][k + fc + 8];
                al[mt][3] = *(const uint32_t*)&As_lo[rb + fr + 8][k + fc + 8];
            }
            // B fragments (hi & lo) for 4 n-tiles
            uint32_t bh[4][2], bl[4][2];
#pragma unroll
            for (int nt = 0; nt < 4; nt++) {
                const int nb = wn * 32 + nt * 8 + fr;   // fr = n within tile? no:
                // B frag: lane -> n = lane>>2 (0..7), k = (lane&3)*2
                const int nn = wn * 32 + nt * 8 + (lane >> 2);
                const int kk = k + fc;
                bh[nt][0] = *(const uint32_t*)&Bs_hi[nn][kk    ];
                bh[nt][1] = *(const uint32_t*)&Bs_hi[nn][kk + 8];
                bl[nt][0] = *(const uint32_t*)&Bs_lo[nn][kk    ];
                bl[nt][1] = *(const uint32_t*)&Bs_lo[nn][kk + 8];
                (void)nb;
            }
            // 3-term split MMA
#pragma unroll
            for (int mt = 0; mt < 2; mt++)
#pragma unroll
                for (int nt = 0; nt < 4; nt++) {
                    mma16816(d[mt][nt], ah[mt], bh[nt]);
                    mma16816(d[mt][nt], ah[mt], bl[nt]);
                    mma16816(d[mt][nt], al[mt], bh[nt]);
                }
        }
        __syncthreads();
    }
}

// ---------------------------------------------------------------------------
// Kernel 1: QKV projection. grid = (2304/64, 8192/128)
// ---------------------------------------------------------------------------
__global__ __launch_bounds__(256)
void qkv_hmma_kernel(const float* __restrict__ x,
                     const float* __restrict__ Wq, const float* __restrict__ bq,
                     const float* __restrict__ Wk, const float* __restrict__ bk,
                     const float* __restrict__ Wv, const float* __restrict__ bv)
{
    const int m0 = blockIdx.y * 128;
    const int j0 = blockIdx.x * 64;
    const int sel = j0 / E_;
    const int h = (j0 % E_) >> 6;

    const float* W   = (sel == 0) ? Wq : (sel == 1) ? Wk : Wv;
    const float* bia = (sel == 0) ? bq : (sel == 1) ? bk : bv;
    float* outp      = (sel == 0) ? g_Q : (sel == 1) ? g_K : g_V;
    const float* Bsrc = W + (size_t)h * E_ * D_;   // B[n][k] = Bsrc[k*64 + n]

    float d[2][4][4];
    gemm_hmma_body(x + (size_t)m0 * E_, Bsrc, D_, d);

    const int wid = threadIdx.x >> 5, lane = threadIdx.x & 31;
    const int wm = wid & 3, wn = wid >> 2;
    const int fr = lane >> 2, fc = (lane & 3) * 2;
    const float* brow = bia + h * D_;

#pragma unroll
    for (int mt = 0; mt < 2; mt++) {
#pragma unroll
        for (int half = 0; half < 2; half++) {
            const int row = m0 + wm * 32 + mt * 16 + fr + half * 8;
            const int bb = row >> 11;
            const int s = row & (S_ - 1);
            float* orow = outp + (((size_t)bb * H_ + h) * S_ + s) * D_;
#pragma unroll
            for (int nt = 0; nt < 4; nt++) {
                const int col = wn * 32 + nt * 8 + fc;
                float2 v;
                v.x = d[mt][nt][half * 2 + 0] + brow[col];
                v.y = d[mt][nt][half * 2 + 1] + brow[col + 1];
                *(float2*)(orow + col) = v;
            }
        }
    }
}

// ---------------------------------------------------------------------------
// Kernel 3: output projection. grid = (768/64, 8192/128)
// ---------------------------------------------------------------------------
__global__ __launch_bounds__(256)
void out_hmma_kernel(const float* __restrict__ Wo, const float* __restrict__ bo,
                     float* __restrict__ out)
{
    const int m0 = blockIdx.y * 128;
    const int n0 = blockIdx.x * 64;
    const float* Bsrc = Wo + n0;                   // B[n][k] = Bsrc[k*768 + n]

    float d[2][4][4];
    gemm_hmma_body(g_attn + (size_t)m0 * E_, Bsrc, E_, d);

    const int wid = threadIdx.x >> 5, lane = threadIdx.x & 31;
    const int wm = wid & 3, wn = wid >> 2;
    const int fr = lane >> 2, fc = (lane & 3) * 2;

#pragma unroll
    for (int mt = 0; mt < 2; mt++) {
#pragma unroll
        for (int half = 0; half < 2; half++) {
            const int row = m0 + wm * 32 + mt * 16 + fr + half * 8;
            float* orow = out + (size_t)row * E_ + n0;
#pragma unroll
            for (int nt = 0; nt < 4; nt++) {
                const int col = wn * 32 + nt * 8 + fc;
                float2 v;
                v.x = d[mt][nt][half * 2 + 0] + bo[n0 + col];
                v.y = d[mt][nt][half * 2 + 1] + bo[n0 + col + 1];
                *(float2*)(orow + col) = v;
            }
        }
    }
}

// ---------------------------------------------------------------------------
// Kernel 2: flash attention (fp32) — unchanged (known good).
// ---------------------------------------------------------------------------
#define LDQ 132
#define LDK 65
#define LDV 68
#define LDSS 132
#define FA_SMEM ((64*LDQ + 128*LDK + 128*LDV + 128*LDSS + 3*128) * 4 + 128 * 4)

__global__ __launch_bounds__(256)
void flash_attn_kernel(const int* __restrict__ mask)
{
    extern __shared__ __align__(16) float sm[];
    float* Qt   = sm;
    float* Ks   = Qt + 64*LDQ;
    float* Vs   = Ks + 128*LDK;
    float* Ss   = Vs + 128*LDV;
    float* m_sh = Ss + 128*LDSS;
    float* l_sh = m_sh + 128;
    float* c_sh = l_sh + 128;
    int*   msk  = (int*)(c_sh + 128);

    const int tid = threadIdx.x;
    const int ty = tid >> 4, tx = tid & 15;
    const int q0 = blockIdx.x * 128;
    const int h = blockIdx.y, b = blockIdx.z;
    const size_t base = ((size_t)b * H_ + h) * S_ * D_;

#pragma unroll
    for (int it = 0; it < 8; it++) {
        const int qr = it*16 + ty;
        float4 t = *(const float4*)(g_Q + base + (size_t)(q0+qr)*D_ + tx*4);
        Qt[(tx*4+0)*LDQ + qr] = t.x;
        Qt[(tx*4+1)*LDQ + qr] = t.y;
        Qt[(tx*4+2)*LDQ + qr] = t.z;
        Qt[(tx*4+3)*LDQ + qr] = t.w;
    }
    if (tid < 128) { m_sh[tid] = -INFINITY; l_sh[tid] = 0.f; }

    float acc[8][4] = {};
    __syncthreads();

    for (int k0 = 0; k0 < S_; k0 += 128) {
#pragma unroll
        for (int it = 0; it < 8; it++) {
            const int kr = it*16 + ty;
            float4 t = *(const float4*)(g_K + base + (size_t)(k0+kr)*D_ + tx*4);
            Ks[kr*LDK + tx*4+0] = t.x;
            Ks[kr*LDK + tx*4+1] = t.y;
            Ks[kr*LDK + tx*4+2] = t.z;
            Ks[kr*LDK + tx*4+3] = t.w;
            float4 u = *(const float4*)(g_V + base + (size_t)(k0+kr)*D_ + tx*4);
            *(float4*)&Vs[kr*LDV + tx*4] = u;
        }
        if (tid < 128) msk[tid] = mask[(size_t)b * S_ + k0 + tid];
        __syncthreads();

        float sc[8][8];
#pragma unroll
        for (int i = 0; i < 8; i++)
#pragma unroll
            for (int j = 0; j < 8; j++) sc[i][j] = 0.f;

#pragma unroll 8
        for (int d = 0; d < 64; d++) {
            float4 a0 = *(const float4*)&Qt[d*LDQ + ty*8];
            float4 a1 = *(const float4*)&Qt[d*LDQ + ty*8 + 4];
            float ar[8] = {a0.x,a0.y,a0.z,a0.w,a1.x,a1.y,a1.z,a1.w};
            float br[8];
#pragma unroll
            for (int j = 0; j < 4; j++) br[j]   = Ks[(tx*4+j)*LDK + d];
#pragma unroll
            for (int j = 0; j < 4; j++) br[4+j] = Ks[(64+tx*4+j)*LDK + d];
#pragma unroll
            for (int i = 0; i < 8; i++)
#pragma unroll
                for (int j = 0; j < 8; j++)
                    sc[i][j] = fmaf(ar[i], br[j], sc[i][j]);
        }

        int mk[8];
#pragma unroll
        for (int j = 0; j < 4; j++) { mk[j] = msk[tx*4+j]; mk[4+j] = msk[64+tx*4+j]; }
#pragma unroll
        for (int i = 0; i < 8; i++) {
            float v[8];
#pragma unroll
            for (int j = 0; j < 8; j++) {
                float s = sc[i][j] * 0.125f;
                v[j] = (mk[j] == 0) ? -1000000000.0f : s;
            }
            *(float4*)&Ss[(ty*8+i)*LDSS + tx*4]      = make_float4(v[0],v[1],v[2],v[3]);
            *(float4*)&Ss[(ty*8+i)*LDSS + 64 + tx*4] = make_float4(v[4],v[5],v[6],v[7]);
        }
        __syncthreads();

        {
            const int r = tid >> 1;
            float* row = &Ss[r*LDSS + (tid & 1) * 64];
            float tm = -INFINITY;
#pragma unroll 16
            for (int c = 0; c < 64; c++) tm = fmaxf(tm, row[c]);
            tm = fmaxf(tm, __shfl_xor_sync(0xffffffffu, tm, 1));
            const float mold = m_sh[r];
            const float mnew = fmaxf(mold, tm);
            float ts = 0.f;
#pragma unroll 16
            for (int c = 0; c < 64; c++) {
                float p = __expf(row[c] - mnew);
                row[c] = p;
                ts += p;
            }
            ts += __shfl_xor_sync(0xffffffffu, ts, 1);
            if ((tid & 1) == 0) {
                const float cf = __expf(mold - mnew);
                c_sh[r] = cf;
                l_sh[r] = l_sh[r] * cf + ts;
                m_sh[r] = mnew;
            }
        }
        __syncthreads();

#pragma unroll
        for (int i = 0; i < 8; i++) {
            const float cf = c_sh[ty*8 + i];
            acc[i][0] *= cf; acc[i][1] *= cf; acc[i][2] *= cf; acc[i][3] *= cf;
        }
#pragma unroll 4
        for (int kk = 0; kk < 128; kk++) {
            float4 vv = *(const float4*)&Vs[kk*LDV + tx*4];
#pragma unroll
            for (int i = 0; i < 8; i++) {
                const float p = Ss[(ty*8+i)*LDSS + kk];
                acc[i][0] = fmaf(p, vv.x, acc[i][0]);
                acc[i][1] = fmaf(p, vv.y, acc[i][1]);
                acc[i][2] = fmaf(p, vv.z, acc[i][2]);
                acc[i][3] = fmaf(p, vv.w, acc[i][3]);
            }
        }
        __syncthreads();
    }

#pragma unroll
    for (int i = 0; i < 8; i++) {
        const int r = ty*8 + i;
        const float inv = 1.0f / l_sh[r];
        float4 o = make_float4(acc[i][0]*inv, acc[i][1]*inv,
                               acc[i][2]*inv, acc[i][3]*inv);
        *(float4*)(g_attn + ((size_t)b * S_ + q0 + r) * E_ + h*D_ + tx*4) = o;
    }
}

// ---------------------------------------------------------------------------
// Launch
// ---------------------------------------------------------------------------
extern "C" void kernel_launch(void* const* d_in, const int* in_sizes, int n_in,
                              void* d_out, int out_size)
{
    const float* x    = (const float*)d_in[0];
    const int*   mask = (const int*)d_in[1];
    const float* Wq   = (const float*)d_in[2];
    const float* bq   = (const float*)d_in[3];
    const float* Wk   = (const float*)d_in[4];
    const float* bk   = (const float*)d_in[5];
    const float* Wv   = (const float*)d_in[6];
    const float* bv   = (const float*)d_in[7];
    const float* Wo   = (const float*)d_in[8];
    const float* bo   = (const float*)d_in[9];
    float* out = (float*)d_out;

    cudaFuncSetAttribute(flash_attn_kernel,
                         cudaFuncAttributeMaxDynamicSharedMemorySize, FA_SMEM);

    {
        dim3 grid(36, 64);    // 2304/64, 8192/128
        qkv_hmma_kernel<<<grid, 256>>>(x, Wq, bq, Wk, bk, Wv, bv);
    }
    {
        dim3 grid(S_ / 128, H_, B_);   // (16, 12, 4)
        flash_attn_kernel<<<grid, 256, FA_SMEM>>>(mask);
    }
    {
        dim3 grid(12, 64);    // 768/64, 8192/128
        out_hmma_kernel<<<grid, 256>>>(Wo, bo, out);
    }
}

// round 7
// speedup vs baseline: 2.4316x; 1.7130x over previous
#include <cuda_runtime.h>
#include <cuda_bf16.h>
#include <stdint.h>
#include <math.h>

#define B_  4
#define S_  2048
#define E_  768
#define H_  12
#define D_  64
#define NR  (B_ * S_)

// Scratch
__device__ float g_Q[(size_t)B_ * H_ * S_ * D_];
__device__ float g_K[(size_t)B_ * H_ * S_ * D_];
__device__ float g_V[(size_t)B_ * H_ * S_ * D_];
__device__ float g_attn[(size_t)NR * E_];

// ===========================================================================
// mma.sync helpers
// ===========================================================================
__device__ __forceinline__ void mma16816(float* d, const uint32_t* a, const uint32_t* b) {
    asm volatile(
        "mma.sync.aligned.m16n8k16.row.col.f32.bf16.bf16.f32 "
        "{%0,%1,%2,%3}, {%4,%5,%6,%7}, {%8,%9}, {%0,%1,%2,%3};"
        : "+f"(d[0]), "+f"(d[1]), "+f"(d[2]), "+f"(d[3])
        : "r"(a[0]), "r"(a[1]), "r"(a[2]), "r"(a[3]), "r"(b[0]), "r"(b[1]));
}

__device__ __forceinline__ void ldsm_x4_trans(uint32_t* r, uint32_t addr) {
    asm volatile("ldmatrix.sync.aligned.m8n8.x4.trans.shared.b16 {%0,%1,%2,%3}, [%4];"
        : "=r"(r[0]), "=r"(r[1]), "=r"(r[2]), "=r"(r[3]) : "r"(addr));
}

__device__ __forceinline__ uint32_t smem_u32(const void* p) {
    uint32_t a;
    asm("{ .reg .u64 t; cvta.to.shared.u64 t, %1; cvt.u32.u64 %0, t; }"
        : "=r"(a) : "l"(p));
    return a;
}

__device__ __forceinline__ uint32_t packbf2(float x, float y) {
    __nv_bfloat162 t = __floats2bfloat162_rn(x, y);
    return *(uint32_t*)&t;
}

// ---------------------------------------------------------------------------
// GEMM body (unchanged from R6, verified): D[128x64] = A[128x768] @ B,
// split-bf16 (hh+hl+lh), HMMA. 8 warps (4m x 2n), warp tile 32x32, BK=32.
// ---------------------------------------------------------------------------
#define GPITCH 40

__device__ __forceinline__ void gemm_hmma_body(
    const float* __restrict__ Arow, const float* __restrict__ Bsrc, int ldb,
    float d[2][4][4])
{
    __shared__ __align__(16) __nv_bfloat16 As_hi[128][GPITCH];
    __shared__ __align__(16) __nv_bfloat16 As_lo[128][GPITCH];
    __shared__ __align__(16) __nv_bfloat16 Bs_hi[64][GPITCH];
    __shared__ __align__(16) __nv_bfloat16 Bs_lo[64][GPITCH];

    const int tid = threadIdx.x;
    const int wid = tid >> 5, lane = tid & 31;
    const int wm = wid & 3;
    const int wn = wid >> 2;
    const int fr = lane >> 2;
    const int fc = (lane & 3) * 2;

    const int arow = tid >> 1;
    const int ac0 = (tid & 1) * 16;
    const int bn = tid & 63;
    const int bk0 = (tid >> 6) * 8;

#pragma unroll
    for (int mt = 0; mt < 2; mt++)
#pragma unroll
        for (int nt = 0; nt < 4; nt++)
#pragma unroll
            for (int e = 0; e < 4; e++) d[mt][nt][e] = 0.f;

    for (int kb = 0; kb < E_ / 32; kb++) {
        {
            const float* ap = Arow + (size_t)arow * E_ + kb * 32 + ac0;
#pragma unroll
            for (int i = 0; i < 4; i++) {
                float4 v = *(const float4*)(ap + i * 4);
                __nv_bfloat162 h01 = __floats2bfloat162_rn(v.x, v.y);
                __nv_bfloat162 h23 = __floats2bfloat162_rn(v.z, v.w);
                __nv_bfloat162 l01 = __floats2bfloat162_rn(
                    v.x - __bfloat162float(h01.x), v.y - __bfloat162float(h01.y));
                __nv_bfloat162 l23 = __floats2bfloat162_rn(
                    v.z - __bfloat162float(h23.x), v.w - __bfloat162float(h23.y));
                *(uint2*)&As_hi[arow][ac0 + i * 4] =
                    make_uint2(*(uint32_t*)&h01, *(uint32_t*)&h23);
                *(uint2*)&As_lo[arow][ac0 + i * 4] =
                    make_uint2(*(uint32_t*)&l01, *(uint32_t*)&l23);
            }
        }
        {
#pragma unroll
            for (int i = 0; i < 8; i++) {
                int k = bk0 + i;
                float v = Bsrc[(size_t)(kb * 32 + k) * ldb + bn];
                __nv_bfloat16 hb = __float2bfloat16_rn(v);
                __nv_bfloat16 lb = __float2bfloat16_rn(v - __bfloat162float(hb));
                Bs_hi[bn][k] = hb;
                Bs_lo[bn][k] = lb;
            }
        }
        __syncthreads();

#pragma unroll
        for (int ks = 0; ks < 2; ks++) {
            const int k = ks * 16;
            uint32_t ah[2][4], al[2][4];
#pragma unroll
            for (int mt = 0; mt < 2; mt++) {
                const int rb = wm * 32 + mt * 16;
                ah[mt][0] = *(const uint32_t*)&As_hi[rb + fr    ][k + fc    ];
                ah[mt][1] = *(const uint32_t*)&As_hi[rb + fr + 8][k + fc    ];
                ah[mt][2] = *(const uint32_t*)&As_hi[rb + fr    ][k + fc + 8];
                ah[mt][3] = *(const uint32_t*)&As_hi[rb + fr + 8][k + fc + 8];
                al[mt][0] = *(const uint32_t*)&As_lo[rb + fr    ][k + fc    ];
                al[mt][1] = *(const uint32_t*)&As_lo[rb + fr + 8][k + fc    ];
                al[mt][2] = *(const uint32_t*)&As_lo[rb + fr    ][k + fc + 8];
                al[mt][3] = *(const uint32_t*)&As_lo[rb + fr + 8][k + fc + 8];
            }
            uint32_t bh[4][2], bl[4][2];
#pragma unroll
            for (int nt = 0; nt < 4; nt++) {
                const int nn = wn * 32 + nt * 8 + (lane >> 2);
                const int kk = k + fc;
                bh[nt][0] = *(const uint32_t*)&Bs_hi[nn][kk    ];
                bh[nt][1] = *(const uint32_t*)&Bs_hi[nn][kk + 8];
                bl[nt][0] = *(const uint32_t*)&Bs_lo[nn][kk    ];
                bl[nt][1] = *(const uint32_t*)&Bs_lo[nn][kk + 8];
            }
#pragma unroll
            for (int mt = 0; mt < 2; mt++)
#pragma unroll
                for (int nt = 0; nt < 4; nt++) {
                    mma16816(d[mt][nt], ah[mt], bh[nt]);
                    mma16816(d[mt][nt], ah[mt], bl[nt]);
                    mma16816(d[mt][nt], al[mt], bh[nt]);
                }
        }
        __syncthreads();
    }
}

// ---------------------------------------------------------------------------
// Kernel 1: QKV projection (verified R6)
// ---------------------------------------------------------------------------
__global__ __launch_bounds__(256)
void qkv_hmma_kernel(const float* __restrict__ x,
                     const float* __restrict__ Wq, const float* __restrict__ bq,
                     const float* __restrict__ Wk, const float* __restrict__ bk,
                     const float* __restrict__ Wv, const float* __restrict__ bv)
{
    const int m0 = blockIdx.y * 128;
    const int j0 = blockIdx.x * 64;
    const int sel = j0 / E_;
    const int h = (j0 % E_) >> 6;

    const float* W   = (sel == 0) ? Wq : (sel == 1) ? Wk : Wv;
    const float* bia = (sel == 0) ? bq : (sel == 1) ? bk : bv;
    float* outp      = (sel == 0) ? g_Q : (sel == 1) ? g_K : g_V;
    const float* Bsrc = W + (size_t)h * E_ * D_;

    float d[2][4][4];
    gemm_hmma_body(x + (size_t)m0 * E_, Bsrc, D_, d);

    const int wid = threadIdx.x >> 5, lane = threadIdx.x & 31;
    const int wm = wid & 3, wn = wid >> 2;
    const int fr = lane >> 2, fc = (lane & 3) * 2;
    const float* brow = bia + h * D_;

#pragma unroll
    for (int mt = 0; mt < 2; mt++) {
#pragma unroll
        for (int half = 0; half < 2; half++) {
            const int row = m0 + wm * 32 + mt * 16 + fr + half * 8;
            const int bb = row >> 11;
            const int s = row & (S_ - 1);
            float* orow = outp + (((size_t)bb * H_ + h) * S_ + s) * D_;
#pragma unroll
            for (int nt = 0; nt < 4; nt++) {
                const int col = wn * 32 + nt * 8 + fc;
                float2 v;
                v.x = d[mt][nt][half * 2 + 0] + brow[col];
                v.y = d[mt][nt][half * 2 + 1] + brow[col + 1];
                *(float2*)(orow + col) = v;
            }
        }
    }
}

// ---------------------------------------------------------------------------
// Kernel 3: output projection (verified R6)
// ---------------------------------------------------------------------------
__global__ __launch_bounds__(256)
void out_hmma_kernel(const float* __restrict__ Wo, const float* __restrict__ bo,
                     float* __restrict__ out)
{
    const int m0 = blockIdx.y * 128;
    const int n0 = blockIdx.x * 64;
    const float* Bsrc = Wo + n0;

    float d[2][4][4];
    gemm_hmma_body(g_attn + (size_t)m0 * E_, Bsrc, E_, d);

    const int wid = threadIdx.x >> 5, lane = threadIdx.x & 31;
    const int wm = wid & 3, wn = wid >> 2;
    const int fr = lane >> 2, fc = (lane & 3) * 2;

#pragma unroll
    for (int mt = 0; mt < 2; mt++) {
#pragma unroll
        for (int half = 0; half < 2; half++) {
            const int row = m0 + wm * 32 + mt * 16 + fr + half * 8;
            float* orow = out + (size_t)row * E_ + n0;
#pragma unroll
            for (int nt = 0; nt < 4; nt++) {
                const int col = wn * 32 + nt * 8 + fc;
                float2 v;
                v.x = d[mt][nt][half * 2 + 0] + bo[n0 + col];
                v.y = d[mt][nt][half * 2 + 1] + bo[n0 + col + 1];
                *(float2*)(orow + col) = v;
            }
        }
    }
}

// ---------------------------------------------------------------------------
// Kernel 2: flash attention via HMMA (split-bf16 QK^T and PV).
// Bq=128 x Bk=128. 8 warps; warp w owns rows w*16..w*16+15 of the q tile.
// ---------------------------------------------------------------------------
#define KV_PITCH 72
#define OFF_KQH 0
#define OFF_KQL 18432
#define OFF_VH  36864
#define OFF_VL  55296
#define OFF_MSK 73728
#define ATT_SMEM (OFF_MSK + 128 * 4)   // 74240 bytes

__device__ __forceinline__ void load_split_tile(
    const float* __restrict__ gsrc, __nv_bfloat16* hi, __nv_bfloat16* lo, int tid)
{
    const int row = tid >> 1;
    const int c0 = (tid & 1) * 32;
    const float* gp = gsrc + (size_t)row * D_ + c0;
#pragma unroll
    for (int i = 0; i < 8; i++) {
        float4 v = *(const float4*)(gp + i * 4);
        __nv_bfloat162 h01 = __floats2bfloat162_rn(v.x, v.y);
        __nv_bfloat162 h23 = __floats2bfloat162_rn(v.z, v.w);
        __nv_bfloat162 l01 = __floats2bfloat162_rn(
            v.x - __bfloat162float(h01.x), v.y - __bfloat162float(h01.y));
        __nv_bfloat162 l23 = __floats2bfloat162_rn(
            v.z - __bfloat162float(h23.x), v.w - __bfloat162float(h23.y));
        *(uint2*)&hi[row * KV_PITCH + c0 + i * 4] =
            make_uint2(*(uint32_t*)&h01, *(uint32_t*)&h23);
        *(uint2*)&lo[row * KV_PITCH + c0 + i * 4] =
            make_uint2(*(uint32_t*)&l01, *(uint32_t*)&l23);
    }
}

__global__ __launch_bounds__(256)
void flash_attn_hmma(const int* __restrict__ mask)
{
    extern __shared__ __align__(16) char smx[];
    __nv_bfloat16* KQh = (__nv_bfloat16*)(smx + OFF_KQH);
    __nv_bfloat16* KQl = (__nv_bfloat16*)(smx + OFF_KQL);
    __nv_bfloat16* Vh  = (__nv_bfloat16*)(smx + OFF_VH);
    __nv_bfloat16* Vl  = (__nv_bfloat16*)(smx + OFF_VL);
    float* maskf = (float*)(smx + OFF_MSK);

    const int tid = threadIdx.x;
    const int wid = tid >> 5, lane = tid & 31;
    const int fr = lane >> 2, fc = (lane & 3) * 2;
    const int q0 = blockIdx.x * 128;
    const int h = blockIdx.y, b = blockIdx.z;
    const size_t base = ((size_t)b * H_ + h) * S_ * D_;

    const uint32_t sVh = smem_u32(Vh);
    const uint32_t sVl = smem_u32(Vl);

    // ---- stage Q through KQ buffer, extract resident fragments ----
    load_split_tile(g_Q + base + (size_t)q0 * D_, KQh, KQl, tid);
    __syncthreads();

    uint32_t qh[4][4], ql[4][4];
    const int r0 = wid * 16 + fr;
#pragma unroll
    for (int kc = 0; kc < 4; kc++) {
        const int k = kc * 16 + fc;
        qh[kc][0] = *(const uint32_t*)&KQh[(r0    ) * KV_PITCH + k    ];
        qh[kc][1] = *(const uint32_t*)&KQh[(r0 + 8) * KV_PITCH + k    ];
        qh[kc][2] = *(const uint32_t*)&KQh[(r0    ) * KV_PITCH + k + 8];
        qh[kc][3] = *(const uint32_t*)&KQh[(r0 + 8) * KV_PITCH + k + 8];
        ql[kc][0] = *(const uint32_t*)&KQl[(r0    ) * KV_PITCH + k    ];
        ql[kc][1] = *(const uint32_t*)&KQl[(r0 + 8) * KV_PITCH + k    ];
        ql[kc][2] = *(const uint32_t*)&KQl[(r0    ) * KV_PITCH + k + 8];
        ql[kc][3] = *(const uint32_t*)&KQl[(r0 + 8) * KV_PITCH + k + 8];
    }

    float m0r = -INFINITY, m1r = -INFINITY;
    float l0r = 0.f, l1r = 0.f;
    float O[8][4];
#pragma unroll
    for (int nt = 0; nt < 8; nt++)
#pragma unroll
        for (int e = 0; e < 4; e++) O[nt][e] = 0.f;

    for (int kb = 0; kb < S_ / 128; kb++) {
        const int k0 = kb * 128;
        __syncthreads();   // previous iteration's reads (and Q extraction) done
        load_split_tile(g_K + base + (size_t)k0 * D_, KQh, KQl, tid);
        load_split_tile(g_V + base + (size_t)k0 * D_, Vh, Vl, tid);
        if (tid < 128) maskf[tid] = mask[(size_t)b * S_ + k0 + tid] ? 0.f : -1e9f;
        __syncthreads();

        // ---- scores: S[16 rows x 128 cols] per warp ----
        float s[16][4];
#pragma unroll
        for (int nt = 0; nt < 16; nt++)
#pragma unroll
            for (int e = 0; e < 4; e++) s[nt][e] = 0.f;

#pragma unroll
        for (int kc = 0; kc < 4; kc++) {
            const int k = kc * 16 + fc;
#pragma unroll
            for (int nt = 0; nt < 16; nt++) {
                const int nn = nt * 8 + fr;
                uint32_t bh[2], bl[2];
                bh[0] = *(const uint32_t*)&KQh[nn * KV_PITCH + k    ];
                bh[1] = *(const uint32_t*)&KQh[nn * KV_PITCH + k + 8];
                bl[0] = *(const uint32_t*)&KQl[nn * KV_PITCH + k    ];
                bl[1] = *(const uint32_t*)&KQl[nn * KV_PITCH + k + 8];
                mma16816(s[nt], qh[kc], bh);
                mma16816(s[nt], qh[kc], bl);
                mma16816(s[nt], ql[kc], bh);
            }
        }

        // ---- scale + mask + row max ----
        float mt0 = -INFINITY, mt1 = -INFINITY;
#pragma unroll
        for (int nt = 0; nt < 16; nt++) {
            float2 mf = *(const float2*)&maskf[nt * 8 + fc];
            s[nt][0] = fmaf(s[nt][0], 0.125f, mf.x);
            s[nt][1] = fmaf(s[nt][1], 0.125f, mf.y);
            s[nt][2] = fmaf(s[nt][2], 0.125f, mf.x);
            s[nt][3] = fmaf(s[nt][3], 0.125f, mf.y);
            mt0 = fmaxf(mt0, fmaxf(s[nt][0], s[nt][1]));
            mt1 = fmaxf(mt1, fmaxf(s[nt][2], s[nt][3]));
        }
        mt0 = fmaxf(mt0, __shfl_xor_sync(0xffffffffu, mt0, 1));
        mt0 = fmaxf(mt0, __shfl_xor_sync(0xffffffffu, mt0, 2));
        mt1 = fmaxf(mt1, __shfl_xor_sync(0xffffffffu, mt1, 1));
        mt1 = fmaxf(mt1, __shfl_xor_sync(0xffffffffu, mt1, 2));

        const float mn0 = fmaxf(m0r, mt0), mn1 = fmaxf(m1r, mt1);
        const float cf0 = __expf(m0r - mn0), cf1 = __expf(m1r - mn1);
        m0r = mn0; m1r = mn1;

        float lt0 = 0.f, lt1 = 0.f;
#pragma unroll
        for (int nt = 0; nt < 16; nt++) {
            s[nt][0] = __expf(s[nt][0] - mn0);
            s[nt][1] = __expf(s[nt][1] - mn0);
            s[nt][2] = __expf(s[nt][2] - mn1);
            s[nt][3] = __expf(s[nt][3] - mn1);
            lt0 += s[nt][0] + s[nt][1];
            lt1 += s[nt][2] + s[nt][3];
        }
        lt0 += __shfl_xor_sync(0xffffffffu, lt0, 1);
        lt0 += __shfl_xor_sync(0xffffffffu, lt0, 2);
        lt1 += __shfl_xor_sync(0xffffffffu, lt1, 1);
        lt1 += __shfl_xor_sync(0xffffffffu, lt1, 2);
        l0r = l0r * cf0 + lt0;
        l1r = l1r * cf1 + lt1;

        // ---- rescale O ----
#pragma unroll
        for (int nt = 0; nt < 8; nt++) {
            O[nt][0] *= cf0; O[nt][1] *= cf0;
            O[nt][2] *= cf1; O[nt][3] *= cf1;
        }

        // ---- PV: O += P @ V, split-bf16, V transposed by ldmatrix.trans ----
#pragma unroll
        for (int kc = 0; kc < 8; kc++) {
            // P fragments from score accumulators (A-frag layout = D-frag layout)
            uint32_t ph[4], pl[4];
            {
                const float p00 = s[2*kc][0],   p01 = s[2*kc][1];
                const float p02 = s[2*kc][2],   p03 = s[2*kc][3];
                const float p10 = s[2*kc+1][0], p11 = s[2*kc+1][1];
                const float p12 = s[2*kc+1][2], p13 = s[2*kc+1][3];
                ph[0] = packbf2(p00, p01);
                ph[1] = packbf2(p02, p03);
                ph[2] = packbf2(p10, p11);
                ph[3] = packbf2(p12, p13);
                __nv_bfloat162* h;
                h = (__nv_bfloat162*)&ph[0];
                pl[0] = packbf2(p00 - __bfloat162float(h->x), p01 - __bfloat162float(h->y));
                h = (__nv_bfloat162*)&ph[1];
                pl[1] = packbf2(p02 - __bfloat162float(h->x), p03 - __bfloat162float(h->y));
                h = (__nv_bfloat162*)&ph[2];
                pl[2] = packbf2(p10 - __bfloat162float(h->x), p11 - __bfloat162float(h->y));
                h = (__nv_bfloat162*)&ph[3];
                pl[3] = packbf2(p12 - __bfloat162float(h->x), p13 - __bfloat162float(h->y));
            }
            const int mat = lane >> 3;           // 0..3
            const int keyr = kc * 16 + (mat & 1) * 8 + (lane & 7);
#pragma unroll
            for (int ntd = 0; ntd < 4; ntd++) {
                const int dc = ntd * 16 + (mat >> 1) * 8;
                const uint32_t boff = (uint32_t)(keyr * KV_PITCH + dc) * 2;
                uint32_t vh[4], vl[4];
                ldsm_x4_trans(vh, sVh + boff);
                ldsm_x4_trans(vl, sVl + boff);
                mma16816(O[2*ntd],     ph, vh);
                mma16816(O[2*ntd],     ph, vl);
                mma16816(O[2*ntd],     pl, vh);
                mma16816(O[2*ntd + 1], ph, vh + 2);
                mma16816(O[2*ntd + 1], ph, vl + 2);
                mma16816(O[2*ntd + 1], pl, vh + 2);
            }
        }
    }

    // ---- epilogue: normalize + write [B, S, H*D] ----
    const float inv0 = 1.0f / l0r, inv1 = 1.0f / l1r;
    const int qrow = q0 + wid * 16 + fr;
    float* dst0 = g_attn + ((size_t)b * S_ + qrow) * E_ + h * D_;
    float* dst1 = dst0 + 8 * E_;
#pragma unroll
    for (int nt = 0; nt < 8; nt++) {
        float2 v0 = make_float2(O[nt][0] * inv0, O[nt][1] * inv0);
        float2 v1 = make_float2(O[nt][2] * inv1, O[nt][3] * inv1);
        *(float2*)(dst0 + nt * 8 + fc) = v0;
        *(float2*)(dst1 + nt * 8 + fc) = v1;
    }
}

// ---------------------------------------------------------------------------
// Launch
// ---------------------------------------------------------------------------
extern "C" void kernel_launch(void* const* d_in, const int* in_sizes, int n_in,
                              void* d_out, int out_size)
{
    const float* x    = (const float*)d_in[0];
    const int*   mask = (const int*)d_in[1];
    const float* Wq   = (const float*)d_in[2];
    const float* bq   = (const float*)d_in[3];
    const float* Wk   = (const float*)d_in[4];
    const float* bk   = (const float*)d_in[5];
    const float* Wv   = (const float*)d_in[6];
    const float* bv   = (const float*)d_in[7];
    const float* Wo   = (const float*)d_in[8];
    const float* bo   = (const float*)d_in[9];
    float* out = (float*)d_out;

    cudaFuncSetAttribute(flash_attn_hmma,
                         cudaFuncAttributeMaxDynamicSharedMemorySize, ATT_SMEM);

    {
        dim3 grid(36, 64);
        qkv_hmma_kernel<<<grid, 256>>>(x, Wq, bq, Wk, bk, Wv, bv);
    }
    {
        dim3 grid(S_ / 128, H_, B_);
        flash_attn_hmma<<<grid, 256, ATT_SMEM>>>(mask);
    }
    {
        dim3 grid(12, 64);
        out_hmma_kernel<<<grid, 256>>>(Wo, bo, out);
    }
}

// round 8
// speedup vs baseline: 2.5051x; 1.0302x over previous
#include <cuda_runtime.h>
#include <cuda_bf16.h>
#include <stdint.h>
#include <math.h>

#define B_  4
#define S_  2048
#define E_  768
#define H_  12
#define D_  64
#define NR  (B_ * S_)
#define WSZ ((size_t)H_ * E_ * D_)   // 589824

// Scratch: bf16 hi/lo split arrays
__device__ __nv_bfloat16 g_xh[(size_t)NR * E_], g_xl[(size_t)NR * E_];
__device__ __nv_bfloat16 g_Wqh[WSZ], g_Wql[WSZ];
__device__ __nv_bfloat16 g_Wkh[WSZ], g_Wkl[WSZ];
__device__ __nv_bfloat16 g_Wvh[WSZ], g_Wvl[WSZ];
__device__ __nv_bfloat16 g_Woh[(size_t)E_ * E_], g_Wol[(size_t)E_ * E_];
__device__ __nv_bfloat16 g_Qh[(size_t)NR * E_ / 12 * 12];  // B*H*S*D = NR*E/?  -> just NR*D*H
__device__ __nv_bfloat16 g_Ql[(size_t)B_ * H_ * S_ * D_];
__device__ __nv_bfloat16 g_Kh[(size_t)B_ * H_ * S_ * D_], g_Kl[(size_t)B_ * H_ * S_ * D_];
__device__ __nv_bfloat16 g_Vh[(size_t)B_ * H_ * S_ * D_], g_Vl[(size_t)B_ * H_ * S_ * D_];
__device__ __nv_bfloat16 g_ah[(size_t)NR * E_], g_al[(size_t)NR * E_];

// ===========================================================================
// helpers
// ===========================================================================
__device__ __forceinline__ void mma16816(float* d, const uint32_t* a, const uint32_t* b) {
    asm volatile(
        "mma.sync.aligned.m16n8k16.row.col.f32.bf16.bf16.f32 "
        "{%0,%1,%2,%3}, {%4,%5,%6,%7}, {%8,%9}, {%0,%1,%2,%3};"
        : "+f"(d[0]), "+f"(d[1]), "+f"(d[2]), "+f"(d[3])
        : "r"(a[0]), "r"(a[1]), "r"(a[2]), "r"(a[3]), "r"(b[0]), "r"(b[1]));
}

__device__ __forceinline__ void ldsm_x4_trans(uint32_t* r, uint32_t addr) {
    asm volatile("ldmatrix.sync.aligned.m8n8.x4.trans.shared.b16 {%0,%1,%2,%3}, [%4];"
        : "=r"(r[0]), "=r"(r[1]), "=r"(r[2]), "=r"(r[3]) : "r"(addr));
}

__device__ __forceinline__ uint32_t smem_u32(const void* p) {
    uint32_t a;
    asm("{ .reg .u64 t; cvta.to.shared.u64 t, %1; cvt.u32.u64 %0, t; }"
        : "=r"(a) : "l"(p));
    return a;
}

__device__ __forceinline__ uint32_t packbf2(float x, float y) {
    __nv_bfloat162 t = __floats2bfloat162_rn(x, y);
    return *(uint32_t*)&t;
}

// split a pair of floats into hi/lo packed bf16x2
__device__ __forceinline__ void split2(float x, float y, uint32_t& hi, uint32_t& lo) {
    __nv_bfloat162 h = __floats2bfloat162_rn(x, y);
    hi = *(uint32_t*)&h;
    __nv_bfloat162 l = __floats2bfloat162_rn(x - __bfloat162float(h.x),
                                             y - __bfloat162float(h.y));
    lo = *(uint32_t*)&l;
}

// ---------------------------------------------------------------------------
// Prep: split fp32 array into bf16 hi/lo. n must be multiple of 4.
// ---------------------------------------------------------------------------
__global__ __launch_bounds__(256)
void split_kernel(const float* __restrict__ src, __nv_bfloat16* __restrict__ hi,
                  __nv_bfloat16* __restrict__ lo, int n)
{
    int i = (blockIdx.x * 256 + threadIdx.x) * 4;
    if (i >= n) return;
    float4 v = *(const float4*)(src + i);
    uint32_t h01, l01, h23, l23;
    split2(v.x, v.y, h01, l01);
    split2(v.z, v.w, h23, l23);
    *(uint2*)(hi + i) = make_uint2(h01, h23);
    *(uint2*)(lo + i) = make_uint2(l01, l23);
}

// ---------------------------------------------------------------------------
// GEMM body (bf16 inputs): D[128x64] = A[128x768] @ B^T, split 3-term HMMA.
// 8 warps (4m x 2n), warp tile 32x32, BK=32. A pitch = E_; B[n][k]=Bh[k*ldb+n].
// ---------------------------------------------------------------------------
#define GPITCH 40

__device__ __forceinline__ void gemm_body_bf16(
    const __nv_bfloat16* __restrict__ Ah, const __nv_bfloat16* __restrict__ Al,
    const __nv_bfloat16* __restrict__ Bh, const __nv_bfloat16* __restrict__ Bl,
    int ldb, float d[2][4][4])
{
    __shared__ __align__(16) __nv_bfloat16 As_hi[128][GPITCH];
    __shared__ __align__(16) __nv_bfloat16 As_lo[128][GPITCH];
    __shared__ __align__(16) __nv_bfloat16 Bs_hi[64][GPITCH];
    __shared__ __align__(16) __nv_bfloat16 Bs_lo[64][GPITCH];

    const int tid = threadIdx.x;
    const int wid = tid >> 5, lane = tid & 31;
    const int wm = wid & 3, wn = wid >> 2;
    const int fr = lane >> 2, fc = (lane & 3) * 2;

    const int arow = tid >> 1;
    const int ac0 = (tid & 1) * 16;
    const int bn = tid & 63;
    const int bk0 = (tid >> 6) * 8;

#pragma unroll
    for (int mt = 0; mt < 2; mt++)
#pragma unroll
        for (int nt = 0; nt < 4; nt++)
#pragma unroll
            for (int e = 0; e < 4; e++) d[mt][nt][e] = 0.f;

    for (int kb = 0; kb < E_ / 32; kb++) {
        {
            const __nv_bfloat16* ap = Ah + (size_t)arow * E_ + kb * 32 + ac0;
            const __nv_bfloat16* al = Al + (size_t)arow * E_ + kb * 32 + ac0;
            *(uint4*)&As_hi[arow][ac0]     = *(const uint4*)ap;
            *(uint4*)&As_hi[arow][ac0 + 8] = *(const uint4*)(ap + 8);
            *(uint4*)&As_lo[arow][ac0]     = *(const uint4*)al;
            *(uint4*)&As_lo[arow][ac0 + 8] = *(const uint4*)(al + 8);
        }
        {
#pragma unroll
            for (int i = 0; i < 8; i++) {
                int k = bk0 + i;
                Bs_hi[bn][k] = Bh[(size_t)(kb * 32 + k) * ldb + bn];
                Bs_lo[bn][k] = Bl[(size_t)(kb * 32 + k) * ldb + bn];
            }
        }
        __syncthreads();

#pragma unroll
        for (int ks = 0; ks < 2; ks++) {
            const int k = ks * 16;
            uint32_t ah[2][4], al2[2][4];
#pragma unroll
            for (int mt = 0; mt < 2; mt++) {
                const int rb = wm * 32 + mt * 16;
                ah[mt][0] = *(const uint32_t*)&As_hi[rb + fr    ][k + fc    ];
                ah[mt][1] = *(const uint32_t*)&As_hi[rb + fr + 8][k + fc    ];
                ah[mt][2] = *(const uint32_t*)&As_hi[rb + fr    ][k + fc + 8];
                ah[mt][3] = *(const uint32_t*)&As_hi[rb + fr + 8][k + fc + 8];
                al2[mt][0] = *(const uint32_t*)&As_lo[rb + fr    ][k + fc    ];
                al2[mt][1] = *(const uint32_t*)&As_lo[rb + fr + 8][k + fc    ];
                al2[mt][2] = *(const uint32_t*)&As_lo[rb + fr    ][k + fc + 8];
                al2[mt][3] = *(const uint32_t*)&As_lo[rb + fr + 8][k + fc + 8];
            }
            uint32_t bh[4][2], bl[4][2];
#pragma unroll
            for (int nt = 0; nt < 4; nt++) {
                const int nn = wn * 32 + nt * 8 + (lane >> 2);
                const int kk = k + fc;
                bh[nt][0] = *(const uint32_t*)&Bs_hi[nn][kk    ];
                bh[nt][1] = *(const uint32_t*)&Bs_hi[nn][kk + 8];
                bl[nt][0] = *(const uint32_t*)&Bs_lo[nn][kk    ];
                bl[nt][1] = *(const uint32_t*)&Bs_lo[nn][kk + 8];
            }
#pragma unroll
            for (int mt = 0; mt < 2; mt++)
#pragma unroll
                for (int nt = 0; nt < 4; nt++) {
                    mma16816(d[mt][nt], ah[mt], bh[nt]);
                    mma16816(d[mt][nt], ah[mt], bl[nt]);
                    mma16816(d[mt][nt], al2[mt], bh[nt]);
                }
        }
        __syncthreads();
    }
}

// ---------------------------------------------------------------------------
// Kernel 1: QKV projection -> split bf16 Q/K/V. grid = (36, 64)
// ---------------------------------------------------------------------------
__global__ __launch_bounds__(256)
void qkv_hmma_kernel(const float* __restrict__ bq, const float* __restrict__ bk,
                     const float* __restrict__ bv)
{
    const int m0 = blockIdx.y * 128;
    const int j0 = blockIdx.x * 64;
    const int sel = j0 / E_;
    const int h = (j0 % E_) >> 6;

    const __nv_bfloat16* Wh = (sel == 0) ? g_Wqh : (sel == 1) ? g_Wkh : g_Wvh;
    const __nv_bfloat16* Wl = (sel == 0) ? g_Wql : (sel == 1) ? g_Wkl : g_Wvl;
    const float* bia = (sel == 0) ? bq : (sel == 1) ? bk : bv;
    __nv_bfloat16* outh = (sel == 0) ? g_Qh : (sel == 1) ? g_Kh : g_Vh;
    __nv_bfloat16* outl = (sel == 0) ? g_Ql : (sel == 1) ? g_Kl : g_Vl;

    float d[2][4][4];
    gemm_body_bf16(g_xh + (size_t)m0 * E_, g_xl + (size_t)m0 * E_,
                   Wh + (size_t)h * E_ * D_, Wl + (size_t)h * E_ * D_, D_, d);

    const int wid = threadIdx.x >> 5, lane = threadIdx.x & 31;
    const int wm = wid & 3, wn = wid >> 2;
    const int fr = lane >> 2, fc = (lane & 3) * 2;
    const float* brow = bia + h * D_;

#pragma unroll
    for (int mt = 0; mt < 2; mt++) {
#pragma unroll
        for (int half = 0; half < 2; half++) {
            const int row = m0 + wm * 32 + mt * 16 + fr + half * 8;
            const int bb = row >> 11;
            const int s = row & (S_ - 1);
            const size_t ro = (((size_t)bb * H_ + h) * S_ + s) * D_;
#pragma unroll
            for (int nt = 0; nt < 4; nt++) {
                const int col = wn * 32 + nt * 8 + fc;
                float vx = d[mt][nt][half * 2 + 0] + brow[col];
                float vy = d[mt][nt][half * 2 + 1] + brow[col + 1];
                uint32_t hi, lo;
                split2(vx, vy, hi, lo);
                *(uint32_t*)(outh + ro + col) = hi;
                *(uint32_t*)(outl + ro + col) = lo;
            }
        }
    }
}

// ---------------------------------------------------------------------------
// Kernel 3: output projection. grid = (12, 64)
// ---------------------------------------------------------------------------
__global__ __launch_bounds__(256)
void out_hmma_kernel(const float* __restrict__ bo, float* __restrict__ out)
{
    const int m0 = blockIdx.y * 128;
    const int n0 = blockIdx.x * 64;

    float d[2][4][4];
    gemm_body_bf16(g_ah + (size_t)m0 * E_, g_al + (size_t)m0 * E_,
                   g_Woh + n0, g_Wol + n0, E_, d);

    const int wid = threadIdx.x >> 5, lane = threadIdx.x & 31;
    const int wm = wid & 3, wn = wid >> 2;
    const int fr = lane >> 2, fc = (lane & 3) * 2;

#pragma unroll
    for (int mt = 0; mt < 2; mt++) {
#pragma unroll
        for (int half = 0; half < 2; half++) {
            const int row = m0 + wm * 32 + mt * 16 + fr + half * 8;
            float* orow = out + (size_t)row * E_ + n0;
#pragma unroll
            for (int nt = 0; nt < 4; nt++) {
                const int col = wn * 32 + nt * 8 + fc;
                float2 v;
                v.x = d[mt][nt][half * 2 + 0] + bo[n0 + col];
                v.y = d[mt][nt][half * 2 + 1] + bo[n0 + col + 1];
                *(float2*)(orow + col) = v;
            }
        }
    }
}

// ---------------------------------------------------------------------------
// Kernel 2: flash attention via HMMA. Inputs already split bf16.
// ---------------------------------------------------------------------------
#define KV_PITCH 72
#define OFF_KQH 0
#define OFF_KQL 18432
#define OFF_VH  36864
#define OFF_VL  55296
#define OFF_MSK 73728
#define ATT_SMEM (OFF_MSK + 128 * 4)

__device__ __forceinline__ void copy_tile_bf16(
    const __nv_bfloat16* __restrict__ gh, const __nv_bfloat16* __restrict__ gl,
    __nv_bfloat16* hi, __nv_bfloat16* lo, int tid)
{
    const int row = tid >> 1;
    const int c0 = (tid & 1) * 32;
    const __nv_bfloat16* ph = gh + (size_t)row * D_ + c0;
    const __nv_bfloat16* pl = gl + (size_t)row * D_ + c0;
#pragma unroll
    for (int i = 0; i < 4; i++) {
        *(uint4*)&hi[row * KV_PITCH + c0 + i * 8] = *(const uint4*)(ph + i * 8);
        *(uint4*)&lo[row * KV_PITCH + c0 + i * 8] = *(const uint4*)(pl + i * 8);
    }
}

__global__ __launch_bounds__(256)
void flash_attn_hmma(const int* __restrict__ mask)
{
    extern __shared__ __align__(16) char smx[];
    __nv_bfloat16* KQh = (__nv_bfloat16*)(smx + OFF_KQH);
    __nv_bfloat16* KQl = (__nv_bfloat16*)(smx + OFF_KQL);
    __nv_bfloat16* Vh  = (__nv_bfloat16*)(smx + OFF_VH);
    __nv_bfloat16* Vl  = (__nv_bfloat16*)(smx + OFF_VL);
    float* maskf = (float*)(smx + OFF_MSK);

    const int tid = threadIdx.x;
    const int wid = tid >> 5, lane = tid & 31;
    const int fr = lane >> 2, fc = (lane & 3) * 2;
    const int q0 = blockIdx.x * 128;
    const int h = blockIdx.y, b = blockIdx.z;
    const size_t base = ((size_t)b * H_ + h) * S_ * D_;

    const uint32_t sVh = smem_u32(Vh);
    const uint32_t sVl = smem_u32(Vl);

    // stage Q, extract resident fragments
    copy_tile_bf16(g_Qh + base + (size_t)q0 * D_, g_Ql + base + (size_t)q0 * D_,
                   KQh, KQl, tid);
    __syncthreads();

    uint32_t qh[4][4], ql[4][4];
    const int r0 = wid * 16 + fr;
#pragma unroll
    for (int kc = 0; kc < 4; kc++) {
        const int k = kc * 16 + fc;
        qh[kc][0] = *(const uint32_t*)&KQh[(r0    ) * KV_PITCH + k    ];
        qh[kc][1] = *(const uint32_t*)&KQh[(r0 + 8) * KV_PITCH + k    ];
        qh[kc][2] = *(const uint32_t*)&KQh[(r0    ) * KV_PITCH + k + 8];
        qh[kc][3] = *(const uint32_t*)&KQh[(r0 + 8) * KV_PITCH + k + 8];
        ql[kc][0] = *(const uint32_t*)&KQl[(r0    ) * KV_PITCH + k    ];
        ql[kc][1] = *(const uint32_t*)&KQl[(r0 + 8) * KV_PITCH + k    ];
        ql[kc][2] = *(const uint32_t*)&KQl[(r0    ) * KV_PITCH + k + 8];
        ql[kc][3] = *(const uint32_t*)&KQl[(r0 + 8) * KV_PITCH + k + 8];
    }

    float m0r = -INFINITY, m1r = -INFINITY;
    float l0r = 0.f, l1r = 0.f;
    float O[8][4];
#pragma unroll
    for (int nt = 0; nt < 8; nt++)
#pragma unroll
        for (int e = 0; e < 4; e++) O[nt][e] = 0.f;

    for (int kb = 0; kb < S_ / 128; kb++) {
        const int k0 = kb * 128;
        __syncthreads();
        copy_tile_bf16(g_Kh + base + (size_t)k0 * D_, g_Kl + base + (size_t)k0 * D_,
                       KQh, KQl, tid);
        copy_tile_bf16(g_Vh + base + (size_t)k0 * D_, g_Vl + base + (size_t)k0 * D_,
                       Vh, Vl, tid);
        if (tid < 128) maskf[tid] = mask[(size_t)b * S_ + k0 + tid] ? 0.f : -1e9f;
        __syncthreads();

        float s[16][4];
#pragma unroll
        for (int nt = 0; nt < 16; nt++)
#pragma unroll
            for (int e = 0; e < 4; e++) s[nt][e] = 0.f;

#pragma unroll
        for (int kc = 0; kc < 4; kc++) {
            const int k = kc * 16 + fc;
#pragma unroll
            for (int nt = 0; nt < 16; nt++) {
                const int nn = nt * 8 + fr;
                uint32_t bh[2], bl[2];
                bh[0] = *(const uint32_t*)&KQh[nn * KV_PITCH + k    ];
                bh[1] = *(const uint32_t*)&KQh[nn * KV_PITCH + k + 8];
                bl[0] = *(const uint32_t*)&KQl[nn * KV_PITCH + k    ];
                bl[1] = *(const uint32_t*)&KQl[nn * KV_PITCH + k + 8];
                mma16816(s[nt], qh[kc], bh);
                mma16816(s[nt], qh[kc], bl);
                mma16816(s[nt], ql[kc], bh);
            }
        }

        float mt0 = -INFINITY, mt1 = -INFINITY;
#pragma unroll
        for (int nt = 0; nt < 16; nt++) {
            float2 mf = *(const float2*)&maskf[nt * 8 + fc];
            s[nt][0] = fmaf(s[nt][0], 0.125f, mf.x);
            s[nt][1] = fmaf(s[nt][1], 0.125f, mf.y);
            s[nt][2] = fmaf(s[nt][2], 0.125f, mf.x);
            s[nt][3] = fmaf(s[nt][3], 0.125f, mf.y);
            mt0 = fmaxf(mt0, fmaxf(s[nt][0], s[nt][1]));
            mt1 = fmaxf(mt1, fmaxf(s[nt][2], s[nt][3]));
        }
        mt0 = fmaxf(mt0, __shfl_xor_sync(0xffffffffu, mt0, 1));
        mt0 = fmaxf(mt0, __shfl_xor_sync(0xffffffffu, mt0, 2));
        mt1 = fmaxf(mt1, __shfl_xor_sync(0xffffffffu, mt1, 1));
        mt1 = fmaxf(mt1, __shfl_xor_sync(0xffffffffu, mt1, 2));

        const float mn0 = fmaxf(m0r, mt0), mn1 = fmaxf(m1r, mt1);
        const float cf0 = __expf(m0r - mn0), cf1 = __expf(m1r - mn1);
        m0r = mn0; m1r = mn1;

        float lt0 = 0.f, lt1 = 0.f;
#pragma unroll
        for (int nt = 0; nt < 16; nt++) {
            s[nt][0] = __expf(s[nt][0] - mn0);
            s[nt][1] = __expf(s[nt][1] - mn0);
            s[nt][2] = __expf(s[nt][2] - mn1);
            s[nt][3] = __expf(s[nt][3] - mn1);
            lt0 += s[nt][0] + s[nt][1];
            lt1 += s[nt][2] + s[nt][3];
        }
        lt0 += __shfl_xor_sync(0xffffffffu, lt0, 1);
        lt0 += __shfl_xor_sync(0xffffffffu, lt0, 2);
        lt1 += __shfl_xor_sync(0xffffffffu, lt1, 1);
        lt1 += __shfl_xor_sync(0xffffffffu, lt1, 2);
        l0r = l0r * cf0 + lt0;
        l1r = l1r * cf1 + lt1;

#pragma unroll
        for (int nt = 0; nt < 8; nt++) {
            O[nt][0] *= cf0; O[nt][1] *= cf0;
            O[nt][2] *= cf1; O[nt][3] *= cf1;
        }

#pragma unroll
        for (int kc = 0; kc < 8; kc++) {
            uint32_t ph[4], pl[4];
            {
                const float p00 = s[2*kc][0],   p01 = s[2*kc][1];
                const float p02 = s[2*kc][2],   p03 = s[2*kc][3];
                const float p10 = s[2*kc+1][0], p11 = s[2*kc+1][1];
                const float p12 = s[2*kc+1][2], p13 = s[2*kc+1][3];
                ph[0] = packbf2(p00, p01);
                ph[1] = packbf2(p02, p03);
                ph[2] = packbf2(p10, p11);
                ph[3] = packbf2(p12, p13);
                __nv_bfloat162* h;
                h = (__nv_bfloat162*)&ph[0];
                pl[0] = packbf2(p00 - __bfloat162float(h->x), p01 - __bfloat162float(h->y));
                h = (__nv_bfloat162*)&ph[1];
                pl[1] = packbf2(p02 - __bfloat162float(h->x), p03 - __bfloat162float(h->y));
                h = (__nv_bfloat162*)&ph[2];
                pl[2] = packbf2(p10 - __bfloat162float(h->x), p11 - __bfloat162float(h->y));
                h = (__nv_bfloat162*)&ph[3];
                pl[3] = packbf2(p12 - __bfloat162float(h->x), p13 - __bfloat162float(h->y));
            }
            const int mat = lane >> 3;
            const int keyr = kc * 16 + (mat & 1) * 8 + (lane & 7);
#pragma unroll
            for (int ntd = 0; ntd < 4; ntd++) {
                const int dc = ntd * 16 + (mat >> 1) * 8;
                const uint32_t boff = (uint32_t)(keyr * KV_PITCH + dc) * 2;
                uint32_t vh[4], vl[4];
                ldsm_x4_trans(vh, sVh + boff);
                ldsm_x4_trans(vl, sVl + boff);
                mma16816(O[2*ntd],     ph, vh);
                mma16816(O[2*ntd],     ph, vl);
                mma16816(O[2*ntd],     pl, vh);
                mma16816(O[2*ntd + 1], ph, vh + 2);
                mma16816(O[2*ntd + 1], ph, vl + 2);
                mma16816(O[2*ntd + 1], pl, vh + 2);
            }
        }
    }

    // epilogue: normalize, split, write g_ah/g_al [B, S, H*D]
    const float inv0 = 1.0f / l0r, inv1 = 1.0f / l1r;
    const int qrow = q0 + wid * 16 + fr;
    const size_t o0 = ((size_t)b * S_ + qrow) * E_ + h * D_;
    const size_t o1 = o0 + 8 * E_;
#pragma unroll
    for (int nt = 0; nt < 8; nt++) {
        uint32_t hi, lo;
        split2(O[nt][0] * inv0, O[nt][1] * inv0, hi, lo);
        *(uint32_t*)(g_ah + o0 + nt * 8 + fc) = hi;
        *(uint32_t*)(g_al + o0 + nt * 8 + fc) = lo;
        split2(O[nt][2] * inv1, O[nt][3] * inv1, hi, lo);
        *(uint32_t*)(g_ah + o1 + nt * 8 + fc) = hi;
        *(uint32_t*)(g_al + o1 + nt * 8 + fc) = lo;
    }
}

// ---------------------------------------------------------------------------
// Launch
// ---------------------------------------------------------------------------
extern "C" void kernel_launch(void* const* d_in, const int* in_sizes, int n_in,
                              void* d_out, int out_size)
{
    const float* x    = (const float*)d_in[0];
    const int*   mask = (const int*)d_in[1];
    const float* Wq   = (const float*)d_in[2];
    const float* bq   = (const float*)d_in[3];
    const float* Wk   = (const float*)d_in[4];
    const float* bk   = (const float*)d_in[5];
    const float* Wv   = (const float*)d_in[6];
    const float* bv   = (const float*)d_in[7];
    const float* Wo   = (const float*)d_in[8];
    const float* bo   = (const float*)d_in[9];
    float* out = (float*)d_out;

    cudaFuncSetAttribute(flash_attn_hmma,
                         cudaFuncAttributeMaxDynamicSharedMemorySize, ATT_SMEM);

    // resolve device-global scratch addresses (host side)
    __nv_bfloat16 *xh, *xl, *wqh, *wql, *wkh, *wkl, *wvh, *wvl, *woh, *wol;
    cudaGetSymbolAddress((void**)&xh,  g_xh);
    cudaGetSymbolAddress((void**)&xl,  g_xl);
    cudaGetSymbolAddress((void**)&wqh, g_Wqh);
    cudaGetSymbolAddress((void**)&wql, g_Wql);
    cudaGetSymbolAddress((void**)&wkh, g_Wkh);
    cudaGetSymbolAddress((void**)&wkl, g_Wkl);
    cudaGetSymbolAddress((void**)&wvh, g_Wvh);
    cudaGetSymbolAddress((void**)&wvl, g_Wvl);
    cudaGetSymbolAddress((void**)&woh, g_Woh);
    cudaGetSymbolAddress((void**)&wol, g_Wol);

    const int nx = NR * E_;
    const int nw = (int)WSZ;
    const int nwo = E_ * E_;
    split_kernel<<<(nx / 4 + 255) / 256, 256>>>(x, xh, xl, nx);
    split_kernel<<<(nw / 4 + 255) / 256, 256>>>(Wq, wqh, wql, nw);
    split_kernel<<<(nw / 4 + 255) / 256, 256>>>(Wk, wkh, wkl, nw);
    split_kernel<<<(nw / 4 + 255) / 256, 256>>>(Wv, wvh, wvl, nw);
    split_kernel<<<(nwo / 4 + 255) / 256, 256>>>(Wo, woh, wol, nwo);

    {
        dim3 grid(36, 64);
        qkv_hmma_kernel<<<grid, 256>>>(bq, bk, bv);
    }
    {
        dim3 grid(S_ / 128, H_, B_);
        flash_attn_hmma<<<grid, 256, ATT_SMEM>>>(mask);
    }
    {
        dim3 grid(12, 64);
        out_hmma_kernel<<<grid, 256>>>(bo, out);
    }
}

// round 9
// speedup vs baseline: 2.6836x; 1.0713x over previous
#include <cuda_runtime.h>
#include <cuda_bf16.h>
#include <stdint.h>
#include <math.h>

#define B_  4
#define S_  2048
#define E_  768
#define H_  12
#define D_  64
#define NR  (B_ * S_)
#define WSZ ((size_t)H_ * E_ * D_)

// Scratch: bf16 hi/lo split arrays
__device__ __nv_bfloat16 g_xh[(size_t)NR * E_], g_xl[(size_t)NR * E_];
__device__ __nv_bfloat16 g_Wqh[WSZ], g_Wql[WSZ];
__device__ __nv_bfloat16 g_Wkh[WSZ], g_Wkl[WSZ];
__device__ __nv_bfloat16 g_Wvh[WSZ], g_Wvl[WSZ];
__device__ __nv_bfloat16 g_Woh[(size_t)E_ * E_], g_Wol[(size_t)E_ * E_];
__device__ __nv_bfloat16 g_Qh[(size_t)B_ * H_ * S_ * D_], g_Ql[(size_t)B_ * H_ * S_ * D_];
__device__ __nv_bfloat16 g_Kh[(size_t)B_ * H_ * S_ * D_], g_Kl[(size_t)B_ * H_ * S_ * D_];
__device__ __nv_bfloat16 g_Vh[(size_t)B_ * H_ * S_ * D_], g_Vl[(size_t)B_ * H_ * S_ * D_];
__device__ __nv_bfloat16 g_ah[(size_t)NR * E_], g_al[(size_t)NR * E_];

// ===========================================================================
// helpers
// ===========================================================================
__device__ __forceinline__ void mma16816(float* d, const uint32_t* a, const uint32_t* b) {
    asm volatile(
        "mma.sync.aligned.m16n8k16.row.col.f32.bf16.bf16.f32 "
        "{%0,%1,%2,%3}, {%4,%5,%6,%7}, {%8,%9}, {%0,%1,%2,%3};"
        : "+f"(d[0]), "+f"(d[1]), "+f"(d[2]), "+f"(d[3])
        : "r"(a[0]), "r"(a[1]), "r"(a[2]), "r"(a[3]), "r"(b[0]), "r"(b[1]));
}

__device__ __forceinline__ void ldsm_x4(uint32_t* r, uint32_t addr) {
    asm volatile("ldmatrix.sync.aligned.m8n8.x4.shared.b16 {%0,%1,%2,%3}, [%4];"
        : "=r"(r[0]), "=r"(r[1]), "=r"(r[2]), "=r"(r[3]) : "r"(addr));
}

__device__ __forceinline__ void ldsm_x4_trans(uint32_t* r, uint32_t addr) {
    asm volatile("ldmatrix.sync.aligned.m8n8.x4.trans.shared.b16 {%0,%1,%2,%3}, [%4];"
        : "=r"(r[0]), "=r"(r[1]), "=r"(r[2]), "=r"(r[3]) : "r"(addr));
}

__device__ __forceinline__ uint32_t smem_u32(const void* p) {
    uint32_t a;
    asm("{ .reg .u64 t; cvta.to.shared.u64 t, %1; cvt.u32.u64 %0, t; }"
        : "=r"(a) : "l"(p));
    return a;
}

__device__ __forceinline__ uint32_t packbf2(float x, float y) {
    __nv_bfloat162 t = __floats2bfloat162_rn(x, y);
    return *(uint32_t*)&t;
}

__device__ __forceinline__ void split2(float x, float y, uint32_t& hi, uint32_t& lo) {
    __nv_bfloat162 h = __floats2bfloat162_rn(x, y);
    hi = *(uint32_t*)&h;
    __nv_bfloat162 l = __floats2bfloat162_rn(x - __bfloat162float(h.x),
                                             y - __bfloat162float(h.y));
    lo = *(uint32_t*)&l;
}

// ---------------------------------------------------------------------------
// Prep: split fp32 array into bf16 hi/lo
// ---------------------------------------------------------------------------
__global__ __launch_bounds__(256)
void split_kernel(const float* __restrict__ src, __nv_bfloat16* __restrict__ hi,
                  __nv_bfloat16* __restrict__ lo, int n)
{
    int i = (blockIdx.x * 256 + threadIdx.x) * 4;
    if (i >= n) return;
    float4 v = *(const float4*)(src + i);
    uint32_t h01, l01, h23, l23;
    split2(v.x, v.y, h01, l01);
    split2(v.z, v.w, h23, l23);
    *(uint2*)(hi + i) = make_uint2(h01, h23);
    *(uint2*)(lo + i) = make_uint2(l01, l23);
}

// ---------------------------------------------------------------------------
// GEMM body (bf16 inputs) with register prefetch of the next tile.
// ---------------------------------------------------------------------------
#define GPITCH 40

__device__ __forceinline__ void gemm_body_bf16(
    const __nv_bfloat16* __restrict__ Ah, const __nv_bfloat16* __restrict__ Al,
    const __nv_bfloat16* __restrict__ Bh, const __nv_bfloat16* __restrict__ Bl,
    int ldb, float d[2][4][4])
{
    __shared__ __align__(16) __nv_bfloat16 As_hi[128][GPITCH];
    __shared__ __align__(16) __nv_bfloat16 As_lo[128][GPITCH];
    __shared__ __align__(16) __nv_bfloat16 Bs_hi[64][GPITCH];
    __shared__ __align__(16) __nv_bfloat16 Bs_lo[64][GPITCH];

    const int tid = threadIdx.x;
    const int wid = tid >> 5, lane = tid & 31;
    const int wm = wid & 3, wn = wid >> 2;
    const int fr = lane >> 2, fc = (lane & 3) * 2;

    const int arow = tid >> 1;
    const int ac0 = (tid & 1) * 16;
    const int bn = tid & 63;
    const int bk0 = (tid >> 6) * 8;

#pragma unroll
    for (int mt = 0; mt < 2; mt++)
#pragma unroll
        for (int nt = 0; nt < 4; nt++)
#pragma unroll
            for (int e = 0; e < 4; e++) d[mt][nt][e] = 0.f;

    const __nv_bfloat16* apb = Ah + (size_t)arow * E_ + ac0;
    const __nv_bfloat16* alb = Al + (size_t)arow * E_ + ac0;

    uint4 aPh0 = *(const uint4*)apb;
    uint4 aPh1 = *(const uint4*)(apb + 8);
    uint4 aPl0 = *(const uint4*)alb;
    uint4 aPl1 = *(const uint4*)(alb + 8);
    unsigned short bPh[8], bPl[8];
#pragma unroll
    for (int i = 0; i < 8; i++) {
        bPh[i] = *(const unsigned short*)&Bh[(size_t)(bk0 + i) * ldb + bn];
        bPl[i] = *(const unsigned short*)&Bl[(size_t)(bk0 + i) * ldb + bn];
    }

    for (int kb = 0; kb < E_ / 32; kb++) {
        *(uint4*)&As_hi[arow][ac0]     = aPh0;
        *(uint4*)&As_hi[arow][ac0 + 8] = aPh1;
        *(uint4*)&As_lo[arow][ac0]     = aPl0;
        *(uint4*)&As_lo[arow][ac0 + 8] = aPl1;
#pragma unroll
        for (int i = 0; i < 8; i++) {
            *(unsigned short*)&Bs_hi[bn][bk0 + i] = bPh[i];
            *(unsigned short*)&Bs_lo[bn][bk0 + i] = bPl[i];
        }
        __syncthreads();

        if (kb + 1 < E_ / 32) {
            const int ko = (kb + 1) * 32;
            aPh0 = *(const uint4*)(apb + ko);
            aPh1 = *(const uint4*)(apb + ko + 8);
            aPl0 = *(const uint4*)(alb + ko);
            aPl1 = *(const uint4*)(alb + ko + 8);
#pragma unroll
            for (int i = 0; i < 8; i++) {
                bPh[i] = *(const unsigned short*)&Bh[(size_t)(ko + bk0 + i) * ldb + bn];
                bPl[i] = *(const unsigned short*)&Bl[(size_t)(ko + bk0 + i) * ldb + bn];
            }
        }

#pragma unroll
        for (int ks = 0; ks < 2; ks++) {
            const int k = ks * 16;
            uint32_t ah[2][4], al2[2][4];
#pragma unroll
            for (int mt = 0; mt < 2; mt++) {
                const int rb = wm * 32 + mt * 16;
                ah[mt][0] = *(const uint32_t*)&As_hi[rb + fr    ][k + fc    ];
                ah[mt][1] = *(const uint32_t*)&As_hi[rb + fr + 8][k + fc    ];
                ah[mt][2] = *(const uint32_t*)&As_hi[rb + fr    ][k + fc + 8];
                ah[mt][3] = *(const uint32_t*)&As_hi[rb + fr + 8][k + fc + 8];
                al2[mt][0] = *(const uint32_t*)&As_lo[rb + fr    ][k + fc    ];
                al2[mt][1] = *(const uint32_t*)&As_lo[rb + fr + 8][k + fc    ];
                al2[mt][2] = *(const uint32_t*)&As_lo[rb + fr    ][k + fc + 8];
                al2[mt][3] = *(const uint32_t*)&As_lo[rb + fr + 8][k + fc + 8];
            }
            uint32_t bh[4][2], bl[4][2];
#pragma unroll
            for (int nt = 0; nt < 4; nt++) {
                const int nn = wn * 32 + nt * 8 + (lane >> 2);
                const int kk = k + fc;
                bh[nt][0] = *(const uint32_t*)&Bs_hi[nn][kk    ];
                bh[nt][1] = *(const uint32_t*)&Bs_hi[nn][kk + 8];
                bl[nt][0] = *(const uint32_t*)&Bs_lo[nn][kk    ];
                bl[nt][1] = *(const uint32_t*)&Bs_lo[nn][kk + 8];
            }
#pragma unroll
            for (int mt = 0; mt < 2; mt++)
#pragma unroll
                for (int nt = 0; nt < 4; nt++) {
                    mma16816(d[mt][nt], ah[mt], bh[nt]);
                    mma16816(d[mt][nt], ah[mt], bl[nt]);
                    mma16816(d[mt][nt], al2[mt], bh[nt]);
                }
        }
        __syncthreads();
    }
}

// ---------------------------------------------------------------------------
// Kernel 1: QKV projection -> split bf16 Q/K/V
// ---------------------------------------------------------------------------
__global__ __launch_bounds__(256)
void qkv_hmma_kernel(const float* __restrict__ bq, const float* __restrict__ bk,
                     const float* __restrict__ bv)
{
    const int m0 = blockIdx.y * 128;
    const int j0 = blockIdx.x * 64;
    const int sel = j0 / E_;
    const int h = (j0 % E_) >> 6;

    const __nv_bfloat16* Wh = (sel == 0) ? g_Wqh : (sel == 1) ? g_Wkh : g_Wvh;
    const __nv_bfloat16* Wl = (sel == 0) ? g_Wql : (sel == 1) ? g_Wkl : g_Wvl;
    const float* bia = (sel == 0) ? bq : (sel == 1) ? bk : bv;
    __nv_bfloat16* outh = (sel == 0) ? g_Qh : (sel == 1) ? g_Kh : g_Vh;
    __nv_bfloat16* outl = (sel == 0) ? g_Ql : (sel == 1) ? g_Kl : g_Vl;

    float d[2][4][4];
    gemm_body_bf16(g_xh + (size_t)m0 * E_, g_xl + (size_t)m0 * E_,
                   Wh + (size_t)h * E_ * D_, Wl + (size_t)h * E_ * D_, D_, d);

    const int wid = threadIdx.x >> 5, lane = threadIdx.x & 31;
    const int wm = wid & 3, wn = wid >> 2;
    const int fr = lane >> 2, fc = (lane & 3) * 2;
    const float* brow = bia + h * D_;

#pragma unroll
    for (int mt = 0; mt < 2; mt++) {
#pragma unroll
        for (int half = 0; half < 2; half++) {
            const int row = m0 + wm * 32 + mt * 16 + fr + half * 8;
            const int bb = row >> 11;
            const int s = row & (S_ - 1);
            const size_t ro = (((size_t)bb * H_ + h) * S_ + s) * D_;
#pragma unroll
            for (int nt = 0; nt < 4; nt++) {
                const int col = wn * 32 + nt * 8 + fc;
                float vx = d[mt][nt][half * 2 + 0] + brow[col];
                float vy = d[mt][nt][half * 2 + 1] + brow[col + 1];
                uint32_t hi, lo;
                split2(vx, vy, hi, lo);
                *(uint32_t*)(outh + ro + col) = hi;
                *(uint32_t*)(outl + ro + col) = lo;
            }
        }
    }
}

// ---------------------------------------------------------------------------
// Kernel 3: output projection
// ---------------------------------------------------------------------------
__global__ __launch_bounds__(256)
void out_hmma_kernel(const float* __restrict__ bo, float* __restrict__ out)
{
    const int m0 = blockIdx.y * 128;
    const int n0 = blockIdx.x * 64;

    float d[2][4][4];
    gemm_body_bf16(g_ah + (size_t)m0 * E_, g_al + (size_t)m0 * E_,
                   g_Woh + n0, g_Wol + n0, E_, d);

    const int wid = threadIdx.x >> 5, lane = threadIdx.x & 31;
    const int wm = wid & 3, wn = wid >> 2;
    const int fr = lane >> 2, fc = (lane & 3) * 2;

#pragma unroll
    for (int mt = 0; mt < 2; mt++) {
#pragma unroll
        for (int half = 0; half < 2; half++) {
            const int row = m0 + wm * 32 + mt * 16 + fr + half * 8;
            float* orow = out + (size_t)row * E_ + n0;
#pragma unroll
            for (int nt = 0; nt < 4; nt++) {
                const int col = wn * 32 + nt * 8 + fc;
                float2 v;
                v.x = d[mt][nt][half * 2 + 0] + bo[n0 + col];
                v.y = d[mt][nt][half * 2 + 1] + bo[n0 + col + 1];
                *(float2*)(orow + col) = v;
            }
        }
    }
}

// ---------------------------------------------------------------------------
// Kernel 2: flash attention, Bq=128, Bk=64, 2 blocks/SM.
// smem: Kh[64][72], Kl, Vh, Vl (+mask). Q staged through the same buffers.
// ---------------------------------------------------------------------------
#define KV_PITCH 72
#define TILE_B (64 * KV_PITCH * 2)            // 9216 bytes per tile
#define OFF_KH 0
#define OFF_KL TILE_B
#define OFF_VH (2 * TILE_B)
#define OFF_VL (3 * TILE_B)
#define OFF_MSK (4 * TILE_B)
#define ATT_SMEM (OFF_MSK + 64 * 4)           // 37120 bytes

__global__ __launch_bounds__(256, 2)
void flash_attn_hmma(const int* __restrict__ mask)
{
    extern __shared__ __align__(16) char smx[];
    __nv_bfloat16* Kh = (__nv_bfloat16*)(smx + OFF_KH);
    __nv_bfloat16* Kl = (__nv_bfloat16*)(smx + OFF_KL);
    __nv_bfloat16* Vh = (__nv_bfloat16*)(smx + OFF_VH);
    __nv_bfloat16* Vl = (__nv_bfloat16*)(smx + OFF_VL);
    float* maskf = (float*)(smx + OFF_MSK);

    const int tid = threadIdx.x;
    const int wid = tid >> 5, lane = tid & 31;
    const int fr = lane >> 2, fc = (lane & 3) * 2;
    const int q0 = blockIdx.x * 128;
    const int h = blockIdx.y, b = blockIdx.z;
    const size_t base = ((size_t)b * H_ + h) * S_ * D_;

    const uint32_t sK = smem_u32(Kh);     // hi; lo at +TILE_B
    const uint32_t sVh = smem_u32(Vh);
    const uint32_t sVl = smem_u32(Vl);

    // ---- stage Q (128x64) through K+V buffers: Qh at Kh..Kl, Ql at Vh..Vl ----
    {
        const int row = tid >> 1;
        const int c0 = (tid & 1) * 32;
        const __nv_bfloat16* ph = g_Qh + base + (size_t)(q0 + row) * D_ + c0;
        const __nv_bfloat16* pl = g_Ql + base + (size_t)(q0 + row) * D_ + c0;
        __nv_bfloat16* dsth = (__nv_bfloat16*)(smx + OFF_KH) + row * KV_PITCH + c0;
        __nv_bfloat16* dstl = (__nv_bfloat16*)(smx + OFF_VH) + row * KV_PITCH + c0;
#pragma unroll
        for (int i = 0; i < 4; i++) {
            *(uint4*)(dsth + i * 8) = *(const uint4*)(ph + i * 8);
            *(uint4*)(dstl + i * 8) = *(const uint4*)(pl + i * 8);
        }
    }
    __syncthreads();

    uint32_t qh[4][4], ql[4][4];
    {
        const __nv_bfloat16* Qh_s = (__nv_bfloat16*)(smx + OFF_KH);
        const __nv_bfloat16* Ql_s = (__nv_bfloat16*)(smx + OFF_VH);
        const int r0 = wid * 16 + fr;
#pragma unroll
        for (int kc = 0; kc < 4; kc++) {
            const int k = kc * 16 + fc;
            qh[kc][0] = *(const uint32_t*)&Qh_s[(r0    ) * KV_PITCH + k    ];
            qh[kc][1] = *(const uint32_t*)&Qh_s[(r0 + 8) * KV_PITCH + k    ];
            qh[kc][2] = *(const uint32_t*)&Qh_s[(r0    ) * KV_PITCH + k + 8];
            qh[kc][3] = *(const uint32_t*)&Qh_s[(r0 + 8) * KV_PITCH + k + 8];
            ql[kc][0] = *(const uint32_t*)&Ql_s[(r0    ) * KV_PITCH + k    ];
            ql[kc][1] = *(const uint32_t*)&Ql_s[(r0 + 8) * KV_PITCH + k    ];
            ql[kc][2] = *(const uint32_t*)&Ql_s[(r0    ) * KV_PITCH + k + 8];
            ql[kc][3] = *(const uint32_t*)&Ql_s[(r0 + 8) * KV_PITCH + k + 8];
        }
    }

    float m0r = -INFINITY, m1r = -INFINITY;
    float l0r = 0.f, l1r = 0.f;
    float O[8][4];
#pragma unroll
    for (int nt = 0; nt < 8; nt++)
#pragma unroll
        for (int e = 0; e < 4; e++) O[nt][e] = 0.f;

    // ldmatrix address (K frags): group g=lane>>3, r=lane&7
    const int lg = lane >> 3, lr = lane & 7;

    for (int kb = 0; kb < S_ / 64; kb++) {
        const int k0 = kb * 64;
        __syncthreads();
        // load K/V tile (64 rows x 64 cols, hi+lo)
        {
            const int row = tid >> 2;
            const int c0 = (tid & 3) * 16;
            const size_t go = base + (size_t)(k0 + row) * D_ + c0;
            __nv_bfloat16* kh = Kh + row * KV_PITCH + c0;
            __nv_bfloat16* kl = Kl + row * KV_PITCH + c0;
            __nv_bfloat16* vh = Vh + row * KV_PITCH + c0;
            __nv_bfloat16* vl = Vl + row * KV_PITCH + c0;
            *(uint4*)kh       = *(const uint4*)(g_Kh + go);
            *(uint4*)(kh + 8) = *(const uint4*)(g_Kh + go + 8);
            *(uint4*)kl       = *(const uint4*)(g_Kl + go);
            *(uint4*)(kl + 8) = *(const uint4*)(g_Kl + go + 8);
            *(uint4*)vh       = *(const uint4*)(g_Vh + go);
            *(uint4*)(vh + 8) = *(const uint4*)(g_Vh + go + 8);
            *(uint4*)vl       = *(const uint4*)(g_Vl + go);
            *(uint4*)(vl + 8) = *(const uint4*)(g_Vl + go + 8);
        }
        if (tid < 64) maskf[tid] = mask[(size_t)b * S_ + k0 + tid] ? 0.f : -1e9f;
        __syncthreads();

        // ---- scores: 16 q-rows x 64 k-cols per warp ----
        float s[8][4];
#pragma unroll
        for (int nt = 0; nt < 8; nt++)
#pragma unroll
            for (int e = 0; e < 4; e++) s[nt][e] = 0.f;

#pragma unroll
        for (int kc = 0; kc < 4; kc++) {
#pragma unroll
            for (int ntp = 0; ntp < 4; ntp++) {
                // rows ntp*16 + (g>=2)*8 + r ; col kc*16 + (g&1)*8
                const uint32_t off =
                    (uint32_t)((ntp * 16 + (lg >> 1) * 8 + lr) * KV_PITCH
                               + kc * 16 + (lg & 1) * 8) * 2;
                uint32_t bh[4], bl[4];
                ldsm_x4(bh, sK + off);
                ldsm_x4(bl, sK + TILE_B + off);
                mma16816(s[2*ntp],   qh[kc], bh);
                mma16816(s[2*ntp],   qh[kc], bl);
                mma16816(s[2*ntp],   ql[kc], bh);
                mma16816(s[2*ntp+1], qh[kc], bh + 2);
                mma16816(s[2*ntp+1], qh[kc], bl + 2);
                mma16816(s[2*ntp+1], ql[kc], bh + 2);
            }
        }

        // ---- scale + mask + row max ----
        float mt0 = -INFINITY, mt1 = -INFINITY;
#pragma unroll
        for (int nt = 0; nt < 8; nt++) {
            float2 mf = *(const float2*)&maskf[nt * 8 + fc];
            s[nt][0] = fmaf(s[nt][0], 0.125f, mf.x);
            s[nt][1] = fmaf(s[nt][1], 0.125f, mf.y);
            s[nt][2] = fmaf(s[nt][2], 0.125f, mf.x);
            s[nt][3] = fmaf(s[nt][3], 0.125f, mf.y);
            mt0 = fmaxf(mt0, fmaxf(s[nt][0], s[nt][1]));
            mt1 = fmaxf(mt1, fmaxf(s[nt][2], s[nt][3]));
        }
        mt0 = fmaxf(mt0, __shfl_xor_sync(0xffffffffu, mt0, 1));
        mt0 = fmaxf(mt0, __shfl_xor_sync(0xffffffffu, mt0, 2));
        mt1 = fmaxf(mt1, __shfl_xor_sync(0xffffffffu, mt1, 1));
        mt1 = fmaxf(mt1, __shfl_xor_sync(0xffffffffu, mt1, 2));

        const float mn0 = fmaxf(m0r, mt0), mn1 = fmaxf(m1r, mt1);
        const float cf0 = __expf(m0r - mn0), cf1 = __expf(m1r - mn1);
        m0r = mn0; m1r = mn1;

        float lt0 = 0.f, lt1 = 0.f;
#pragma unroll
        for (int nt = 0; nt < 8; nt++) {
            s[nt][0] = __expf(s[nt][0] - mn0);
            s[nt][1] = __expf(s[nt][1] - mn0);
            s[nt][2] = __expf(s[nt][2] - mn1);
            s[nt][3] = __expf(s[nt][3] - mn1);
            lt0 += s[nt][0] + s[nt][1];
            lt1 += s[nt][2] + s[nt][3];
        }
        lt0 += __shfl_xor_sync(0xffffffffu, lt0, 1);
        lt0 += __shfl_xor_sync(0xffffffffu, lt0, 2);
        lt1 += __shfl_xor_sync(0xffffffffu, lt1, 1);
        lt1 += __shfl_xor_sync(0xffffffffu, lt1, 2);
        l0r = l0r * cf0 + lt0;
        l1r = l1r * cf1 + lt1;

#pragma unroll
        for (int nt = 0; nt < 8; nt++) {
            O[nt][0] *= cf0; O[nt][1] *= cf0;
            O[nt][2] *= cf1; O[nt][3] *= cf1;
        }

        // ---- PV ----
#pragma unroll
        for (int kc = 0; kc < 4; kc++) {
            uint32_t ph[4], pl[4];
            {
                const float p00 = s[2*kc][0],   p01 = s[2*kc][1];
                const float p02 = s[2*kc][2],   p03 = s[2*kc][3];
                const float p10 = s[2*kc+1][0], p11 = s[2*kc+1][1];
                const float p12 = s[2*kc+1][2], p13 = s[2*kc+1][3];
                ph[0] = packbf2(p00, p01);
                ph[1] = packbf2(p02, p03);
                ph[2] = packbf2(p10, p11);
                ph[3] = packbf2(p12, p13);
                __nv_bfloat162* hh;
                hh = (__nv_bfloat162*)&ph[0];
                pl[0] = packbf2(p00 - __bfloat162float(hh->x), p01 - __bfloat162float(hh->y));
                hh = (__nv_bfloat162*)&ph[1];
                pl[1] = packbf2(p02 - __bfloat162float(hh->x), p03 - __bfloat162float(hh->y));
                hh = (__nv_bfloat162*)&ph[2];
                pl[2] = packbf2(p10 - __bfloat162float(hh->x), p11 - __bfloat162float(hh->y));
                hh = (__nv_bfloat162*)&ph[3];
                pl[3] = packbf2(p12 - __bfloat162float(hh->x), p13 - __bfloat162float(hh->y));
            }
            const int mat = lane >> 3;
            const int keyr = kc * 16 + (mat & 1) * 8 + (lane & 7);
#pragma unroll
            for (int ntd = 0; ntd < 4; ntd++) {
                const int dc = ntd * 16 + (mat >> 1) * 8;
                const uint32_t boff = (uint32_t)(keyr * KV_PITCH + dc) * 2;
                uint32_t vh[4], vl[4];
                ldsm_x4_trans(vh, sVh + boff);
                ldsm_x4_trans(vl, sVl + boff);
                mma16816(O[2*ntd],     ph, vh);
                mma16816(O[2*ntd],     ph, vl);
                mma16816(O[2*ntd],     pl, vh);
                mma16816(O[2*ntd + 1], ph, vh + 2);
                mma16816(O[2*ntd + 1], ph, vl + 2);
                mma16816(O[2*ntd + 1], pl, vh + 2);
            }
        }
    }

    // ---- epilogue ----
    const float inv0 = 1.0f / l0r, inv1 = 1.0f / l1r;
    const int qrow = q0 + wid * 16 + fr;
    const size_t o0 = ((size_t)b * S_ + qrow) * E_ + h * D_;
    const size_t o1 = o0 + 8 * E_;
#pragma unroll
    for (int nt = 0; nt < 8; nt++) {
        uint32_t hi, lo;
        split2(O[nt][0] * inv0, O[nt][1] * inv0, hi, lo);
        *(uint32_t*)(g_ah + o0 + nt * 8 + fc) = hi;
        *(uint32_t*)(g_al + o0 + nt * 8 + fc) = lo;
        split2(O[nt][2] * inv1, O[nt][3] * inv1, hi, lo);
        *(uint32_t*)(g_ah + o1 + nt * 8 + fc) = hi;
        *(uint32_t*)(g_al + o1 + nt * 8 + fc) = lo;
    }
}

// ---------------------------------------------------------------------------
// Launch
// ---------------------------------------------------------------------------
extern "C" void kernel_launch(void* const* d_in, const int* in_sizes, int n_in,
                              void* d_out, int out_size)
{
    const float* x    = (const float*)d_in[0];
    const int*   mask = (const int*)d_in[1];
    const float* Wq   = (const float*)d_in[2];
    const float* bq   = (const float*)d_in[3];
    const float* Wk   = (const float*)d_in[4];
    const float* bk   = (const float*)d_in[5];
    const float* Wv   = (const float*)d_in[6];
    const float* bv   = (const float*)d_in[7];
    const float* Wo   = (const float*)d_in[8];
    const float* bo   = (const float*)d_in[9];
    float* out = (float*)d_out;

    cudaFuncSetAttribute(flash_attn_hmma,
                         cudaFuncAttributeMaxDynamicSharedMemorySize, ATT_SMEM);

    __nv_bfloat16 *xh, *xl, *wqh, *wql, *wkh, *wkl, *wvh, *wvl, *woh, *wol;
    cudaGetSymbolAddress((void**)&xh,  g_xh);
    cudaGetSymbolAddress((void**)&xl,  g_xl);
    cudaGetSymbolAddress((void**)&wqh, g_Wqh);
    cudaGetSymbolAddress((void**)&wql, g_Wql);
    cudaGetSymbolAddress((void**)&wkh, g_Wkh);
    cudaGetSymbolAddress((void**)&wkl, g_Wkl);
    cudaGetSymbolAddress((void**)&wvh, g_Wvh);
    cudaGetSymbolAddress((void**)&wvl, g_Wvl);
    cudaGetSymbolAddress((void**)&woh, g_Woh);
    cudaGetSymbolAddress((void**)&wol, g_Wol);

    const int nx = NR * E_;
    const int nw = (int)WSZ;
    const int nwo = E_ * E_;
    split_kernel<<<(nx / 4 + 255) / 256, 256>>>(x, xh, xl, nx);
    split_kernel<<<(nw / 4 + 255) / 256, 256>>>(Wq, wqh, wql, nw);
    split_kernel<<<(nw / 4 + 255) / 256, 256>>>(Wk, wkh, wkl, nw);
    split_kernel<<<(nw / 4 + 255) / 256, 256>>>(Wv, wvh, wvl, nw);
    split_kernel<<<(nwo / 4 + 255) / 256, 256>>>(Wo, woh, wol, nwo);

    {
        dim3 grid(36, 64);
        qkv_hmma_kernel<<<grid, 256>>>(bq, bk, bv);
    }
    {
        dim3 grid(S_ / 128, H_, B_);
        flash_attn_hmma<<<grid, 256, ATT_SMEM>>>(mask);
    }
    {
        dim3 grid(12, 64);
        out_hmma_kernel<<<grid, 256>>>(bo, out);
    }
}

// round 10
// speedup vs baseline: 3.3990x; 1.2666x over previous
#include <cuda_runtime.h>
#include <cuda_bf16.h>
#include <stdint.h>
#include <math.h>

#define B_  4
#define S_  2048
#define E_  768
#define H_  12
#define D_  64
#define NR  (B_ * S_)
#define WSZ ((size_t)H_ * E_ * D_)

// Scratch: bf16 hi/lo split arrays
__device__ __nv_bfloat16 g_xh[(size_t)NR * E_], g_xl[(size_t)NR * E_];
__device__ __nv_bfloat16 g_Wqh[WSZ], g_Wql[WSZ];
__device__ __nv_bfloat16 g_Wkh[WSZ], g_Wkl[WSZ];
__device__ __nv_bfloat16 g_Wvh[WSZ], g_Wvl[WSZ];
__device__ __nv_bfloat16 g_Woh[(size_t)E_ * E_], g_Wol[(size_t)E_ * E_];
__device__ __nv_bfloat16 g_Qh[(size_t)B_ * H_ * S_ * D_], g_Ql[(size_t)B_ * H_ * S_ * D_];
__device__ __nv_bfloat16 g_Kh[(size_t)B_ * H_ * S_ * D_], g_Kl[(size_t)B_ * H_ * S_ * D_];
__device__ __nv_bfloat16 g_Vh[(size_t)B_ * H_ * S_ * D_], g_Vl[(size_t)B_ * H_ * S_ * D_];
__device__ __nv_bfloat16 g_ah[(size_t)NR * E_], g_al[(size_t)NR * E_];
// Key compaction
__device__ int g_cpos[B_ * S_];
__device__ int g_nk[B_];

// ===========================================================================
// helpers
// ===========================================================================
__device__ __forceinline__ void mma16816(float* d, const uint32_t* a, const uint32_t* b) {
    asm volatile(
        "mma.sync.aligned.m16n8k16.row.col.f32.bf16.bf16.f32 "
        "{%0,%1,%2,%3}, {%4,%5,%6,%7}, {%8,%9}, {%0,%1,%2,%3};"
        : "+f"(d[0]), "+f"(d[1]), "+f"(d[2]), "+f"(d[3])
        : "r"(a[0]), "r"(a[1]), "r"(a[2]), "r"(a[3]), "r"(b[0]), "r"(b[1]));
}

__device__ __forceinline__ void ldsm_x4(uint32_t* r, uint32_t addr) {
    asm volatile("ldmatrix.sync.aligned.m8n8.x4.shared.b16 {%0,%1,%2,%3}, [%4];"
        : "=r"(r[0]), "=r"(r[1]), "=r"(r[2]), "=r"(r[3]) : "r"(addr));
}

__device__ __forceinline__ void ldsm_x4_trans(uint32_t* r, uint32_t addr) {
    asm volatile("ldmatrix.sync.aligned.m8n8.x4.trans.shared.b16 {%0,%1,%2,%3}, [%4];"
        : "=r"(r[0]), "=r"(r[1]), "=r"(r[2]), "=r"(r[3]) : "r"(addr));
}

__device__ __forceinline__ uint32_t smem_u32(const void* p) {
    uint32_t a;
    asm("{ .reg .u64 t; cvta.to.shared.u64 t, %1; cvt.u32.u64 %0, t; }"
        : "=r"(a) : "l"(p));
    return a;
}

__device__ __forceinline__ uint32_t packbf2(float x, float y) {
    __nv_bfloat162 t = __floats2bfloat162_rn(x, y);
    return *(uint32_t*)&t;
}

__device__ __forceinline__ void split2(float x, float y, uint32_t& hi, uint32_t& lo) {
    __nv_bfloat162 h = __floats2bfloat162_rn(x, y);
    hi = *(uint32_t*)&h;
    __nv_bfloat162 l = __floats2bfloat162_rn(x - __bfloat162float(h.x),
                                             y - __bfloat162float(h.y));
    lo = *(uint32_t*)&l;
}

// ---------------------------------------------------------------------------
// Prep: split fp32 array into bf16 hi/lo
// ---------------------------------------------------------------------------
__global__ __launch_bounds__(256)
void split_kernel(const float* __restrict__ src, __nv_bfloat16* __restrict__ hi,
                  __nv_bfloat16* __restrict__ lo, int n)
{
    int i = (blockIdx.x * 256 + threadIdx.x) * 4;
    if (i >= n) return;
    float4 v = *(const float4*)(src + i);
    uint32_t h01, l01, h23, l23;
    split2(v.x, v.y, h01, l01);
    split2(v.z, v.w, h23, l23);
    *(uint2*)(hi + i) = make_uint2(h01, h23);
    *(uint2*)(lo + i) = make_uint2(l01, l23);
}

// ---------------------------------------------------------------------------
// Mask scan: per batch, compact positions + count, zero pad rows of K/V.
// One block per batch, 256 threads x 8 elements.
// ---------------------------------------------------------------------------
__global__ __launch_bounds__(256)
void scan_mask_kernel(const int* __restrict__ mask)
{
    __shared__ int sums[256];
    const int b = blockIdx.x, tid = threadIdx.x;
    const int* mb = mask + (size_t)b * S_;

    int loc[8]; int s = 0;
#pragma unroll
    for (int i = 0; i < 8; i++) { loc[i] = mb[tid * 8 + i] ? 1 : 0; s += loc[i]; }
    sums[tid] = s;
    __syncthreads();
    for (int off = 1; off < 256; off <<= 1) {
        int v = 0;
        if (tid >= off) v = sums[tid - off];
        __syncthreads();
        if (tid >= off) sums[tid] += v;
        __syncthreads();
    }
    int excl = (tid == 0) ? 0 : sums[tid - 1];
    const int total = sums[255];
#pragma unroll
    for (int i = 0; i < 8; i++) {
        if (loc[i]) g_cpos[b * S_ + tid * 8 + i] = excl;
        excl += loc[i];
    }
    if (tid == 0) g_nk[b] = total;
    __syncthreads();

    // zero pad rows [total, nkp) of Kh/Kl/Vh/Vl for all heads
    const int nkp = (total + 63) & ~63;
    const int padn = nkp - total;
    if (padn == 0) return;
    const uint4 z = make_uint4(0, 0, 0, 0);
    for (int w = tid; w < padn * H_; w += 256) {
        const int h = w / padn;
        const int r = total + (w % padn);
        const size_t base = (((size_t)b * H_ + h) * S_ + r) * D_;
#pragma unroll
        for (int i = 0; i < 8; i++) {
            ((uint4*)(g_Kh + base))[i] = z;
            ((uint4*)(g_Kl + base))[i] = z;
            ((uint4*)(g_Vh + base))[i] = z;
            ((uint4*)(g_Vl + base))[i] = z;
        }
    }
}

// ---------------------------------------------------------------------------
// GEMM body (bf16 inputs) with register prefetch of the next tile.
// ---------------------------------------------------------------------------
#define GPITCH 40

__device__ __forceinline__ void gemm_body_bf16(
    const __nv_bfloat16* __restrict__ Ah, const __nv_bfloat16* __restrict__ Al,
    const __nv_bfloat16* __restrict__ Bh, const __nv_bfloat16* __restrict__ Bl,
    int ldb, float d[2][4][4])
{
    __shared__ __align__(16) __nv_bfloat16 As_hi[128][GPITCH];
    __shared__ __align__(16) __nv_bfloat16 As_lo[128][GPITCH];
    __shared__ __align__(16) __nv_bfloat16 Bs_hi[64][GPITCH];
    __shared__ __align__(16) __nv_bfloat16 Bs_lo[64][GPITCH];

    const int tid = threadIdx.x;
    const int wid = tid >> 5, lane = tid & 31;
    const int wm = wid & 3, wn = wid >> 2;
    const int fr = lane >> 2, fc = (lane & 3) * 2;

    const int arow = tid >> 1;
    const int ac0 = (tid & 1) * 16;
    const int bn = tid & 63;
    const int bk0 = (tid >> 6) * 8;

#pragma unroll
    for (int mt = 0; mt < 2; mt++)
#pragma unroll
        for (int nt = 0; nt < 4; nt++)
#pragma unroll
            for (int e = 0; e < 4; e++) d[mt][nt][e] = 0.f;

    const __nv_bfloat16* apb = Ah + (size_t)arow * E_ + ac0;
    const __nv_bfloat16* alb = Al + (size_t)arow * E_ + ac0;

    uint4 aPh0 = *(const uint4*)apb;
    uint4 aPh1 = *(const uint4*)(apb + 8);
    uint4 aPl0 = *(const uint4*)alb;
    uint4 aPl1 = *(const uint4*)(alb + 8);
    unsigned short bPh[8], bPl[8];
#pragma unroll
    for (int i = 0; i < 8; i++) {
        bPh[i] = *(const unsigned short*)&Bh[(size_t)(bk0 + i) * ldb + bn];
        bPl[i] = *(const unsigned short*)&Bl[(size_t)(bk0 + i) * ldb + bn];
    }

    for (int kb = 0; kb < E_ / 32; kb++) {
        *(uint4*)&As_hi[arow][ac0]     = aPh0;
        *(uint4*)&As_hi[arow][ac0 + 8] = aPh1;
        *(uint4*)&As_lo[arow][ac0]     = aPl0;
        *(uint4*)&As_lo[arow][ac0 + 8] = aPl1;
#pragma unroll
        for (int i = 0; i < 8; i++) {
            *(unsigned short*)&Bs_hi[bn][bk0 + i] = bPh[i];
            *(unsigned short*)&Bs_lo[bn][bk0 + i] = bPl[i];
        }
        __syncthreads();

        if (kb + 1 < E_ / 32) {
            const int ko = (kb + 1) * 32;
            aPh0 = *(const uint4*)(apb + ko);
            aPh1 = *(const uint4*)(apb + ko + 8);
            aPl0 = *(const uint4*)(alb + ko);
            aPl1 = *(const uint4*)(alb + ko + 8);
#pragma unroll
            for (int i = 0; i < 8; i++) {
                bPh[i] = *(const unsigned short*)&Bh[(size_t)(ko + bk0 + i) * ldb + bn];
                bPl[i] = *(const unsigned short*)&Bl[(size_t)(ko + bk0 + i) * ldb + bn];
            }
        }

#pragma unroll
        for (int ks = 0; ks < 2; ks++) {
            const int k = ks * 16;
            uint32_t ah[2][4], al2[2][4];
#pragma unroll
            for (int mt = 0; mt < 2; mt++) {
                const int rb = wm * 32 + mt * 16;
                ah[mt][0] = *(const uint32_t*)&As_hi[rb + fr    ][k + fc    ];
                ah[mt][1] = *(const uint32_t*)&As_hi[rb + fr + 8][k + fc    ];
                ah[mt][2] = *(const uint32_t*)&As_hi[rb + fr    ][k + fc + 8];
                ah[mt][3] = *(const uint32_t*)&As_hi[rb + fr + 8][k + fc + 8];
                al2[mt][0] = *(const uint32_t*)&As_lo[rb + fr    ][k + fc    ];
                al2[mt][1] = *(const uint32_t*)&As_lo[rb + fr + 8][k + fc    ];
                al2[mt][2] = *(const uint32_t*)&As_lo[rb + fr    ][k + fc + 8];
                al2[mt][3] = *(const uint32_t*)&As_lo[rb + fr + 8][k + fc + 8];
            }
            uint32_t bh[4][2], bl[4][2];
#pragma unroll
            for (int nt = 0; nt < 4; nt++) {
                const int nn = wn * 32 + nt * 8 + (lane >> 2);
                const int kk = k + fc;
                bh[nt][0] = *(const uint32_t*)&Bs_hi[nn][kk    ];
                bh[nt][1] = *(const uint32_t*)&Bs_hi[nn][kk + 8];
                bl[nt][0] = *(const uint32_t*)&Bs_lo[nn][kk    ];
                bl[nt][1] = *(const uint32_t*)&Bs_lo[nn][kk + 8];
            }
#pragma unroll
            for (int mt = 0; mt < 2; mt++)
#pragma unroll
                for (int nt = 0; nt < 4; nt++) {
                    mma16816(d[mt][nt], ah[mt], bh[nt]);
                    mma16816(d[mt][nt], ah[mt], bl[nt]);
                    mma16816(d[mt][nt], al2[mt], bh[nt]);
                }
        }
        __syncthreads();
    }
}

// ---------------------------------------------------------------------------
// Kernel 1: QKV projection -> split bf16 Q (dense) / K,V (compacted scatter)
// ---------------------------------------------------------------------------
__global__ __launch_bounds__(256)
void qkv_hmma_kernel(const int* __restrict__ mask,
                     const float* __restrict__ bq, const float* __restrict__ bk,
                     const float* __restrict__ bv)
{
    const int m0 = blockIdx.y * 128;
    const int j0 = blockIdx.x * 64;
    const int sel = j0 / E_;
    const int h = (j0 % E_) >> 6;

    const __nv_bfloat16* Wh = (sel == 0) ? g_Wqh : (sel == 1) ? g_Wkh : g_Wvh;
    const __nv_bfloat16* Wl = (sel == 0) ? g_Wql : (sel == 1) ? g_Wkl : g_Wvl;
    const float* bia = (sel == 0) ? bq : (sel == 1) ? bk : bv;
    __nv_bfloat16* outh = (sel == 0) ? g_Qh : (sel == 1) ? g_Kh : g_Vh;
    __nv_bfloat16* outl = (sel == 0) ? g_Ql : (sel == 1) ? g_Kl : g_Vl;

    float d[2][4][4];
    gemm_body_bf16(g_xh + (size_t)m0 * E_, g_xl + (size_t)m0 * E_,
                   Wh + (size_t)h * E_ * D_, Wl + (size_t)h * E_ * D_, D_, d);

    const int wid = threadIdx.x >> 5, lane = threadIdx.x & 31;
    const int wm = wid & 3, wn = wid >> 2;
    const int fr = lane >> 2, fc = (lane & 3) * 2;
    const float* brow = bia + h * D_;

#pragma unroll
    for (int mt = 0; mt < 2; mt++) {
#pragma unroll
        for (int half = 0; half < 2; half++) {
            const int row = m0 + wm * 32 + mt * 16 + fr + half * 8;
            const int bb = row >> 11;
            const int s = row & (S_ - 1);
            int srow = s;
            if (sel != 0) {
                if (!mask[bb * S_ + s]) continue;   // masked key: never used
                srow = g_cpos[bb * S_ + s];
            }
            const size_t ro = (((size_t)bb * H_ + h) * S_ + srow) * D_;
#pragma unroll
            for (int nt = 0; nt < 4; nt++) {
                const int col = wn * 32 + nt * 8 + fc;
                float vx = d[mt][nt][half * 2 + 0] + brow[col];
                float vy = d[mt][nt][half * 2 + 1] + brow[col + 1];
                uint32_t hi, lo;
                split2(vx, vy, hi, lo);
                *(uint32_t*)(outh + ro + col) = hi;
                *(uint32_t*)(outl + ro + col) = lo;
            }
        }
    }
}

// ---------------------------------------------------------------------------
// Kernel 3: output projection
// ---------------------------------------------------------------------------
__global__ __launch_bounds__(256)
void out_hmma_kernel(const float* __restrict__ bo, float* __restrict__ out)
{
    const int m0 = blockIdx.y * 128;
    const int n0 = blockIdx.x * 64;

    float d[2][4][4];
    gemm_body_bf16(g_ah + (size_t)m0 * E_, g_al + (size_t)m0 * E_,
                   g_Woh + n0, g_Wol + n0, E_, d);

    const int wid = threadIdx.x >> 5, lane = threadIdx.x & 31;
    const int wm = wid & 3, wn = wid >> 2;
    const int fr = lane >> 2, fc = (lane & 3) * 2;

#pragma unroll
    for (int mt = 0; mt < 2; mt++) {
#pragma unroll
        for (int half = 0; half < 2; half++) {
            const int row = m0 + wm * 32 + mt * 16 + fr + half * 8;
            float* orow = out + (size_t)row * E_ + n0;
#pragma unroll
            for (int nt = 0; nt < 4; nt++) {
                const int col = wn * 32 + nt * 8 + fc;
                float2 v;
                v.x = d[mt][nt][half * 2 + 0] + bo[n0 + col];
                v.y = d[mt][nt][half * 2 + 1] + bo[n0 + col + 1];
                *(float2*)(orow + col) = v;
            }
        }
    }
}

// ---------------------------------------------------------------------------
// Kernel 2: flash attention over COMPACTED keys. Bq=128, Bk=64, 2 blocks/SM.
// ---------------------------------------------------------------------------
#define KV_PITCH 72
#define TILE_B (64 * KV_PITCH * 2)
#define OFF_KH 0
#define OFF_KL TILE_B
#define OFF_VH (2 * TILE_B)
#define OFF_VL (3 * TILE_B)
#define OFF_MSK (4 * TILE_B)
#define ATT_SMEM (OFF_MSK + 64 * 4)

__global__ __launch_bounds__(256, 2)
void flash_attn_hmma()
{
    extern __shared__ __align__(16) char smx[];
    __nv_bfloat16* Kh = (__nv_bfloat16*)(smx + OFF_KH);
    __nv_bfloat16* Kl = (__nv_bfloat16*)(smx + OFF_KL);
    __nv_bfloat16* Vh = (__nv_bfloat16*)(smx + OFF_VH);
    __nv_bfloat16* Vl = (__nv_bfloat16*)(smx + OFF_VL);
    float* maskf = (float*)(smx + OFF_MSK);

    const int tid = threadIdx.x;
    const int wid = tid >> 5, lane = tid & 31;
    const int fr = lane >> 2, fc = (lane & 3) * 2;
    const int q0 = blockIdx.x * 128;
    const int h = blockIdx.y, b = blockIdx.z;
    const size_t base = ((size_t)b * H_ + h) * S_ * D_;
    const int nk = g_nk[b];
    const int nkb = (nk + 63) >> 6;

    const uint32_t sK = smem_u32(Kh);
    const uint32_t sVh = smem_u32(Vh);
    const uint32_t sVl = smem_u32(Vl);

    // stage Q through K+V buffers
    {
        const int row = tid >> 1;
        const int c0 = (tid & 1) * 32;
        const __nv_bfloat16* ph = g_Qh + base + (size_t)(q0 + row) * D_ + c0;
        const __nv_bfloat16* pl = g_Ql + base + (size_t)(q0 + row) * D_ + c0;
        __nv_bfloat16* dsth = (__nv_bfloat16*)(smx + OFF_KH) + row * KV_PITCH + c0;
        __nv_bfloat16* dstl = (__nv_bfloat16*)(smx + OFF_VH) + row * KV_PITCH + c0;
#pragma unroll
        for (int i = 0; i < 4; i++) {
            *(uint4*)(dsth + i * 8) = *(const uint4*)(ph + i * 8);
            *(uint4*)(dstl + i * 8) = *(const uint4*)(pl + i * 8);
        }
    }
    __syncthreads();

    uint32_t qh[4][4], ql[4][4];
    {
        const __nv_bfloat16* Qh_s = (__nv_bfloat16*)(smx + OFF_KH);
        const __nv_bfloat16* Ql_s = (__nv_bfloat16*)(smx + OFF_VH);
        const int r0 = wid * 16 + fr;
#pragma unroll
        for (int kc = 0; kc < 4; kc++) {
            const int k = kc * 16 + fc;
            qh[kc][0] = *(const uint32_t*)&Qh_s[(r0    ) * KV_PITCH + k    ];
            qh[kc][1] = *(const uint32_t*)&Qh_s[(r0 + 8) * KV_PITCH + k    ];
            qh[kc][2] = *(const uint32_t*)&Qh_s[(r0    ) * KV_PITCH + k + 8];
            qh[kc][3] = *(const uint32_t*)&Qh_s[(r0 + 8) * KV_PITCH + k + 8];
            ql[kc][0] = *(const uint32_t*)&Ql_s[(r0    ) * KV_PITCH + k    ];
            ql[kc][1] = *(const uint32_t*)&Ql_s[(r0 + 8) * KV_PITCH + k    ];
            ql[kc][2] = *(const uint32_t*)&Ql_s[(r0    ) * KV_PITCH + k + 8];
            ql[kc][3] = *(const uint32_t*)&Ql_s[(r0 + 8) * KV_PITCH + k + 8];
        }
    }

    float m0r = -INFINITY, m1r = -INFINITY;
    float l0r = 0.f, l1r = 0.f;
    float O[8][4];
#pragma unroll
    for (int nt = 0; nt < 8; nt++)
#pragma unroll
        for (int e = 0; e < 4; e++) O[nt][e] = 0.f;

    const int lg = lane >> 3, lr = lane & 7;

    for (int kb = 0; kb < nkb; kb++) {
        const int k0 = kb * 64;
        __syncthreads();
        {
            const int row = tid >> 2;
            const int c0 = (tid & 3) * 16;
            const size_t go = base + (size_t)(k0 + row) * D_ + c0;
            __nv_bfloat16* kh = Kh + row * KV_PITCH + c0;
            __nv_bfloat16* kl = Kl + row * KV_PITCH + c0;
            __nv_bfloat16* vh = Vh + row * KV_PITCH + c0;
            __nv_bfloat16* vl = Vl + row * KV_PITCH + c0;
            *(uint4*)kh       = *(const uint4*)(g_Kh + go);
            *(uint4*)(kh + 8) = *(const uint4*)(g_Kh + go + 8);
            *(uint4*)kl       = *(const uint4*)(g_Kl + go);
            *(uint4*)(kl + 8) = *(const uint4*)(g_Kl + go + 8);
            *(uint4*)vh       = *(const uint4*)(g_Vh + go);
            *(uint4*)(vh + 8) = *(const uint4*)(g_Vh + go + 8);
            *(uint4*)vl       = *(const uint4*)(g_Vl + go);
            *(uint4*)(vl + 8) = *(const uint4*)(g_Vl + go + 8);
        }
        if (tid < 64) maskf[tid] = (k0 + tid < nk) ? 0.f : -1e9f;
        __syncthreads();

        float s[8][4];
#pragma unroll
        for (int nt = 0; nt < 8; nt++)
#pragma unroll
            for (int e = 0; e < 4; e++) s[nt][e] = 0.f;

#pragma unroll
        for (int kc = 0; kc < 4; kc++) {
#pragma unroll
            for (int ntp = 0; ntp < 4; ntp++) {
                const uint32_t off =
                    (uint32_t)((ntp * 16 + (lg >> 1) * 8 + lr) * KV_PITCH
                               + kc * 16 + (lg & 1) * 8) * 2;
                uint32_t bh[4], bl[4];
                ldsm_x4(bh, sK + off);
                ldsm_x4(bl, sK + TILE_B + off);
                mma16816(s[2*ntp],   qh[kc], bh);
                mma16816(s[2*ntp],   qh[kc], bl);
                mma16816(s[2*ntp],   ql[kc], bh);
                mma16816(s[2*ntp+1], qh[kc], bh + 2);
                mma16816(s[2*ntp+1], qh[kc], bl + 2);
                mma16816(s[2*ntp+1], ql[kc], bh + 2);
            }
        }

        float mt0 = -INFINITY, mt1 = -INFINITY;
#pragma unroll
        for (int nt = 0; nt < 8; nt++) {
            float2 mf = *(const float2*)&maskf[nt * 8 + fc];
            s[nt][0] = fmaf(s[nt][0], 0.125f, mf.x);
            s[nt][1] = fmaf(s[nt][1], 0.125f, mf.y);
            s[nt][2] = fmaf(s[nt][2], 0.125f, mf.x);
            s[nt][3] = fmaf(s[nt][3], 0.125f, mf.y);
            mt0 = fmaxf(mt0, fmaxf(s[nt][0], s[nt][1]));
            mt1 = fmaxf(mt1, fmaxf(s[nt][2], s[nt][3]));
        }
        mt0 = fmaxf(mt0, __shfl_xor_sync(0xffffffffu, mt0, 1));
        mt0 = fmaxf(mt0, __shfl_xor_sync(0xffffffffu, mt0, 2));
        mt1 = fmaxf(mt1, __shfl_xor_sync(0xffffffffu, mt1, 1));
        mt1 = fmaxf(mt1, __shfl_xor_sync(0xffffffffu, mt1, 2));

        const float mn0 = fmaxf(m0r, mt0), mn1 = fmaxf(m1r, mt1);
        const float cf0 = __expf(m0r - mn0), cf1 = __expf(m1r - mn1);
        m0r = mn0; m1r = mn1;

        float lt0 = 0.f, lt1 = 0.f;
#pragma unroll
        for (int nt = 0; nt < 8; nt++) {
            s[nt][0] = __expf(s[nt][0] - mn0);
            s[nt][1] = __expf(s[nt][1] - mn0);
            s[nt][2] = __expf(s[nt][2] - mn1);
            s[nt][3] = __expf(s[nt][3] - mn1);
            lt0 += s[nt][0] + s[nt][1];
            lt1 += s[nt][2] + s[nt][3];
        }
        lt0 += __shfl_xor_sync(0xffffffffu, lt0, 1);
        lt0 += __shfl_xor_sync(0xffffffffu, lt0, 2);
        lt1 += __shfl_xor_sync(0xffffffffu, lt1, 1);
        lt1 += __shfl_xor_sync(0xffffffffu, lt1, 2);
        l0r = l0r * cf0 + lt0;
        l1r = l1r * cf1 + lt1;

#pragma unroll
        for (int nt = 0; nt < 8; nt++) {
            O[nt][0] *= cf0; O[nt][1] *= cf0;
            O[nt][2] *= cf1; O[nt][3] *= cf1;
        }

#pragma unroll
        for (int kc = 0; kc < 4; kc++) {
            uint32_t ph[4], pl[4];
            {
                const float p00 = s[2*kc][0],   p01 = s[2*kc][1];
                const float p02 = s[2*kc][2],   p03 = s[2*kc][3];
                const float p10 = s[2*kc+1][0], p11 = s[2*kc+1][1];
                const float p12 = s[2*kc+1][2], p13 = s[2*kc+1][3];
                ph[0] = packbf2(p00, p01);
                ph[1] = packbf2(p02, p03);
                ph[2] = packbf2(p10, p11);
                ph[3] = packbf2(p12, p13);
                __nv_bfloat162* hh;
                hh = (__nv_bfloat162*)&ph[0];
                pl[0] = packbf2(p00 - __bfloat162float(hh->x), p01 - __bfloat162float(hh->y));
                hh = (__nv_bfloat162*)&ph[1];
                pl[1] = packbf2(p02 - __bfloat162float(hh->x), p03 - __bfloat162float(hh->y));
                hh = (__nv_bfloat162*)&ph[2];
                pl[2] = packbf2(p10 - __bfloat162float(hh->x), p11 - __bfloat162float(hh->y));
                hh = (__nv_bfloat162*)&ph[3];
                pl[3] = packbf2(p12 - __bfloat162float(hh->x), p13 - __bfloat162float(hh->y));
            }
            const int mat = lane >> 3;
            const int keyr = kc * 16 + (mat & 1) * 8 + (lane & 7);
#pragma unroll
            for (int ntd = 0; ntd < 4; ntd++) {
                const int dc = ntd * 16 + (mat >> 1) * 8;
                const uint32_t boff = (uint32_t)(keyr * KV_PITCH + dc) * 2;
                uint32_t vh[4], vl[4];
                ldsm_x4_trans(vh, sVh + boff);
                ldsm_x4_trans(vl, sVl + boff);
                mma16816(O[2*ntd],     ph, vh);
                mma16816(O[2*ntd],     ph, vl);
                mma16816(O[2*ntd],     pl, vh);
                mma16816(O[2*ntd + 1], ph, vh + 2);
                mma16816(O[2*ntd + 1], ph, vl + 2);
                mma16816(O[2*ntd + 1], pl, vh + 2);
            }
        }
    }

    // epilogue
    const float inv0 = 1.0f / l0r, inv1 = 1.0f / l1r;
    const int qrow = q0 + wid * 16 + fr;
    const size_t o0 = ((size_t)b * S_ + qrow) * E_ + h * D_;
    const size_t o1 = o0 + 8 * E_;
#pragma unroll
    for (int nt = 0; nt < 8; nt++) {
        uint32_t hi, lo;
        split2(O[nt][0] * inv0, O[nt][1] * inv0, hi, lo);
        *(uint32_t*)(g_ah + o0 + nt * 8 + fc) = hi;
        *(uint32_t*)(g_al + o0 + nt * 8 + fc) = lo;
        split2(O[nt][2] * inv1, O[nt][3] * inv1, hi, lo);
        *(uint32_t*)(g_ah + o1 + nt * 8 + fc) = hi;
        *(uint32_t*)(g_al + o1 + nt * 8 + fc) = lo;
    }
}

// ---------------------------------------------------------------------------
// Launch
// ---------------------------------------------------------------------------
extern "C" void kernel_launch(void* const* d_in, const int* in_sizes, int n_in,
                              void* d_out, int out_size)
{
    const float* x    = (const float*)d_in[0];
    const int*   mask = (const int*)d_in[1];
    const float* Wq   = (const float*)d_in[2];
    const float* bq   = (const float*)d_in[3];
    const float* Wk   = (const float*)d_in[4];
    const float* bk   = (const float*)d_in[5];
    const float* Wv   = (const float*)d_in[6];
    const float* bv   = (const float*)d_in[7];
    const float* Wo   = (const float*)d_in[8];
    const float* bo   = (const float*)d_in[9];
    float* out = (float*)d_out;

    cudaFuncSetAttribute(flash_attn_hmma,
                         cudaFuncAttributeMaxDynamicSharedMemorySize, ATT_SMEM);

    __nv_bfloat16 *xh, *xl, *wqh, *wql, *wkh, *wkl, *wvh, *wvl, *woh, *wol;
    cudaGetSymbolAddress((void**)&xh,  g_xh);
    cudaGetSymbolAddress((void**)&xl,  g_xl);
    cudaGetSymbolAddress((void**)&wqh, g_Wqh);
    cudaGetSymbolAddress((void**)&wql, g_Wql);
    cudaGetSymbolAddress((void**)&wkh, g_Wkh);
    cudaGetSymbolAddress((void**)&wkl, g_Wkl);
    cudaGetSymbolAddress((void**)&wvh, g_Wvh);
    cudaGetSymbolAddress((void**)&wvl, g_Wvl);
    cudaGetSymbolAddress((void**)&woh, g_Woh);
    cudaGetSymbolAddress((void**)&wol, g_Wol);

    const int nx = NR * E_;
    const int nw = (int)WSZ;
    const int nwo = E_ * E_;
    split_kernel<<<(nx / 4 + 255) / 256, 256>>>(x, xh, xl, nx);
    split_kernel<<<(nw / 4 + 255) / 256, 256>>>(Wq, wqh, wql, nw);
    split_kernel<<<(nw / 4 + 255) / 256, 256>>>(Wk, wkh, wkl, nw);
    split_kernel<<<(nw / 4 + 255) / 256, 256>>>(Wv, wvh, wvl, nw);
    split_kernel<<<(nwo / 4 + 255) / 256, 256>>>(Wo, woh, wol, nwo);
    scan_mask_kernel<<<B_, 256>>>(mask);

    {
        dim3 grid(36, 64);
        qkv_hmma_kernel<<<grid, 256>>>(mask, bq, bk, bv);
    }
    {
        dim3 grid(S_ / 128, H_, B_);
        flash_attn_hmma<<<grid, 256, ATT_SMEM>>>();
    }
    {
        dim3 grid(12, 64);
        out_hmma_kernel<<<grid, 256>>>(bo, out);
    }
}

// round 11
// speedup vs baseline: 3.7115x; 1.0919x over previous
#include <cuda_runtime.h>
#include <cuda_bf16.h>
#include <stdint.h>
#include <math.h>

#define B_  4
#define S_  2048
#define E_  768
#define H_  12
#define D_  64
#define NR  (B_ * S_)
#define WSZ ((size_t)H_ * E_ * D_)

// Scratch: bf16 hi/lo split arrays. Weights stored TRANSPOSED: [h][d][e], Wo: [n][k].
__device__ __nv_bfloat16 g_xh[(size_t)NR * E_], g_xl[(size_t)NR * E_];
__device__ __nv_bfloat16 g_Wqh[WSZ], g_Wql[WSZ];
__device__ __nv_bfloat16 g_Wkh[WSZ], g_Wkl[WSZ];
__device__ __nv_bfloat16 g_Wvh[WSZ], g_Wvl[WSZ];
__device__ __nv_bfloat16 g_Woh[(size_t)E_ * E_], g_Wol[(size_t)E_ * E_];
__device__ __nv_bfloat16 g_Qh[(size_t)B_ * H_ * S_ * D_], g_Ql[(size_t)B_ * H_ * S_ * D_];
__device__ __nv_bfloat16 g_Kh[(size_t)B_ * H_ * S_ * D_], g_Kl[(size_t)B_ * H_ * S_ * D_];
__device__ __nv_bfloat16 g_Vh[(size_t)B_ * H_ * S_ * D_], g_Vl[(size_t)B_ * H_ * S_ * D_];
__device__ __nv_bfloat16 g_ah[(size_t)NR * E_], g_al[(size_t)NR * E_];
__device__ int g_cpos[B_ * S_];
__device__ int g_nk[B_];

// ===========================================================================
// helpers
// ===========================================================================
__device__ __forceinline__ void mma16816(float* d, const uint32_t* a, const uint32_t* b) {
    asm volatile(
        "mma.sync.aligned.m16n8k16.row.col.f32.bf16.bf16.f32 "
        "{%0,%1,%2,%3}, {%4,%5,%6,%7}, {%8,%9}, {%0,%1,%2,%3};"
        : "+f"(d[0]), "+f"(d[1]), "+f"(d[2]), "+f"(d[3])
        : "r"(a[0]), "r"(a[1]), "r"(a[2]), "r"(a[3]), "r"(b[0]), "r"(b[1]));
}

__device__ __forceinline__ void ldsm_x4(uint32_t* r, uint32_t addr) {
    asm volatile("ldmatrix.sync.aligned.m8n8.x4.shared.b16 {%0,%1,%2,%3}, [%4];"
        : "=r"(r[0]), "=r"(r[1]), "=r"(r[2]), "=r"(r[3]) : "r"(addr));
}

__device__ __forceinline__ void ldsm_x4_trans(uint32_t* r, uint32_t addr) {
    asm volatile("ldmatrix.sync.aligned.m8n8.x4.trans.shared.b16 {%0,%1,%2,%3}, [%4];"
        : "=r"(r[0]), "=r"(r[1]), "=r"(r[2]), "=r"(r[3]) : "r"(addr));
}

__device__ __forceinline__ uint32_t smem_u32(const void* p) {
    uint32_t a;
    asm("{ .reg .u64 t; cvta.to.shared.u64 t, %1; cvt.u32.u64 %0, t; }"
        : "=r"(a) : "l"(p));
    return a;
}

__device__ __forceinline__ uint32_t packbf2(float x, float y) {
    __nv_bfloat162 t = __floats2bfloat162_rn(x, y);
    return *(uint32_t*)&t;
}

__device__ __forceinline__ void split2(float x, float y, uint32_t& hi, uint32_t& lo) {
    __nv_bfloat162 h = __floats2bfloat162_rn(x, y);
    hi = *(uint32_t*)&h;
    __nv_bfloat162 l = __floats2bfloat162_rn(x - __bfloat162float(h.x),
                                             y - __bfloat162float(h.y));
    lo = *(uint32_t*)&l;
}

// ---------------------------------------------------------------------------
// Prep: split fp32 array into bf16 hi/lo (same layout)
// ---------------------------------------------------------------------------
__global__ __launch_bounds__(256)
void split_kernel(const float* __restrict__ src, __nv_bfloat16* __restrict__ hi,
                  __nv_bfloat16* __restrict__ lo, int n)
{
    int i = (blockIdx.x * 256 + threadIdx.x) * 4;
    if (i >= n) return;
    float4 v = *(const float4*)(src + i);
    uint32_t h01, l01, h23, l23;
    split2(v.x, v.y, h01, l01);
    split2(v.z, v.w, h23, l23);
    *(uint2*)(hi + i) = make_uint2(h01, h23);
    *(uint2*)(lo + i) = make_uint2(l01, l23);
}

// ---------------------------------------------------------------------------
// Prep: split + transpose. src per-head [R][C] -> dst [C][R]. head = blockIdx.y.
// ---------------------------------------------------------------------------
__global__ __launch_bounds__(256)
void splitT_kernel(const float* __restrict__ src, __nv_bfloat16* __restrict__ hi,
                   __nv_bfloat16* __restrict__ lo, int R, int C)
{
    const size_t hoff = (size_t)blockIdx.y * R * C;
    const int r4n = R >> 2;
    int idx = blockIdx.x * 256 + threadIdx.x;
    if (idx >= C * r4n) return;
    const int c = idx / r4n;
    const int r0 = (idx % r4n) * 4;
    const float* s = src + hoff + (size_t)r0 * C + c;
    float v0 = s[0], v1 = s[C], v2 = s[2 * C], v3 = s[3 * C];
    uint32_t h01, l01, h23, l23;
    split2(v0, v1, h01, l01);
    split2(v2, v3, h23, l23);
    *(uint2*)(hi + hoff + (size_t)c * R + r0) = make_uint2(h01, h23);
    *(uint2*)(lo + hoff + (size_t)c * R + r0) = make_uint2(l01, l23);
}

// ---------------------------------------------------------------------------
// Mask scan (unchanged from R10)
// ---------------------------------------------------------------------------
__global__ __launch_bounds__(256)
void scan_mask_kernel(const int* __restrict__ mask)
{
    __shared__ int sums[256];
    const int b = blockIdx.x, tid = threadIdx.x;
    const int* mb = mask + (size_t)b * S_;

    int loc[8]; int s = 0;
#pragma unroll
    for (int i = 0; i < 8; i++) { loc[i] = mb[tid * 8 + i] ? 1 : 0; s += loc[i]; }
    sums[tid] = s;
    __syncthreads();
    for (int off = 1; off < 256; off <<= 1) {
        int v = 0;
        if (tid >= off) v = sums[tid - off];
        __syncthreads();
        if (tid >= off) sums[tid] += v;
        __syncthreads();
    }
    int excl = (tid == 0) ? 0 : sums[tid - 1];
    const int total = sums[255];
#pragma unroll
    for (int i = 0; i < 8; i++) {
        if (loc[i]) g_cpos[b * S_ + tid * 8 + i] = excl;
        excl += loc[i];
    }
    if (tid == 0) g_nk[b] = total;
    __syncthreads();

    const int nkp = (total + 63) & ~63;
    const int padn = nkp - total;
    if (padn == 0) return;
    const uint4 z = make_uint4(0, 0, 0, 0);
    for (int w = tid; w < padn * H_; w += 256) {
        const int h = w / padn;
        const int r = total + (w % padn);
        const size_t base = (((size_t)b * H_ + h) * S_ + r) * D_;
#pragma unroll
        for (int i = 0; i < 8; i++) {
            ((uint4*)(g_Kh + base))[i] = z;
            ((uint4*)(g_Kl + base))[i] = z;
            ((uint4*)(g_Vh + base))[i] = z;
            ((uint4*)(g_Vl + base))[i] = z;
        }
    }
}

// ---------------------------------------------------------------------------
// GEMM body: D[128x64] = A[128x768] @ B^T. A [m][k], B [n][k] (k-contiguous,
// pitch E_). Fragments via ldmatrix.x4. Register prefetch of next tile.
// ---------------------------------------------------------------------------
#define GPITCH 40

__device__ __forceinline__ void gemm_body_bf16(
    const __nv_bfloat16* __restrict__ Ah, const __nv_bfloat16* __restrict__ Al,
    const __nv_bfloat16* __restrict__ Bh, const __nv_bfloat16* __restrict__ Bl,
    float d[2][4][4])
{
    __shared__ __align__(16) __nv_bfloat16 As_hi[128][GPITCH];
    __shared__ __align__(16) __nv_bfloat16 As_lo[128][GPITCH];
    __shared__ __align__(16) __nv_bfloat16 Bs_hi[64][GPITCH];
    __shared__ __align__(16) __nv_bfloat16 Bs_lo[64][GPITCH];

    const int tid = threadIdx.x;
    const int wid = tid >> 5, lane = tid & 31;
    const int wm = wid & 3, wn = wid >> 2;
    const int lg = lane >> 3, lr = lane & 7;

    const int arow = tid >> 1;
    const int ac0 = (tid & 1) * 16;
    const int bn = tid >> 2;
    const int bc0 = (tid & 3) * 8;

    const uint32_t sAh = smem_u32(As_hi), sAl = smem_u32(As_lo);
    const uint32_t sBh = smem_u32(Bs_hi), sBl = smem_u32(Bs_lo);

#pragma unroll
    for (int mt = 0; mt < 2; mt++)
#pragma unroll
        for (int nt = 0; nt < 4; nt++)
#pragma unroll
            for (int e = 0; e < 4; e++) d[mt][nt][e] = 0.f;

    const __nv_bfloat16* apb = Ah + (size_t)arow * E_ + ac0;
    const __nv_bfloat16* alb = Al + (size_t)arow * E_ + ac0;
    const __nv_bfloat16* bpb = Bh + (size_t)bn * E_ + bc0;
    const __nv_bfloat16* blb = Bl + (size_t)bn * E_ + bc0;

    uint4 aPh0 = *(const uint4*)apb;
    uint4 aPh1 = *(const uint4*)(apb + 8);
    uint4 aPl0 = *(const uint4*)alb;
    uint4 aPl1 = *(const uint4*)(alb + 8);
    uint4 bPh = *(const uint4*)bpb;
    uint4 bPl = *(const uint4*)blb;

    for (int kb = 0; kb < E_ / 32; kb++) {
        *(uint4*)&As_hi[arow][ac0]     = aPh0;
        *(uint4*)&As_hi[arow][ac0 + 8] = aPh1;
        *(uint4*)&As_lo[arow][ac0]     = aPl0;
        *(uint4*)&As_lo[arow][ac0 + 8] = aPl1;
        *(uint4*)&Bs_hi[bn][bc0] = bPh;
        *(uint4*)&Bs_lo[bn][bc0] = bPl;
        __syncthreads();

        if (kb + 1 < E_ / 32) {
            const int ko = (kb + 1) * 32;
            aPh0 = *(const uint4*)(apb + ko);
            aPh1 = *(const uint4*)(apb + ko + 8);
            aPl0 = *(const uint4*)(alb + ko);
            aPl1 = *(const uint4*)(alb + ko + 8);
            bPh = *(const uint4*)(bpb + ko);
            bPl = *(const uint4*)(blb + ko);
        }

#pragma unroll
        for (int ks = 0; ks < 2; ks++) {
            const int k = ks * 16;
            // A fragments: 2 m-tiles, hi+lo, one ldmatrix.x4 each
            uint32_t ah[2][4], al2[2][4];
#pragma unroll
            for (int mt = 0; mt < 2; mt++) {
                const uint32_t aoff =
                    (uint32_t)((wm * 32 + mt * 16 + (lg & 1) * 8 + lr) * GPITCH
                               + k + (lg >> 1) * 8) * 2;
                ldsm_x4(ah[mt], sAh + aoff);
                ldsm_x4(al2[mt], sAl + aoff);
            }
            // B fragments: 4 n-tiles via 2 x4 loads (hi+lo)
            uint32_t bhf[2][4], blf[2][4];
#pragma unroll
            for (int j = 0; j < 2; j++) {
                const uint32_t boff =
                    (uint32_t)((wn * 32 + j * 16 + (lg >> 1) * 8 + lr) * GPITCH
                               + k + (lg & 1) * 8) * 2;
                ldsm_x4(bhf[j], sBh + boff);
                ldsm_x4(blf[j], sBl + boff);
            }
#pragma unroll
            for (int mt = 0; mt < 2; mt++)
#pragma unroll
                for (int nt = 0; nt < 4; nt++) {
                    const uint32_t* bh = &bhf[nt >> 1][(nt & 1) * 2];
                    const uint32_t* bl = &blf[nt >> 1][(nt & 1) * 2];
                    mma16816(d[mt][nt], ah[mt], bh);
                    mma16816(d[mt][nt], ah[mt], bl);
                    mma16816(d[mt][nt], al2[mt], bh);
                }
        }
        __syncthreads();
    }
}

// ---------------------------------------------------------------------------
// Kernel 1: QKV projection -> split bf16 Q (dense) / K,V (compacted scatter)
// ---------------------------------------------------------------------------
__global__ __launch_bounds__(256)
void qkv_hmma_kernel(const int* __restrict__ mask,
                     const float* __restrict__ bq, const float* __restrict__ bk,
                     const float* __restrict__ bv)
{
    const int m0 = blockIdx.y * 128;
    const int j0 = blockIdx.x * 64;
    const int sel = j0 / E_;
    const int h = (j0 % E_) >> 6;

    const __nv_bfloat16* Wh = (sel == 0) ? g_Wqh : (sel == 1) ? g_Wkh : g_Wvh;
    const __nv_bfloat16* Wl = (sel == 0) ? g_Wql : (sel == 1) ? g_Wkl : g_Wvl;
    const float* bia = (sel == 0) ? bq : (sel == 1) ? bk : bv;
    __nv_bfloat16* outh = (sel == 0) ? g_Qh : (sel == 1) ? g_Kh : g_Vh;
    __nv_bfloat16* outl = (sel == 0) ? g_Ql : (sel == 1) ? g_Kl : g_Vl;

    float d[2][4][4];
    gemm_body_bf16(g_xh + (size_t)m0 * E_, g_xl + (size_t)m0 * E_,
                   Wh + (size_t)h * D_ * E_, Wl + (size_t)h * D_ * E_, d);

    const int wid = threadIdx.x >> 5, lane = threadIdx.x & 31;
    const int wm = wid & 3, wn = wid >> 2;
    const int fr = lane >> 2, fc = (lane & 3) * 2;
    const float* brow = bia + h * D_;

#pragma unroll
    for (int mt = 0; mt < 2; mt++) {
#pragma unroll
        for (int half = 0; half < 2; half++) {
            const int row = m0 + wm * 32 + mt * 16 + fr + half * 8;
            const int bb = row >> 11;
            const int s = row & (S_ - 1);
            int srow = s;
            if (sel != 0) {
                if (!mask[bb * S_ + s]) continue;
                srow = g_cpos[bb * S_ + s];
            }
            const size_t ro = (((size_t)bb * H_ + h) * S_ + srow) * D_;
#pragma unroll
            for (int nt = 0; nt < 4; nt++) {
                const int col = wn * 32 + nt * 8 + fc;
                float vx = d[mt][nt][half * 2 + 0] + brow[col];
                float vy = d[mt][nt][half * 2 + 1] + brow[col + 1];
                uint32_t hi, lo;
                split2(vx, vy, hi, lo);
                *(uint32_t*)(outh + ro + col) = hi;
                *(uint32_t*)(outl + ro + col) = lo;
            }
        }
    }
}

// ---------------------------------------------------------------------------
// Kernel 3: output projection (Wo pre-transposed to [n][k])
// ---------------------------------------------------------------------------
__global__ __launch_bounds__(256)
void out_hmma_kernel(const float* __restrict__ bo, float* __restrict__ out)
{
    const int m0 = blockIdx.y * 128;
    const int n0 = blockIdx.x * 64;

    float d[2][4][4];
    gemm_body_bf16(g_ah + (size_t)m0 * E_, g_al + (size_t)m0 * E_,
                   g_Woh + (size_t)n0 * E_, g_Wol + (size_t)n0 * E_, d);

    const int wid = threadIdx.x >> 5, lane = threadIdx.x & 31;
    const int wm = wid & 3, wn = wid >> 2;
    const int fr = lane >> 2, fc = (lane & 3) * 2;

#pragma unroll
    for (int mt = 0; mt < 2; mt++) {
#pragma unroll
        for (int half = 0; half < 2; half++) {
            const int row = m0 + wm * 32 + mt * 16 + fr + half * 8;
            float* orow = out + (size_t)row * E_ + n0;
#pragma unroll
            for (int nt = 0; nt < 4; nt++) {
                const int col = wn * 32 + nt * 8 + fc;
                float2 v;
                v.x = d[mt][nt][half * 2 + 0] + bo[n0 + col];
                v.y = d[mt][nt][half * 2 + 1] + bo[n0 + col + 1];
                *(float2*)(orow + col) = v;
            }
        }
    }
}

// ---------------------------------------------------------------------------
// Kernel 2: flash attention over COMPACTED keys (unchanged from R10)
// ---------------------------------------------------------------------------
#define KV_PITCH 72
#define TILE_B (64 * KV_PITCH * 2)
#define OFF_KH 0
#define OFF_KL TILE_B
#define OFF_VH (2 * TILE_B)
#define OFF_VL (3 * TILE_B)
#define OFF_MSK (4 * TILE_B)
#define ATT_SMEM (OFF_MSK + 64 * 4)

__global__ __launch_bounds__(256, 2)
void flash_attn_hmma()
{
    extern __shared__ __align__(16) char smx[];
    __nv_bfloat16* Kh = (__nv_bfloat16*)(smx + OFF_KH);
    __nv_bfloat16* Kl = (__nv_bfloat16*)(smx + OFF_KL);
    __nv_bfloat16* Vh = (__nv_bfloat16*)(smx + OFF_VH);
    __nv_bfloat16* Vl = (__nv_bfloat16*)(smx + OFF_VL);
    float* maskf = (float*)(smx + OFF_MSK);

    const int tid = threadIdx.x;
    const int wid = tid >> 5, lane = tid & 31;
    const int fr = lane >> 2, fc = (lane & 3) * 2;
    const int q0 = blockIdx.x * 128;
    const int h = blockIdx.y, b = blockIdx.z;
    const size_t base = ((size_t)b * H_ + h) * S_ * D_;
    const int nk = g_nk[b];
    const int nkb = (nk + 63) >> 6;

    const uint32_t sK = smem_u32(Kh);
    const uint32_t sVh = smem_u32(Vh);
    const uint32_t sVl = smem_u32(Vl);

    {
        const int row = tid >> 1;
        const int c0 = (tid & 1) * 32;
        const __nv_bfloat16* ph = g_Qh + base + (size_t)(q0 + row) * D_ + c0;
        const __nv_bfloat16* pl = g_Ql + base + (size_t)(q0 + row) * D_ + c0;
        __nv_bfloat16* dsth = (__nv_bfloat16*)(smx + OFF_KH) + row * KV_PITCH + c0;
        __nv_bfloat16* dstl = (__nv_bfloat16*)(smx + OFF_VH) + row * KV_PITCH + c0;
#pragma unroll
        for (int i = 0; i < 4; i++) {
            *(uint4*)(dsth + i * 8) = *(const uint4*)(ph + i * 8);
            *(uint4*)(dstl + i * 8) = *(const uint4*)(pl + i * 8);
        }
    }
    __syncthreads();

    uint32_t qh[4][4], ql[4][4];
    {
        const __nv_bfloat16* Qh_s = (__nv_bfloat16*)(smx + OFF_KH);
        const __nv_bfloat16* Ql_s = (__nv_bfloat16*)(smx + OFF_VH);
        const int r0 = wid * 16 + fr;
#pragma unroll
        for (int kc = 0; kc < 4; kc++) {
            const int k = kc * 16 + fc;
            qh[kc][0] = *(const uint32_t*)&Qh_s[(r0    ) * KV_PITCH + k    ];
            qh[kc][1] = *(const uint32_t*)&Qh_s[(r0 + 8) * KV_PITCH + k    ];
            qh[kc][2] = *(const uint32_t*)&Qh_s[(r0    ) * KV_PITCH + k + 8];
            qh[kc][3] = *(const uint32_t*)&Qh_s[(r0 + 8) * KV_PITCH + k + 8];
            ql[kc][0] = *(const uint32_t*)&Ql_s[(r0    ) * KV_PITCH + k    ];
            ql[kc][1] = *(const uint32_t*)&Ql_s[(r0 + 8) * KV_PITCH + k    ];
            ql[kc][2] = *(const uint32_t*)&Ql_s[(r0    ) * KV_PITCH + k + 8];
            ql[kc][3] = *(const uint32_t*)&Ql_s[(r0 + 8) * KV_PITCH + k + 8];
        }
    }

    float m0r = -INFINITY, m1r = -INFINITY;
    float l0r = 0.f, l1r = 0.f;
    float O[8][4];
#pragma unroll
    for (int nt = 0; nt < 8; nt++)
#pragma unroll
        for (int e = 0; e < 4; e++) O[nt][e] = 0.f;

    const int lg = lane >> 3, lr = lane & 7;

    for (int kb = 0; kb < nkb; kb++) {
        const int k0 = kb * 64;
        __syncthreads();
        {
            const int row = tid >> 2;
            const int c0 = (tid & 3) * 16;
            const size_t go = base + (size_t)(k0 + row) * D_ + c0;
            __nv_bfloat16* kh = Kh + row * KV_PITCH + c0;
            __nv_bfloat16* kl = Kl + row * KV_PITCH + c0;
            __nv_bfloat16* vh = Vh + row * KV_PITCH + c0;
            __nv_bfloat16* vl = Vl + row * KV_PITCH + c0;
            *(uint4*)kh       = *(const uint4*)(g_Kh + go);
            *(uint4*)(kh + 8) = *(const uint4*)(g_Kh + go + 8);
            *(uint4*)kl       = *(const uint4*)(g_Kl + go);
            *(uint4*)(kl + 8) = *(const uint4*)(g_Kl + go + 8);
            *(uint4*)vh       = *(const uint4*)(g_Vh + go);
            *(uint4*)(vh + 8) = *(const uint4*)(g_Vh + go + 8);
            *(uint4*)vl       = *(const uint4*)(g_Vl + go);
            *(uint4*)(vl + 8) = *(const uint4*)(g_Vl + go + 8);
        }
        if (tid < 64) maskf[tid] = (k0 + tid < nk) ? 0.f : -1e9f;
        __syncthreads();

        float s[8][4];
#pragma unroll
        for (int nt = 0; nt < 8; nt++)
#pragma unroll
            for (int e = 0; e < 4; e++) s[nt][e] = 0.f;

#pragma unroll
        for (int kc = 0; kc < 4; kc++) {
#pragma unroll
            for (int ntp = 0; ntp < 4; ntp++) {
                const uint32_t off =
                    (uint32_t)((ntp * 16 + (lg >> 1) * 8 + lr) * KV_PITCH
                               + kc * 16 + (lg & 1) * 8) * 2;
                uint32_t bh[4], bl[4];
                ldsm_x4(bh, sK + off);
                ldsm_x4(bl, sK + TILE_B + off);
                mma16816(s[2*ntp],   qh[kc], bh);
                mma16816(s[2*ntp],   qh[kc], bl);
                mma16816(s[2*ntp],   ql[kc], bh);
                mma16816(s[2*ntp+1], qh[kc], bh + 2);
                mma16816(s[2*ntp+1], qh[kc], bl + 2);
                mma16816(s[2*ntp+1], ql[kc], bh + 2);
            }
        }

        float mt0 = -INFINITY, mt1 = -INFINITY;
#pragma unroll
        for (int nt = 0; nt < 8; nt++) {
            float2 mf = *(const float2*)&maskf[nt * 8 + fc];
            s[nt][0] = fmaf(s[nt][0], 0.125f, mf.x);
            s[nt][1] = fmaf(s[nt][1], 0.125f, mf.y);
            s[nt][2] = fmaf(s[nt][2], 0.125f, mf.x);
            s[nt][3] = fmaf(s[nt][3], 0.125f, mf.y);
            mt0 = fmaxf(mt0, fmaxf(s[nt][0], s[nt][1]));
            mt1 = fmaxf(mt1, fmaxf(s[nt][2], s[nt][3]));
        }
        mt0 = fmaxf(mt0, __shfl_xor_sync(0xffffffffu, mt0, 1));
        mt0 = fmaxf(mt0, __shfl_xor_sync(0xffffffffu, mt0, 2));
        mt1 = fmaxf(mt1, __shfl_xor_sync(0xffffffffu, mt1, 1));
        mt1 = fmaxf(mt1, __shfl_xor_sync(0xffffffffu, mt1, 2));

        const float mn0 = fmaxf(m0r, mt0), mn1 = fmaxf(m1r, mt1);
        const float cf0 = __expf(m0r - mn0), cf1 = __expf(m1r - mn1);
        m0r = mn0; m1r = mn1;

        float lt0 = 0.f, lt1 = 0.f;
#pragma unroll
        for (int nt = 0; nt < 8; nt++) {
            s[nt][0] = __expf(s[nt][0] - mn0);
            s[nt][1] = __expf(s[nt][1] - mn0);
            s[nt][2] = __expf(s[nt][2] - mn1);
            s[nt][3] = __expf(s[nt][3] - mn1);
            lt0 += s[nt][0] + s[nt][1];
            lt1 += s[nt][2] + s[nt][3];
        }
        lt0 += __shfl_xor_sync(0xffffffffu, lt0, 1);
        lt0 += __shfl_xor_sync(0xffffffffu, lt0, 2);
        lt1 += __shfl_xor_sync(0xffffffffu, lt1, 1);
        lt1 += __shfl_xor_sync(0xffffffffu, lt1, 2);
        l0r = l0r * cf0 + lt0;
        l1r = l1r * cf1 + lt1;

#pragma unroll
        for (int nt = 0; nt < 8; nt++) {
            O[nt][0] *= cf0; O[nt][1] *= cf0;
            O[nt][2] *= cf1; O[nt][3] *= cf1;
        }

#pragma unroll
        for (int kc = 0; kc < 4; kc++) {
            uint32_t ph[4], pl[4];
            {
                const float p00 = s[2*kc][0],   p01 = s[2*kc][1];
                const float p02 = s[2*kc][2],   p03 = s[2*kc][3];
                const float p10 = s[2*kc+1][0], p11 = s[2*kc+1][1];
                const float p12 = s[2*kc+1][2], p13 = s[2*kc+1][3];
                ph[0] = packbf2(p00, p01);
                ph[1] = packbf2(p02, p03);
                ph[2] = packbf2(p10, p11);
                ph[3] = packbf2(p12, p13);
                __nv_bfloat162* hh;
                hh = (__nv_bfloat162*)&ph[0];
                pl[0] = packbf2(p00 - __bfloat162float(hh->x), p01 - __bfloat162float(hh->y));
                hh = (__nv_bfloat162*)&ph[1];
                pl[1] = packbf2(p02 - __bfloat162float(hh->x), p03 - __bfloat162float(hh->y));
                hh = (__nv_bfloat162*)&ph[2];
                pl[2] = packbf2(p10 - __bfloat162float(hh->x), p11 - __bfloat162float(hh->y));
                hh = (__nv_bfloat162*)&ph[3];
                pl[3] = packbf2(p12 - __bfloat162float(hh->x), p13 - __bfloat162float(hh->y));
            }
            const int mat = lane >> 3;
            const int keyr = kc * 16 + (mat & 1) * 8 + (lane & 7);
#pragma unroll
            for (int ntd = 0; ntd < 4; ntd++) {
                const int dc = ntd * 16 + (mat >> 1) * 8;
                const uint32_t boff = (uint32_t)(keyr * KV_PITCH + dc) * 2;
                uint32_t vh[4], vl[4];
                ldsm_x4_trans(vh, sVh + boff);
                ldsm_x4_trans(vl, sVl + boff);
                mma16816(O[2*ntd],     ph, vh);
                mma16816(O[2*ntd],     ph, vl);
                mma16816(O[2*ntd],     pl, vh);
                mma16816(O[2*ntd + 1], ph, vh + 2);
                mma16816(O[2*ntd + 1], ph, vl + 2);
                mma16816(O[2*ntd + 1], pl, vh + 2);
            }
        }
    }

    const float inv0 = 1.0f / l0r, inv1 = 1.0f / l1r;
    const int qrow = q0 + wid * 16 + fr;
    const size_t o0 = ((size_t)b * S_ + qrow) * E_ + h * D_;
    const size_t o1 = o0 + 8 * E_;
#pragma unroll
    for (int nt = 0; nt < 8; nt++) {
        uint32_t hi, lo;
        split2(O[nt][0] * inv0, O[nt][1] * inv0, hi, lo);
        *(uint32_t*)(g_ah + o0 + nt * 8 + fc) = hi;
        *(uint32_t*)(g_al + o0 + nt * 8 + fc) = lo;
        split2(O[nt][2] * inv1, O[nt][3] * inv1, hi, lo);
        *(uint32_t*)(g_ah + o1 + nt * 8 + fc) = hi;
        *(uint32_t*)(g_al + o1 + nt * 8 + fc) = lo;
    }
}

// ---------------------------------------------------------------------------
// Launch
// ---------------------------------------------------------------------------
extern "C" void kernel_launch(void* const* d_in, const int* in_sizes, int n_in,
                              void* d_out, int out_size)
{
    const float* x    = (const float*)d_in[0];
    const int*   mask = (const int*)d_in[1];
    const float* Wq   = (const float*)d_in[2];
    const float* bq   = (const float*)d_in[3];
    const float* Wk   = (const float*)d_in[4];
    const float* bk   = (const float*)d_in[5];
    const float* Wv   = (const float*)d_in[6];
    const float* bv   = (const float*)d_in[7];
    const float* Wo   = (const float*)d_in[8];
    const float* bo   = (const float*)d_in[9];
    float* out = (float*)d_out;

    cudaFuncSetAttribute(flash_attn_hmma,
                         cudaFuncAttributeMaxDynamicSharedMemorySize, ATT_SMEM);

    __nv_bfloat16 *xh, *xl, *wqh, *wql, *wkh, *wkl, *wvh, *wvl, *woh, *wol;
    cudaGetSymbolAddress((void**)&xh,  g_xh);
    cudaGetSymbolAddress((void**)&xl,  g_xl);
    cudaGetSymbolAddress((void**)&wqh, g_Wqh);
    cudaGetSymbolAddress((void**)&wql, g_Wql);
    cudaGetSymbolAddress((void**)&wkh, g_Wkh);
    cudaGetSymbolAddress((void**)&wkl, g_Wkl);
    cudaGetSymbolAddress((void**)&wvh, g_Wvh);
    cudaGetSymbolAddress((void**)&wvl, g_Wvl);
    cudaGetSymbolAddress((void**)&woh, g_Woh);
    cudaGetSymbolAddress((void**)&wol, g_Wol);

    const int nx = NR * E_;
    split_kernel<<<(nx / 4 + 255) / 256, 256>>>(x, xh, xl, nx);
    // per-head transposed weight splits: [E][D] -> [D][E], 12288 thr/head
    {
        dim3 g(48, H_);
        splitT_kernel<<<g, 256>>>(Wq, wqh, wql, E_, D_);
        splitT_kernel<<<g, 256>>>(Wk, wkh, wkl, E_, D_);
        splitT_kernel<<<g, 256>>>(Wv, wvh, wvl, E_, D_);
    }
    // Wo: [k=768][n=768] -> [n][k]
    splitT_kernel<<<dim3(576, 1), 256>>>(Wo, woh, wol, E_, E_);
    scan_mask_kernel<<<B_, 256>>>(mask);

    {
        dim3 grid(36, 64);
        qkv_hmma_kernel<<<grid, 256>>>(mask, bq, bk, bv);
    }
    {
        dim3 grid(S_ / 128, H_, B_);
        flash_attn_hmma<<<grid, 256, ATT_SMEM>>>();
    }
    {
        dim3 grid(12, 64);
        out_hmma_kernel<<<grid, 256>>>(bo, out);
    }
}

// round 12
// speedup vs baseline: 3.8943x; 1.0493x over previous
#include <cuda_runtime.h>
#include <cuda_bf16.h>
#include <stdint.h>
#include <math.h>

#define B_  4
#define S_  2048
#define E_  768
#define H_  12
#define D_  64
#define NR  (B_ * S_)
#define WSZ ((size_t)H_ * E_ * D_)

// Scratch: bf16 hi/lo split arrays. Weights TRANSPOSED: [h][d][e], Wo: [n][k].
__device__ __nv_bfloat16 g_xh[(size_t)NR * E_], g_xl[(size_t)NR * E_];
__device__ __nv_bfloat16 g_Wqh[WSZ], g_Wql[WSZ];
__device__ __nv_bfloat16 g_Wkh[WSZ], g_Wkl[WSZ];
__device__ __nv_bfloat16 g_Wvh[WSZ], g_Wvl[WSZ];
__device__ __nv_bfloat16 g_Woh[(size_t)E_ * E_], g_Wol[(size_t)E_ * E_];
__device__ __nv_bfloat16 g_Qh[(size_t)B_ * H_ * S_ * D_], g_Ql[(size_t)B_ * H_ * S_ * D_];
__device__ __nv_bfloat16 g_Kh[(size_t)B_ * H_ * S_ * D_], g_Kl[(size_t)B_ * H_ * S_ * D_];
__device__ __nv_bfloat16 g_Vh[(size_t)B_ * H_ * S_ * D_], g_Vl[(size_t)B_ * H_ * S_ * D_];
__device__ __nv_bfloat16 g_ah[(size_t)NR * E_], g_al[(size_t)NR * E_];
__device__ int g_cpos[B_ * S_];
__device__ int g_nk[B_];

// ===========================================================================
// helpers
// ===========================================================================
__device__ __forceinline__ void mma16816(float* d, const uint32_t* a, const uint32_t* b) {
    asm volatile(
        "mma.sync.aligned.m16n8k16.row.col.f32.bf16.bf16.f32 "
        "{%0,%1,%2,%3}, {%4,%5,%6,%7}, {%8,%9}, {%0,%1,%2,%3};"
        : "+f"(d[0]), "+f"(d[1]), "+f"(d[2]), "+f"(d[3])
        : "r"(a[0]), "r"(a[1]), "r"(a[2]), "r"(a[3]), "r"(b[0]), "r"(b[1]));
}

__device__ __forceinline__ void ldsm_x4(uint32_t* r, uint32_t addr) {
    asm volatile("ldmatrix.sync.aligned.m8n8.x4.shared.b16 {%0,%1,%2,%3}, [%4];"
        : "=r"(r[0]), "=r"(r[1]), "=r"(r[2]), "=r"(r[3]) : "r"(addr));
}

__device__ __forceinline__ void ldsm_x4_trans(uint32_t* r, uint32_t addr) {
    asm volatile("ldmatrix.sync.aligned.m8n8.x4.trans.shared.b16 {%0,%1,%2,%3}, [%4];"
        : "=r"(r[0]), "=r"(r[1]), "=r"(r[2]), "=r"(r[3]) : "r"(addr));
}

__device__ __forceinline__ uint32_t smem_u32(const void* p) {
    uint32_t a;
    asm("{ .reg .u64 t; cvta.to.shared.u64 t, %1; cvt.u32.u64 %0, t; }"
        : "=r"(a) : "l"(p));
    return a;
}

__device__ __forceinline__ uint32_t packbf2(float x, float y) {
    __nv_bfloat162 t = __floats2bfloat162_rn(x, y);
    return *(uint32_t*)&t;
}

__device__ __forceinline__ void split2(float x, float y, uint32_t& hi, uint32_t& lo) {
    __nv_bfloat162 h = __floats2bfloat162_rn(x, y);
    hi = *(uint32_t*)&h;
    __nv_bfloat162 l = __floats2bfloat162_rn(x - __bfloat162float(h.x),
                                             y - __bfloat162float(h.y));
    lo = *(uint32_t*)&l;
}

// ---------------------------------------------------------------------------
// Prep kernels (verified R11)
// ---------------------------------------------------------------------------
__global__ __launch_bounds__(256)
void split_kernel(const float* __restrict__ src, __nv_bfloat16* __restrict__ hi,
                  __nv_bfloat16* __restrict__ lo, int n)
{
    int i = (blockIdx.x * 256 + threadIdx.x) * 4;
    if (i >= n) return;
    float4 v = *(const float4*)(src + i);
    uint32_t h01, l01, h23, l23;
    split2(v.x, v.y, h01, l01);
    split2(v.z, v.w, h23, l23);
    *(uint2*)(hi + i) = make_uint2(h01, h23);
    *(uint2*)(lo + i) = make_uint2(l01, l23);
}

__global__ __launch_bounds__(256)
void splitT_kernel(const float* __restrict__ src, __nv_bfloat16* __restrict__ hi,
                   __nv_bfloat16* __restrict__ lo, int R, int C)
{
    const size_t hoff = (size_t)blockIdx.y * R * C;
    const int r4n = R >> 2;
    int idx = blockIdx.x * 256 + threadIdx.x;
    if (idx >= C * r4n) return;
    const int c = idx / r4n;
    const int r0 = (idx % r4n) * 4;
    const float* s = src + hoff + (size_t)r0 * C + c;
    float v0 = s[0], v1 = s[C], v2 = s[2 * C], v3 = s[3 * C];
    uint32_t h01, l01, h23, l23;
    split2(v0, v1, h01, l01);
    split2(v2, v3, h23, l23);
    *(uint2*)(hi + hoff + (size_t)c * R + r0) = make_uint2(h01, h23);
    *(uint2*)(lo + hoff + (size_t)c * R + r0) = make_uint2(l01, l23);
}

__global__ __launch_bounds__(256)
void scan_mask_kernel(const int* __restrict__ mask)
{
    __shared__ int sums[256];
    const int b = blockIdx.x, tid = threadIdx.x;
    const int* mb = mask + (size_t)b * S_;

    int loc[8]; int s = 0;
#pragma unroll
    for (int i = 0; i < 8; i++) { loc[i] = mb[tid * 8 + i] ? 1 : 0; s += loc[i]; }
    sums[tid] = s;
    __syncthreads();
    for (int off = 1; off < 256; off <<= 1) {
        int v = 0;
        if (tid >= off) v = sums[tid - off];
        __syncthreads();
        if (tid >= off) sums[tid] += v;
        __syncthreads();
    }
    int excl = (tid == 0) ? 0 : sums[tid - 1];
    const int total = sums[255];
#pragma unroll
    for (int i = 0; i < 8; i++) {
        if (loc[i]) g_cpos[b * S_ + tid * 8 + i] = excl;
        excl += loc[i];
    }
    if (tid == 0) g_nk[b] = total;
    __syncthreads();

    const int nkp = (total + 63) & ~63;
    const int padn = nkp - total;
    if (padn == 0) return;
    const uint4 z = make_uint4(0, 0, 0, 0);
    for (int w = tid; w < padn * H_; w += 256) {
        const int h = w / padn;
        const int r = total + (w % padn);
        const size_t base = (((size_t)b * H_ + h) * S_ + r) * D_;
#pragma unroll
        for (int i = 0; i < 8; i++) {
            ((uint4*)(g_Kh + base))[i] = z;
            ((uint4*)(g_Kl + base))[i] = z;
            ((uint4*)(g_Vh + base))[i] = z;
            ((uint4*)(g_Vl + base))[i] = z;
        }
    }
}

// ---------------------------------------------------------------------------
// GEMM body: double-buffered smem, one sync/iter, ldmatrix fragments.
// ---------------------------------------------------------------------------
#define GPITCH 40
#define A_BUF (128 * GPITCH)     // halves per buffer
#define B_BUF (64 * GPITCH)
#define OFF_AH 0
#define OFF_AL (2 * A_BUF)
#define OFF_BH (4 * A_BUF)
#define OFF_BL (4 * A_BUF + 2 * B_BUF)
#define GEMM_SMEM ((4 * A_BUF + 4 * B_BUF) * 2)   // 61440 bytes
#define NKB (E_ / 32)            // 24

__device__ __forceinline__ void gemm_body_bf16(
    __nv_bfloat16* sm,
    const __nv_bfloat16* __restrict__ Ah, const __nv_bfloat16* __restrict__ Al,
    const __nv_bfloat16* __restrict__ Bh, const __nv_bfloat16* __restrict__ Bl,
    float d[2][4][4])
{
    const int tid = threadIdx.x;
    const int wid = tid >> 5, lane = tid & 31;
    const int wm = wid & 3, wn = wid >> 2;
    const int lg = lane >> 3, lr = lane & 7;

    const int arow = tid >> 1;
    const int ac0 = (tid & 1) * 16;
    const int bn = tid >> 2;
    const int bc0 = (tid & 3) * 8;

    const uint32_t sb = smem_u32(sm);

#pragma unroll
    for (int mt = 0; mt < 2; mt++)
#pragma unroll
        for (int nt = 0; nt < 4; nt++)
#pragma unroll
            for (int e = 0; e < 4; e++) d[mt][nt][e] = 0.f;

    const __nv_bfloat16* apb = Ah + (size_t)arow * E_ + ac0;
    const __nv_bfloat16* alb = Al + (size_t)arow * E_ + ac0;
    const __nv_bfloat16* bpb = Bh + (size_t)bn * E_ + bc0;
    const __nv_bfloat16* blb = Bl + (size_t)bn * E_ + bc0;

    // store pointers per buffer
    __nv_bfloat16* stAH0 = sm + OFF_AH + arow * GPITCH + ac0;
    __nv_bfloat16* stAL0 = sm + OFF_AL + arow * GPITCH + ac0;
    __nv_bfloat16* stBH0 = sm + OFF_BH + bn * GPITCH + bc0;
    __nv_bfloat16* stBL0 = sm + OFF_BL + bn * GPITCH + bc0;

    uint4 aPh0, aPh1, aPl0, aPl1, bPh, bPl;

    // prologue: tile0 -> buf0; prefetch tile1
    aPh0 = *(const uint4*)apb;
    aPh1 = *(const uint4*)(apb + 8);
    aPl0 = *(const uint4*)alb;
    aPl1 = *(const uint4*)(alb + 8);
    bPh = *(const uint4*)bpb;
    bPl = *(const uint4*)blb;
    *(uint4*)stAH0       = aPh0;
    *(uint4*)(stAH0 + 8) = aPh1;
    *(uint4*)stAL0       = aPl0;
    *(uint4*)(stAL0 + 8) = aPl1;
    *(uint4*)stBH0 = bPh;
    *(uint4*)stBL0 = bPl;
    aPh0 = *(const uint4*)(apb + 32);
    aPh1 = *(const uint4*)(apb + 40);
    aPl0 = *(const uint4*)(alb + 32);
    aPl1 = *(const uint4*)(alb + 40);
    bPh = *(const uint4*)(bpb + 32);
    bPl = *(const uint4*)(blb + 32);
    __syncthreads();

    for (int kb = 0; kb < NKB; kb++) {
        const int cur = kb & 1;
        if (kb + 1 < NKB) {
            const int nb = cur ^ 1;
            *(uint4*)(stAH0 + nb * A_BUF)     = aPh0;
            *(uint4*)(stAH0 + nb * A_BUF + 8) = aPh1;
            *(uint4*)(stAL0 + nb * A_BUF)     = aPl0;
            *(uint4*)(stAL0 + nb * A_BUF + 8) = aPl1;
            *(uint4*)(stBH0 + nb * B_BUF) = bPh;
            *(uint4*)(stBL0 + nb * B_BUF) = bPl;
            if (kb + 2 < NKB) {
                const int ko = (kb + 2) * 32;
                aPh0 = *(const uint4*)(apb + ko);
                aPh1 = *(const uint4*)(apb + ko + 8);
                aPl0 = *(const uint4*)(alb + ko);
                aPl1 = *(const uint4*)(alb + ko + 8);
                bPh = *(const uint4*)(bpb + ko);
                bPl = *(const uint4*)(blb + ko);
            }
        }

        const uint32_t baseAH = sb + (uint32_t)(OFF_AH + cur * A_BUF) * 2;
        const uint32_t baseAL = sb + (uint32_t)(OFF_AL + cur * A_BUF) * 2;
        const uint32_t baseBH = sb + (uint32_t)(OFF_BH + cur * B_BUF) * 2;
        const uint32_t baseBL = sb + (uint32_t)(OFF_BL + cur * B_BUF) * 2;

#pragma unroll
        for (int ks = 0; ks < 2; ks++) {
            const int k = ks * 16;
            uint32_t ah[2][4], al2[2][4];
#pragma unroll
            for (int mt = 0; mt < 2; mt++) {
                const uint32_t aoff =
                    (uint32_t)((wm * 32 + mt * 16 + (lg & 1) * 8 + lr) * GPITCH
                               + k + (lg >> 1) * 8) * 2;
                ldsm_x4(ah[mt], baseAH + aoff);
                ldsm_x4(al2[mt], baseAL + aoff);
            }
            uint32_t bhf[2][4], blf[2][4];
#pragma unroll
            for (int j = 0; j < 2; j++) {
                const uint32_t boff =
                    (uint32_t)((wn * 32 + j * 16 + (lg >> 1) * 8 + lr) * GPITCH
                               + k + (lg & 1) * 8) * 2;
                ldsm_x4(bhf[j], baseBH + boff);
                ldsm_x4(blf[j], baseBL + boff);
            }
#pragma unroll
            for (int mt = 0; mt < 2; mt++)
#pragma unroll
                for (int nt = 0; nt < 4; nt++) {
                    const uint32_t* bh = &bhf[nt >> 1][(nt & 1) * 2];
                    const uint32_t* bl = &blf[nt >> 1][(nt & 1) * 2];
                    mma16816(d[mt][nt], ah[mt], bh);
                    mma16816(d[mt][nt], ah[mt], bl);
                    mma16816(d[mt][nt], al2[mt], bh);
                }
        }
        __syncthreads();
    }
}

// ---------------------------------------------------------------------------
// Kernel 1: QKV projection -> split bf16 Q (dense) / K,V (compacted scatter)
// ---------------------------------------------------------------------------
__global__ __launch_bounds__(256)
void qkv_hmma_kernel(const int* __restrict__ mask,
                     const float* __restrict__ bq, const float* __restrict__ bk,
                     const float* __restrict__ bv)
{
    extern __shared__ __align__(16) __nv_bfloat16 smg[];
    const int m0 = blockIdx.y * 128;
    const int j0 = blockIdx.x * 64;
    const int sel = j0 / E_;
    const int h = (j0 % E_) >> 6;

    const __nv_bfloat16* Wh = (sel == 0) ? g_Wqh : (sel == 1) ? g_Wkh : g_Wvh;
    const __nv_bfloat16* Wl = (sel == 0) ? g_Wql : (sel == 1) ? g_Wkl : g_Wvl;
    const float* bia = (sel == 0) ? bq : (sel == 1) ? bk : bv;
    __nv_bfloat16* outh = (sel == 0) ? g_Qh : (sel == 1) ? g_Kh : g_Vh;
    __nv_bfloat16* outl = (sel == 0) ? g_Ql : (sel == 1) ? g_Kl : g_Vl;

    float d[2][4][4];
    gemm_body_bf16(smg, g_xh + (size_t)m0 * E_, g_xl + (size_t)m0 * E_,
                   Wh + (size_t)h * D_ * E_, Wl + (size_t)h * D_ * E_, d);

    const int wid = threadIdx.x >> 5, lane = threadIdx.x & 31;
    const int wm = wid & 3, wn = wid >> 2;
    const int fr = lane >> 2, fc = (lane & 3) * 2;
    const float* brow = bia + h * D_;

#pragma unroll
    for (int mt = 0; mt < 2; mt++) {
#pragma unroll
        for (int half = 0; half < 2; half++) {
            const int row = m0 + wm * 32 + mt * 16 + fr + half * 8;
            const int bb = row >> 11;
            const int s = row & (S_ - 1);
            int srow = s;
            if (sel != 0) {
                if (!mask[bb * S_ + s]) continue;
                srow = g_cpos[bb * S_ + s];
            }
            const size_t ro = (((size_t)bb * H_ + h) * S_ + srow) * D_;
#pragma unroll
            for (int nt = 0; nt < 4; nt++) {
                const int col = wn * 32 + nt * 8 + fc;
                float vx = d[mt][nt][half * 2 + 0] + brow[col];
                float vy = d[mt][nt][half * 2 + 1] + brow[col + 1];
                uint32_t hi, lo;
                split2(vx, vy, hi, lo);
                *(uint32_t*)(outh + ro + col) = hi;
                *(uint32_t*)(outl + ro + col) = lo;
            }
        }
    }
}

// ---------------------------------------------------------------------------
// Kernel 3: output projection (Wo pre-transposed to [n][k])
// ---------------------------------------------------------------------------
__global__ __launch_bounds__(256)
void out_hmma_kernel(const float* __restrict__ bo, float* __restrict__ out)
{
    extern __shared__ __align__(16) __nv_bfloat16 smg[];
    const int m0 = blockIdx.y * 128;
    const int n0 = blockIdx.x * 64;

    float d[2][4][4];
    gemm_body_bf16(smg, g_ah + (size_t)m0 * E_, g_al + (size_t)m0 * E_,
                   g_Woh + (size_t)n0 * E_, g_Wol + (size_t)n0 * E_, d);

    const int wid = threadIdx.x >> 5, lane = threadIdx.x & 31;
    const int wm = wid & 3, wn = wid >> 2;
    const int fr = lane >> 2, fc = (lane & 3) * 2;

#pragma unroll
    for (int mt = 0; mt < 2; mt++) {
#pragma unroll
        for (int half = 0; half < 2; half++) {
            const int row = m0 + wm * 32 + mt * 16 + fr + half * 8;
            float* orow = out + (size_t)row * E_ + n0;
#pragma unroll
            for (int nt = 0; nt < 4; nt++) {
                const int col = wn * 32 + nt * 8 + fc;
                float2 v;
                v.x = d[mt][nt][half * 2 + 0] + bo[n0 + col];
                v.y = d[mt][nt][half * 2 + 1] + bo[n0 + col + 1];
                *(float2*)(orow + col) = v;
            }
        }
    }
}

// ---------------------------------------------------------------------------
// Kernel 2: flash attention over COMPACTED keys. PV drops the P-residual term.
// ---------------------------------------------------------------------------
#define KV_PITCH 72
#define TILE_B (64 * KV_PITCH * 2)
#define OFF_KH 0
#define OFF_KL TILE_B
#define OFF_VH (2 * TILE_B)
#define OFF_VL (3 * TILE_B)
#define OFF_MSK (4 * TILE_B)
#define ATT_SMEM (OFF_MSK + 64 * 4)

__global__ __launch_bounds__(256, 2)
void flash_attn_hmma()
{
    extern __shared__ __align__(16) char smx[];
    __nv_bfloat16* Kh = (__nv_bfloat16*)(smx + OFF_KH);
    __nv_bfloat16* Kl = (__nv_bfloat16*)(smx + OFF_KL);
    __nv_bfloat16* Vh = (__nv_bfloat16*)(smx + OFF_VH);
    __nv_bfloat16* Vl = (__nv_bfloat16*)(smx + OFF_VL);
    float* maskf = (float*)(smx + OFF_MSK);

    const int tid = threadIdx.x;
    const int wid = tid >> 5, lane = tid & 31;
    const int fr = lane >> 2, fc = (lane & 3) * 2;
    const int q0 = blockIdx.x * 128;
    const int h = blockIdx.y, b = blockIdx.z;
    const size_t base = ((size_t)b * H_ + h) * S_ * D_;
    const int nk = g_nk[b];
    const int nkb = (nk + 63) >> 6;

    const uint32_t sK = smem_u32(Kh);
    const uint32_t sVh = smem_u32(Vh);
    const uint32_t sVl = smem_u32(Vl);

    // stage Q through K+V buffers
    {
        const int row = tid >> 1;
        const int c0 = (tid & 1) * 32;
        const __nv_bfloat16* ph = g_Qh + base + (size_t)(q0 + row) * D_ + c0;
        const __nv_bfloat16* pl = g_Ql + base + (size_t)(q0 + row) * D_ + c0;
        __nv_bfloat16* dsth = (__nv_bfloat16*)(smx + OFF_KH) + row * KV_PITCH + c0;
        __nv_bfloat16* dstl = (__nv_bfloat16*)(smx + OFF_VH) + row * KV_PITCH + c0;
#pragma unroll
        for (int i = 0; i < 4; i++) {
            *(uint4*)(dsth + i * 8) = *(const uint4*)(ph + i * 8);
            *(uint4*)(dstl + i * 8) = *(const uint4*)(pl + i * 8);
        }
    }
    __syncthreads();

    uint32_t qh[4][4], ql[4][4];
    {
        const __nv_bfloat16* Qh_s = (__nv_bfloat16*)(smx + OFF_KH);
        const __nv_bfloat16* Ql_s = (__nv_bfloat16*)(smx + OFF_VH);
        const int r0 = wid * 16 + fr;
#pragma unroll
        for (int kc = 0; kc < 4; kc++) {
            const int k = kc * 16 + fc;
            qh[kc][0] = *(const uint32_t*)&Qh_s[(r0    ) * KV_PITCH + k    ];
            qh[kc][1] = *(const uint32_t*)&Qh_s[(r0 + 8) * KV_PITCH + k    ];
            qh[kc][2] = *(const uint32_t*)&Qh_s[(r0    ) * KV_PITCH + k + 8];
            qh[kc][3] = *(const uint32_t*)&Qh_s[(r0 + 8) * KV_PITCH + k + 8];
            ql[kc][0] = *(const uint32_t*)&Ql_s[(r0    ) * KV_PITCH + k    ];
            ql[kc][1] = *(const uint32_t*)&Ql_s[(r0 + 8) * KV_PITCH + k    ];
            ql[kc][2] = *(const uint32_t*)&Ql_s[(r0    ) * KV_PITCH + k + 8];
            ql[kc][3] = *(const uint32_t*)&Ql_s[(r0 + 8) * KV_PITCH + k + 8];
        }
    }

    float m0r = -INFINITY, m1r = -INFINITY;
    float l0r = 0.f, l1r = 0.f;
    float O[8][4];
#pragma unroll
    for (int nt = 0; nt < 8; nt++)
#pragma unroll
        for (int e = 0; e < 4; e++) O[nt][e] = 0.f;

    const int lg = lane >> 3, lr = lane & 7;

    for (int kb = 0; kb < nkb; kb++) {
        const int k0 = kb * 64;
        __syncthreads();
        {
            const int row = tid >> 2;
            const int c0 = (tid & 3) * 16;
            const size_t go = base + (size_t)(k0 + row) * D_ + c0;
            __nv_bfloat16* kh = Kh + row * KV_PITCH + c0;
            __nv_bfloat16* kl = Kl + row * KV_PITCH + c0;
            __nv_bfloat16* vh = Vh + row * KV_PITCH + c0;
            __nv_bfloat16* vl = Vl + row * KV_PITCH + c0;
            *(uint4*)kh       = *(const uint4*)(g_Kh + go);
            *(uint4*)(kh + 8) = *(const uint4*)(g_Kh + go + 8);
            *(uint4*)kl       = *(const uint4*)(g_Kl + go);
            *(uint4*)(kl + 8) = *(const uint4*)(g_Kl + go + 8);
            *(uint4*)vh       = *(const uint4*)(g_Vh + go);
            *(uint4*)(vh + 8) = *(const uint4*)(g_Vh + go + 8);
            *(uint4*)vl       = *(const uint4*)(g_Vl + go);
            *(uint4*)(vl + 8) = *(const uint4*)(g_Vl + go + 8);
        }
        if (tid < 64) maskf[tid] = (k0 + tid < nk) ? 0.f : -1e9f;
        __syncthreads();

        float s[8][4];
#pragma unroll
        for (int nt = 0; nt < 8; nt++)
#pragma unroll
            for (int e = 0; e < 4; e++) s[nt][e] = 0.f;

#pragma unroll
        for (int kc = 0; kc < 4; kc++) {
#pragma unroll
            for (int ntp = 0; ntp < 4; ntp++) {
                const uint32_t off =
                    (uint32_t)((ntp * 16 + (lg >> 1) * 8 + lr) * KV_PITCH
                               + kc * 16 + (lg & 1) * 8) * 2;
                uint32_t bh[4], bl[4];
                ldsm_x4(bh, sK + off);
                ldsm_x4(bl, sK + TILE_B + off);
                mma16816(s[2*ntp],   qh[kc], bh);
                mma16816(s[2*ntp],   qh[kc], bl);
                mma16816(s[2*ntp],   ql[kc], bh);
                mma16816(s[2*ntp+1], qh[kc], bh + 2);
                mma16816(s[2*ntp+1], qh[kc], bl + 2);
                mma16816(s[2*ntp+1], ql[kc], bh + 2);
            }
        }

        float mt0 = -INFINITY, mt1 = -INFINITY;
#pragma unroll
        for (int nt = 0; nt < 8; nt++) {
            float2 mf = *(const float2*)&maskf[nt * 8 + fc];
            s[nt][0] = fmaf(s[nt][0], 0.125f, mf.x);
            s[nt][1] = fmaf(s[nt][1], 0.125f, mf.y);
            s[nt][2] = fmaf(s[nt][2], 0.125f, mf.x);
            s[nt][3] = fmaf(s[nt][3], 0.125f, mf.y);
            mt0 = fmaxf(mt0, fmaxf(s[nt][0], s[nt][1]));
            mt1 = fmaxf(mt1, fmaxf(s[nt][2], s[nt][3]));
        }
        mt0 = fmaxf(mt0, __shfl_xor_sync(0xffffffffu, mt0, 1));
        mt0 = fmaxf(mt0, __shfl_xor_sync(0xffffffffu, mt0, 2));
        mt1 = fmaxf(mt1, __shfl_xor_sync(0xffffffffu, mt1, 1));
        mt1 = fmaxf(mt1, __shfl_xor_sync(0xffffffffu, mt1, 2));

        const float mn0 = fmaxf(m0r, mt0), mn1 = fmaxf(m1r, mt1);
        const float cf0 = __expf(m0r - mn0), cf1 = __expf(m1r - mn1);
        m0r = mn0; m1r = mn1;

        float lt0 = 0.f, lt1 = 0.f;
#pragma unroll
        for (int nt = 0; nt < 8; nt++) {
            s[nt][0] = __expf(s[nt][0] - mn0);
            s[nt][1] = __expf(s[nt][1] - mn0);
            s[nt][2] = __expf(s[nt][2] - mn1);
            s[nt][3] = __expf(s[nt][3] - mn1);
            lt0 += s[nt][0] + s[nt][1];
            lt1 += s[nt][2] + s[nt][3];
        }
        lt0 += __shfl_xor_sync(0xffffffffu, lt0, 1);
        lt0 += __shfl_xor_sync(0xffffffffu, lt0, 2);
        lt1 += __shfl_xor_sync(0xffffffffu, lt1, 1);
        lt1 += __shfl_xor_sync(0xffffffffu, lt1, 2);
        l0r = l0r * cf0 + lt0;
        l1r = l1r * cf1 + lt1;

#pragma unroll
        for (int nt = 0; nt < 8; nt++) {
            O[nt][0] *= cf0; O[nt][1] *= cf0;
            O[nt][2] *= cf1; O[nt][3] *= cf1;
        }

        // PV: P as bf16 (hi only) x V split hi/lo
#pragma unroll
        for (int kc = 0; kc < 4; kc++) {
            uint32_t ph[4];
            ph[0] = packbf2(s[2*kc][0],   s[2*kc][1]);
            ph[1] = packbf2(s[2*kc][2],   s[2*kc][3]);
            ph[2] = packbf2(s[2*kc+1][0], s[2*kc+1][1]);
            ph[3] = packbf2(s[2*kc+1][2], s[2*kc+1][3]);
            const int mat = lane >> 3;
            const int keyr = kc * 16 + (mat & 1) * 8 + (lane & 7);
#pragma unroll
            for (int ntd = 0; ntd < 4; ntd++) {
                const int dc = ntd * 16 + (mat >> 1) * 8;
                const uint32_t boff = (uint32_t)(keyr * KV_PITCH + dc) * 2;
                uint32_t vh[4], vl[4];
                ldsm_x4_trans(vh, sVh + boff);
                ldsm_x4_trans(vl, sVl + boff);
                mma16816(O[2*ntd],     ph, vh);
                mma16816(O[2*ntd],     ph, vl);
                mma16816(O[2*ntd + 1], ph, vh + 2);
                mma16816(O[2*ntd + 1], ph, vl + 2);
            }
        }
    }

    const float inv0 = 1.0f / l0r, inv1 = 1.0f / l1r;
    const int qrow = q0 + wid * 16 + fr;
    const size_t o0 = ((size_t)b * S_ + qrow) * E_ + h * D_;
    const size_t o1 = o0 + 8 * E_;
#pragma unroll
    for (int nt = 0; nt < 8; nt++) {
        uint32_t hi, lo;
        split2(O[nt][0] * inv0, O[nt][1] * inv0, hi, lo);
        *(uint32_t*)(g_ah + o0 + nt * 8 + fc) = hi;
        *(uint32_t*)(g_al + o0 + nt * 8 + fc) = lo;
        split2(O[nt][2] * inv1, O[nt][3] * inv1, hi, lo);
        *(uint32_t*)(g_ah + o1 + nt * 8 + fc) = hi;
        *(uint32_t*)(g_al + o1 + nt * 8 + fc) = lo;
    }
}

// ---------------------------------------------------------------------------
// Launch
// ---------------------------------------------------------------------------
extern "C" void kernel_launch(void* const* d_in, const int* in_sizes, int n_in,
                              void* d_out, int out_size)
{
    const float* x    = (const float*)d_in[0];
    const int*   mask = (const int*)d_in[1];
    const float* Wq   = (const float*)d_in[2];
    const float* bq   = (const float*)d_in[3];
    const float* Wk   = (const float*)d_in[4];
    const float* bk   = (const float*)d_in[5];
    const float* Wv   = (const float*)d_in[6];
    const float* bv   = (const float*)d_in[7];
    const float* Wo   = (const float*)d_in[8];
    const float* bo   = (const float*)d_in[9];
    float* out = (float*)d_out;

    cudaFuncSetAttribute(flash_attn_hmma,
                         cudaFuncAttributeMaxDynamicSharedMemorySize, ATT_SMEM);
    cudaFuncSetAttribute(qkv_hmma_kernel,
                         cudaFuncAttributeMaxDynamicSharedMemorySize, GEMM_SMEM);
    cudaFuncSetAttribute(out_hmma_kernel,
                         cudaFuncAttributeMaxDynamicSharedMemorySize, GEMM_SMEM);

    __nv_bfloat16 *xh, *xl, *wqh, *wql, *wkh, *wkl, *wvh, *wvl, *woh, *wol;
    cudaGetSymbolAddress((void**)&xh,  g_xh);
    cudaGetSymbolAddress((void**)&xl,  g_xl);
    cudaGetSymbolAddress((void**)&wqh, g_Wqh);
    cudaGetSymbolAddress((void**)&wql, g_Wql);
    cudaGetSymbolAddress((void**)&wkh, g_Wkh);
    cudaGetSymbolAddress((void**)&wkl, g_Wkl);
    cudaGetSymbolAddress((void**)&wvh, g_Wvh);
    cudaGetSymbolAddress((void**)&wvl, g_Wvl);
    cudaGetSymbolAddress((void**)&woh, g_Woh);
    cudaGetSymbolAddress((void**)&wol, g_Wol);

    const int nx = NR * E_;
    split_kernel<<<(nx / 4 + 255) / 256, 256>>>(x, xh, xl, nx);
    {
        dim3 g(48, H_);
        splitT_kernel<<<g, 256>>>(Wq, wqh, wql, E_, D_);
        splitT_kernel<<<g, 256>>>(Wk, wkh, wkl, E_, D_);
        splitT_kernel<<<g, 256>>>(Wv, wvh, wvl, E_, D_);
    }
    splitT_kernel<<<dim3(576, 1), 256>>>(Wo, woh, wol, E_, E_);
    scan_mask_kernel<<<B_, 256>>>(mask);

    {
        dim3 grid(36, 64);
        qkv_hmma_kernel<<<grid, 256, GEMM_SMEM>>>(mask, bq, bk, bv);
    }
    {
        dim3 grid(S_ / 128, H_, B_);
        flash_attn_hmma<<<grid, 256, ATT_SMEM>>>();
    }
    {
        dim3 grid(12, 64);
        out_hmma_kernel<<<grid, 256, GEMM_SMEM>>>(bo, out);
    }
}